// round 1
// baseline (speedup 1.0000x reference)
#include <cuda_runtime.h>
#include <math.h>

// ---------------- static scratch (no allocations allowed) ----------------
__device__ float g_qc   [4096*1536];          // q_c (rmsnormed in place)
__device__ float g_kvc  [4096*512];           // kv_c
__device__ float g_krope[4096*64];            // x @ wk_rope^T (pre-rope)
__device__ float g_qnope[4096*2048];          // q_c @ wq_up^T
__device__ float g_qpe  [4096*1024];          // q_c @ wq_rope^T (pre-rope)
__device__ float g_kvup [4096ull*4096];       // kv_c @ wkv_up^T  (k_nope | v interleaved per head)
__device__ float g_Q    [32ull*2048*192];     // assembled Q  [b,h][s][192]
__device__ float g_Kt   [32ull*192*2048];     // assembled K^T [b,h][d][s]
__device__ float g_attn [4096*2048];          // attention out [m][h*128+c]

// ---------------- generic SGEMM: C[M,N] = A[M,K] @ B[N,K]^T ----------------
// BM=BN=128, BK=8, 256 threads, 8x8 micro-tile. M,K assumed multiples of 128/8.
__global__ __launch_bounds__(256) void sgemm_nt(const float* __restrict__ A,
                                                const float* __restrict__ B,
                                                float* __restrict__ C,
                                                int M, int N, int K) {
    __shared__ float As[8][128];
    __shared__ float Bs[8][128];
    const int tid = threadIdx.x;
    const int tx = tid & 15, ty = tid >> 4;
    const int bx = blockIdx.x, by = blockIdx.y;

    const int lrow = tid >> 1;
    const int lk   = (tid & 1) * 4;
    const float* Ab = A + (size_t)(by*128 + lrow) * K + lk;
    const int brow  = bx*128 + lrow;
    const float* Bb = B + (size_t)brow * K + lk;
    const bool bok  = brow < N;

    float acc[8][8];
    #pragma unroll
    for (int i = 0; i < 8; i++)
        #pragma unroll
        for (int j = 0; j < 8; j++) acc[i][j] = 0.f;

    for (int k0 = 0; k0 < K; k0 += 8) {
        float4 av = *(const float4*)(Ab + k0);
        float4 bv = bok ? *(const float4*)(Bb + k0) : make_float4(0.f,0.f,0.f,0.f);
        As[lk+0][lrow]=av.x; As[lk+1][lrow]=av.y; As[lk+2][lrow]=av.z; As[lk+3][lrow]=av.w;
        Bs[lk+0][lrow]=bv.x; Bs[lk+1][lrow]=bv.y; Bs[lk+2][lrow]=bv.z; Bs[lk+3][lrow]=bv.w;
        __syncthreads();
        #pragma unroll
        for (int k = 0; k < 8; k++) {
            float4 a0 = *(const float4*)&As[k][ty*8];
            float4 a1 = *(const float4*)&As[k][ty*8+4];
            float4 b0 = *(const float4*)&Bs[k][tx*8];
            float4 b1 = *(const float4*)&Bs[k][tx*8+4];
            float a[8] = {a0.x,a0.y,a0.z,a0.w,a1.x,a1.y,a1.z,a1.w};
            float b[8] = {b0.x,b0.y,b0.z,b0.w,b1.x,b1.y,b1.z,b1.w};
            #pragma unroll
            for (int i = 0; i < 8; i++)
                #pragma unroll
                for (int j = 0; j < 8; j++)
                    acc[i][j] = fmaf(a[i], b[j], acc[i][j]);
        }
        __syncthreads();
    }
    const int row0 = by*128 + ty*8;
    const int col0 = bx*128 + tx*8;
    if (col0 < N) {  // N always a multiple of 8 here
        #pragma unroll
        for (int i = 0; i < 8; i++) {
            float* Crow = C + (size_t)(row0 + i) * N + col0;
            *(float4*)(Crow)     = make_float4(acc[i][0],acc[i][1],acc[i][2],acc[i][3]);
            *(float4*)(Crow + 4) = make_float4(acc[i][4],acc[i][5],acc[i][6],acc[i][7]);
        }
    }
}

// ---------------- RMSNorm (in place, one block per row) ----------------
__global__ __launch_bounds__(256) void rmsnorm_k(float* __restrict__ x,
                                                 const float* __restrict__ w, int cols) {
    const int row = blockIdx.x;
    float* xr = x + (size_t)row * cols;
    const int tid = threadIdx.x;
    float s = 0.f;
    for (int c = tid; c < cols; c += 256) { float v = xr[c]; s = fmaf(v, v, s); }
    __shared__ float red[256];
    red[tid] = s; __syncthreads();
    for (int st = 128; st > 0; st >>= 1) {
        if (tid < st) red[tid] += red[tid + st];
        __syncthreads();
    }
    const float inv = rsqrtf(red[0] / (float)cols + 1e-6f);
    for (int c = tid; c < cols; c += 256) xr[c] = xr[c] * inv * w[c];
}

// ---------------- RoPE helper (LLaMA interleaved pairs, d=64) ----------------
__device__ __forceinline__ float rope_val(const float* __restrict__ src, int base, int j, int s) {
    const int p = j & ~1;                              // pair start (even)
    const float inv = powf(10000.0f, -(float)p * (1.0f/64.0f));
    const float ang = (float)s * inv;
    float sn, cs; sincosf(ang, &sn, &cs);
    const float x1 = src[base + p], x2 = src[base + p + 1];
    return (j & 1) ? fmaf(x1, sn, x2 * cs) : fmaf(x1, cs, -x2 * sn);
}

// ---------------- assemble Q: [b,h][s][192] = [q_nope | rope(q_pe)] ----------------
__global__ __launch_bounds__(256) void assemble_q(const float* __restrict__ qn,
                                                  const float* __restrict__ qp,
                                                  float* __restrict__ Qg) {
    const int idx = blockIdx.x * 256 + threadIdx.x;
    const int total = 32 * 2048 * 192;
    if (idx >= total) return;
    const int d  = idx % 192;
    const int t  = idx / 192;
    const int s  = t & 2047;
    const int bh = t >> 11;
    const int b = bh >> 4, h = bh & 15;
    const int m = b * 2048 + s;
    float val;
    if (d < 128) val = qn[(size_t)m * 2048 + h * 128 + d];
    else         val = rope_val(qp, m * 1024 + h * 64, d - 128, s);
    Qg[idx] = val;
}

// ---------------- assemble K^T: [b,h][d][s] = [k_nope | rope(k_rope)]^T ----------------
__global__ void assemble_kt(const float* __restrict__ kvup,
                            const float* __restrict__ krope,
                            float* __restrict__ Kt) {
    __shared__ float tile[32][33];
    const int bh = blockIdx.z;
    const int b = bh >> 4, h = bh & 15;
    const int d0 = blockIdx.y * 32, s0 = blockIdx.x * 32;
    const int txi = threadIdx.x, tyi = threadIdx.y;
    const int s = s0 + tyi, d = d0 + txi;
    const int m = b * 2048 + s;
    float val;
    if (d < 128) val = kvup[(size_t)m * 4096 + h * 256 + d];
    else         val = rope_val(krope, m * 64, d - 128, s);
    tile[tyi][txi] = val;
    __syncthreads();
    Kt[((size_t)bh * 192 + d0 + tyi) * 2048 + s0 + txi] = tile[txi][tyi];
}

// ---------------- flash attention (causal, fp32, 64x64 tiles) ----------------
// grid (qt=32, h=16, b=2), 256 threads (16x16), dynamic smem.
// Q row-major in smem; K k-major (pre-transposed in GMEM); V read straight from kv_up.
#define FLASH_SMEM_FLOATS (64*192 + 192*68 + 64*128 + 64*64)
__global__ __launch_bounds__(256) void flash_kernel(const float* __restrict__ Qg,
                                                    const float* __restrict__ Ktg,
                                                    const float* __restrict__ kvup,
                                                    float* __restrict__ Og) {
    extern __shared__ float sm[];
    float* Qs = sm;                    // [64][192] row-major
    float* Ks = sm + 64*192;           // [192][68] k-major (pad 64->68)
    float* Vs = Ks + 192*68;           // [64][128] row-major
    float* Ps = Vs + 64*128;           // [64][64]

    const int qt = blockIdx.x, h = blockIdx.y, b = blockIdx.z;
    const int bh = b * 16 + h;
    const int tid = threadIdx.x, tx = tid & 15, ty = tid >> 4;

    // load Q tile
    const float4* qg4 = (const float4*)(Qg + ((size_t)bh * 2048 + qt * 64) * 192);
    for (int i = tid; i < 64 * 48; i += 256) ((float4*)Qs)[i] = qg4[i];

    float m_i[4], l_i[4], o[4][8];
    #pragma unroll
    for (int i = 0; i < 4; i++) {
        m_i[i] = -INFINITY; l_i[i] = 0.f;
        #pragma unroll
        for (int j = 0; j < 8; j++) o[i][j] = 0.f;
    }
    __syncthreads();

    const float* ktg = Ktg + (size_t)bh * 192 * 2048;
    const float* vg0 = kvup + (size_t)b * 2048 * 4096 + h * 256 + 128;
    const float scale = 0.07216878364870323f;   // 1/sqrt(192)

    for (int kt = 0; kt <= qt; kt++) {
        // load K tile (k-major, coalesced from pre-transposed GMEM)
        for (int i = tid; i < 192 * 16; i += 256) {
            int dd = i >> 4, q4 = i & 15;
            float4 v = *(const float4*)(ktg + (size_t)dd * 2048 + kt * 64 + q4 * 4);
            *(float4*)&Ks[dd * 68 + q4 * 4] = v;
        }
        // load V tile straight from kv_up (row stride 4096)
        const float* vg = vg0 + (size_t)kt * 64 * 4096;
        for (int i = tid; i < 64 * 32; i += 256) {
            int r = i >> 5, c4 = i & 31;
            *(float4*)&Vs[r * 128 + c4 * 4] = *(const float4*)(vg + (size_t)r * 4096 + c4 * 4);
        }
        __syncthreads();

        // scores: sacc[i][j] = Q[ty*4+i] . K[tx*4+j]
        float sacc[4][4];
        #pragma unroll
        for (int i = 0; i < 4; i++)
            #pragma unroll
            for (int j = 0; j < 4; j++) sacc[i][j] = 0.f;

        for (int k0 = 0; k0 < 192; k0 += 4) {
            float qv[4][4];
            #pragma unroll
            for (int i = 0; i < 4; i++) {
                float4 t = *(const float4*)&Qs[(ty * 4 + i) * 192 + k0];
                qv[i][0]=t.x; qv[i][1]=t.y; qv[i][2]=t.z; qv[i][3]=t.w;
            }
            #pragma unroll
            for (int kk = 0; kk < 4; kk++) {
                float4 kvv = *(const float4*)&Ks[(k0 + kk) * 68 + tx * 4];
                float kv[4] = {kvv.x, kvv.y, kvv.z, kvv.w};
                #pragma unroll
                for (int i = 0; i < 4; i++)
                    #pragma unroll
                    for (int j = 0; j < 4; j++)
                        sacc[i][j] = fmaf(qv[i][kk], kv[j], sacc[i][j]);
            }
        }

        // online softmax per row (16-lane row groups)
        const bool diag = (kt == qt);
        #pragma unroll
        for (int i = 0; i < 4; i++) {
            const int rg = (qt << 6) + (ty << 2) + i;
            float sv[4];
            float rmax = -INFINITY;
            #pragma unroll
            for (int j = 0; j < 4; j++) {
                float v = sacc[i][j] * scale;
                if (diag) {
                    int cg = (kt << 6) + (tx << 2) + j;
                    if (cg > rg) v = -INFINITY;
                }
                sv[j] = v;
                rmax = fmaxf(rmax, v);
            }
            #pragma unroll
            for (int off = 8; off > 0; off >>= 1)
                rmax = fmaxf(rmax, __shfl_xor_sync(0xffffffffu, rmax, off, 16));
            const float mnew  = fmaxf(m_i[i], rmax);
            const float alpha = expf(m_i[i] - mnew);
            float ps = 0.f;
            #pragma unroll
            for (int j = 0; j < 4; j++) {
                float p = expf(sv[j] - mnew);
                Ps[(ty * 4 + i) * 64 + tx * 4 + j] = p;
                ps += p;
            }
            #pragma unroll
            for (int off = 8; off > 0; off >>= 1)
                ps += __shfl_xor_sync(0xffffffffu, ps, off, 16);
            l_i[i] = l_i[i] * alpha + ps;
            m_i[i] = mnew;
            #pragma unroll
            for (int j = 0; j < 8; j++) o[i][j] *= alpha;
        }
        __syncthreads();

        // O += P @ V  (P[64x64] @ V[64x128])
        for (int k0 = 0; k0 < 64; k0 += 4) {
            float pv[4][4];
            #pragma unroll
            for (int i = 0; i < 4; i++) {
                float4 t = *(const float4*)&Ps[(ty * 4 + i) * 64 + k0];
                pv[i][0]=t.x; pv[i][1]=t.y; pv[i][2]=t.z; pv[i][3]=t.w;
            }
            #pragma unroll
            for (int kk = 0; kk < 4; kk++) {
                const float* vr = &Vs[(k0 + kk) * 128 + tx * 8];
                float4 v0 = *(const float4*)vr;
                float4 v1 = *(const float4*)(vr + 4);
                float vv[8] = {v0.x,v0.y,v0.z,v0.w,v1.x,v1.y,v1.z,v1.w};
                #pragma unroll
                for (int i = 0; i < 4; i++)
                    #pragma unroll
                    for (int j = 0; j < 8; j++)
                        o[i][j] = fmaf(pv[i][kk], vv[j], o[i][j]);
            }
        }
        __syncthreads();
    }

    // epilogue: normalize and write [m][h*128 + c]
    #pragma unroll
    for (int i = 0; i < 4; i++) {
        const float inv = 1.f / l_i[i];
        const int s = (qt << 6) + (ty << 2) + i;
        float* orow = Og + ((size_t)(b * 2048 + s)) * 2048 + h * 128 + tx * 8;
        *(float4*)orow       = make_float4(o[i][0]*inv, o[i][1]*inv, o[i][2]*inv, o[i][3]*inv);
        *(float4*)(orow + 4) = make_float4(o[i][4]*inv, o[i][5]*inv, o[i][6]*inv, o[i][7]*inv);
    }
}

// ---------------- host orchestration ----------------
extern "C" void kernel_launch(void* const* d_in, const int* in_sizes, int n_in,
                              void* d_out, int out_size) {
    const float* x        = (const float*)d_in[0];
    const float* wq_down  = (const float*)d_in[1];
    const float* q_norm_w = (const float*)d_in[2];
    const float* wq_up    = (const float*)d_in[3];
    const float* wq_rope  = (const float*)d_in[4];
    const float* wkv_down = (const float*)d_in[5];
    const float* kv_norm_w= (const float*)d_in[6];
    const float* wkv_up   = (const float*)d_in[7];
    const float* wk_rope  = (const float*)d_in[8];
    const float* wo       = (const float*)d_in[9];
    float* out = (float*)d_out;

    float *qc, *kvc, *krope, *qnope, *qpe, *kvup, *Q, *Kt, *attn;
    cudaGetSymbolAddress((void**)&qc,    g_qc);
    cudaGetSymbolAddress((void**)&kvc,   g_kvc);
    cudaGetSymbolAddress((void**)&krope, g_krope);
    cudaGetSymbolAddress((void**)&qnope, g_qnope);
    cudaGetSymbolAddress((void**)&qpe,   g_qpe);
    cudaGetSymbolAddress((void**)&kvup,  g_kvup);
    cudaGetSymbolAddress((void**)&Q,     g_Q);
    cudaGetSymbolAddress((void**)&Kt,    g_Kt);
    cudaGetSymbolAddress((void**)&attn,  g_attn);

    // down projections + shared rope key
    sgemm_nt<<<dim3(12, 32), 256>>>(x, wq_down,  qc,    4096, 1536, 2048);
    sgemm_nt<<<dim3(4,  32), 256>>>(x, wkv_down, kvc,   4096, 512,  2048);
    sgemm_nt<<<dim3(1,  32), 256>>>(x, wk_rope,  krope, 4096, 64,   2048);

    rmsnorm_k<<<4096, 256>>>(qc,  q_norm_w,  1536);
    rmsnorm_k<<<4096, 256>>>(kvc, kv_norm_w, 512);

    // up projections
    sgemm_nt<<<dim3(16, 32), 256>>>(qc,  wq_up,   qnope, 4096, 2048, 1536);
    sgemm_nt<<<dim3(8,  32), 256>>>(qc,  wq_rope, qpe,   4096, 1024, 1536);
    sgemm_nt<<<dim3(32, 32), 256>>>(kvc, wkv_up,  kvup,  4096, 4096, 512);

    // assemble Q / K^T with RoPE fused
    assemble_q <<<(32*2048*192 + 255)/256, 256>>>(qnope, qpe, Q);
    assemble_kt<<<dim3(64, 6, 32), dim3(32, 32)>>>(kvup, krope, Kt);

    // flash attention
    const int smem = FLASH_SMEM_FLOATS * (int)sizeof(float);   // 150528 B
    cudaFuncSetAttribute(flash_kernel, cudaFuncAttributeMaxDynamicSharedMemorySize, smem);
    flash_kernel<<<dim3(32, 16, 2), 256, smem>>>(Q, Kt, kvup, attn);

    // output projection
    sgemm_nt<<<dim3(16, 32), 256>>>(attn, wo, out, 4096, 2048, 2048);
}

// round 2
// speedup vs baseline: 1.2866x; 1.2866x over previous
#include <cuda_runtime.h>
#include <math.h>
#include <stdint.h>

// ---------------- static scratch (no allocations allowed) ----------------
__device__ float g_qc   [4096*1536];          // q_c (rmsnormed in place)
__device__ float g_kvc  [4096*512];           // kv_c
__device__ float g_krope[4096*64];            // x @ wk_rope^T (pre-rope)
__device__ float g_qnope[4096*2048];          // q_c @ wq_up^T
__device__ float g_qpe  [4096*1024];          // q_c @ wq_rope^T (pre-rope)
__device__ float g_kvup [4096ull*4096];       // kv_c @ wkv_up^T  (k_nope | v interleaved per head)
__device__ float g_Q    [32ull*2048*192];     // assembled Q  [b,h][s][192]
__device__ float g_Kt   [32ull*192*2048];     // assembled K^T [b,h][d][s]
__device__ float g_attn [4096*2048];          // attention out [m][h*128+c]

// ---------------- tf32 helpers ----------------
__device__ __forceinline__ uint32_t f2tf32(float x) {
    uint32_t u; asm("cvt.rna.tf32.f32 %0, %1;" : "=r"(u) : "f"(x));
    return u;
}

__device__ __forceinline__ void mma8(float* d, const uint32_t* a, const uint32_t* b) {
    asm volatile("mma.sync.aligned.m16n8k8.row.col.f32.tf32.tf32.f32 "
        "{%0,%1,%2,%3}, {%4,%5,%6,%7}, {%8,%9}, {%0,%1,%2,%3};"
        : "+f"(d[0]), "+f"(d[1]), "+f"(d[2]), "+f"(d[3])
        : "r"(a[0]), "r"(a[1]), "r"(a[2]), "r"(a[3]), "r"(b[0]), "r"(b[1]));
}

// ---------------- tensor-core GEMM: C[M,N] = A[M,K] @ B[N,K]^T (3xTF32) ----------------
// BM=BN=128, BK=16, 256 threads (8 warps, 2x4), warp tile 64x32.
// M multiple of 128, K multiple of 16; N arbitrary multiple of 8 (guarded).
#define SPAD 20   // smem row stride (floats): conflict-free for frag loads
__global__ __launch_bounds__(256) void gemm_tf32(const float* __restrict__ A,
                                                 const float* __restrict__ B,
                                                 float* __restrict__ C,
                                                 int M, int N, int K) {
    __shared__ float Ah[128*SPAD], Al[128*SPAD], Bh[128*SPAD], Bl[128*SPAD];
    const int tid = threadIdx.x;
    const int bx = blockIdx.x, by = blockIdx.y;
    const int w = tid >> 5, lane = tid & 31;
    const int wm = (w >> 2) * 64;      // warp row origin in tile
    const int wn = (w & 3) * 32;       // warp col origin in tile
    const int g = lane >> 2, t = lane & 3;

    // gmem load mapping: each thread loads 2 float4 of A and 2 of B per BK step
    const int lrow = tid >> 2;          // 0..63
    const int lk   = (tid & 3) * 4;     // 0,4,8,12
    const float* Ap0 = A + (size_t)(by * 128 + lrow) * K + lk;
    const float* Ap1 = Ap0 + (size_t)64 * K;
    const int nrow0 = bx * 128 + lrow, nrow1 = nrow0 + 64;
    const float* Bp0 = B + (size_t)nrow0 * K + lk;
    const float* Bp1 = B + (size_t)nrow1 * K + lk;
    const bool b0ok = nrow0 < N, b1ok = nrow1 < N;

    float acc[4][4][4];
    #pragma unroll
    for (int mt = 0; mt < 4; mt++)
        #pragma unroll
        for (int nt = 0; nt < 4; nt++)
            #pragma unroll
            for (int i = 0; i < 4; i++) acc[mt][nt][i] = 0.f;

    const float4 z4 = make_float4(0.f, 0.f, 0.f, 0.f);
    float4 fa0 = *(const float4*)(Ap0);
    float4 fa1 = *(const float4*)(Ap1);
    float4 fb0 = b0ok ? *(const float4*)(Bp0) : z4;
    float4 fb1 = b1ok ? *(const float4*)(Bp1) : z4;

    for (int k0 = 0; ; ) {
        // split current tile into (hi, lo) and store to smem
        {
            float4 h, l;
            #define SPLIT_ST(H, L, ROW, V) do { \
                h.x = __uint_as_float(f2tf32((V).x)); l.x = (V).x - h.x; \
                h.y = __uint_as_float(f2tf32((V).y)); l.y = (V).y - h.y; \
                h.z = __uint_as_float(f2tf32((V).z)); l.z = (V).z - h.z; \
                h.w = __uint_as_float(f2tf32((V).w)); l.w = (V).w - h.w; \
                *(float4*)&(H)[(ROW) * SPAD + lk] = h; \
                *(float4*)&(L)[(ROW) * SPAD + lk] = l; } while (0)
            SPLIT_ST(Ah, Al, lrow,      fa0);
            SPLIT_ST(Ah, Al, lrow + 64, fa1);
            SPLIT_ST(Bh, Bl, lrow,      fb0);
            SPLIT_ST(Bh, Bl, lrow + 64, fb1);
            #undef SPLIT_ST
        }
        __syncthreads();

        const bool more = (k0 + 16) < K;
        if (more) {   // prefetch next tile (LDG latency overlaps mma work)
            fa0 = *(const float4*)(Ap0 + k0 + 16);
            fa1 = *(const float4*)(Ap1 + k0 + 16);
            fb0 = b0ok ? *(const float4*)(Bp0 + k0 + 16) : z4;
            fb1 = b1ok ? *(const float4*)(Bp1 + k0 + 16) : z4;
        }

        #pragma unroll
        for (int ks = 0; ks < 16; ks += 8) {
            uint32_t ah[4][4], al[4][4], bh[4][2], bl[4][2];
            #pragma unroll
            for (int mt = 0; mt < 4; mt++) {
                const int ra = (wm + mt * 16 + g) * SPAD + ks + t;
                const int rb = ra + 8 * SPAD;
                ah[mt][0] = __float_as_uint(Ah[ra]);
                ah[mt][1] = __float_as_uint(Ah[rb]);
                ah[mt][2] = __float_as_uint(Ah[ra + 4]);
                ah[mt][3] = __float_as_uint(Ah[rb + 4]);
                al[mt][0] = __float_as_uint(Al[ra]);
                al[mt][1] = __float_as_uint(Al[rb]);
                al[mt][2] = __float_as_uint(Al[ra + 4]);
                al[mt][3] = __float_as_uint(Al[rb + 4]);
            }
            #pragma unroll
            for (int nt = 0; nt < 4; nt++) {
                const int rn = (wn + nt * 8 + g) * SPAD + ks + t;
                bh[nt][0] = __float_as_uint(Bh[rn]);
                bh[nt][1] = __float_as_uint(Bh[rn + 4]);
                bl[nt][0] = __float_as_uint(Bl[rn]);
                bl[nt][1] = __float_as_uint(Bl[rn + 4]);
            }
            #pragma unroll
            for (int mt = 0; mt < 4; mt++)
                #pragma unroll
                for (int nt = 0; nt < 4; nt++) {
                    mma8(acc[mt][nt], ah[mt], bh[nt]);   // hi*hi
                    mma8(acc[mt][nt], ah[mt], bl[nt]);   // hi*lo
                    mma8(acc[mt][nt], al[mt], bh[nt]);   // lo*hi
                }
        }
        k0 += 16;
        if (!more) break;
        __syncthreads();
    }

    // epilogue
    #pragma unroll
    for (int mt = 0; mt < 4; mt++) {
        const int row = by * 128 + wm + mt * 16 + g;
        #pragma unroll
        for (int nt = 0; nt < 4; nt++) {
            const int col = bx * 128 + wn + nt * 8 + 2 * t;
            if (col < N) {
                float* cp = C + (size_t)row * N + col;
                *(float2*)cp             = make_float2(acc[mt][nt][0], acc[mt][nt][1]);
                *(float2*)(cp + 8 * (size_t)N) = make_float2(acc[mt][nt][2], acc[mt][nt][3]);
            }
        }
    }
}

// ---------------- RMSNorm (in place, one block per row) ----------------
__global__ __launch_bounds__(256) void rmsnorm_k(float* __restrict__ x,
                                                 const float* __restrict__ w, int cols) {
    const int row = blockIdx.x;
    float* xr = x + (size_t)row * cols;
    const int tid = threadIdx.x;
    float s = 0.f;
    for (int c = tid; c < cols; c += 256) { float v = xr[c]; s = fmaf(v, v, s); }
    __shared__ float red[256];
    red[tid] = s; __syncthreads();
    for (int st = 128; st > 0; st >>= 1) {
        if (tid < st) red[tid] += red[tid + st];
        __syncthreads();
    }
    const float inv = rsqrtf(red[0] / (float)cols + 1e-6f);
    for (int c = tid; c < cols; c += 256) xr[c] = xr[c] * inv * w[c];
}

// ---------------- RoPE helper (LLaMA interleaved pairs, d=64) ----------------
__device__ __forceinline__ float rope_val(const float* __restrict__ src, int base, int j, int s) {
    const int p = j & ~1;                              // pair start (even)
    const float inv = powf(10000.0f, -(float)p * (1.0f/64.0f));
    const float ang = (float)s * inv;
    float sn, cs; sincosf(ang, &sn, &cs);
    const float x1 = src[base + p], x2 = src[base + p + 1];
    return (j & 1) ? fmaf(x1, sn, x2 * cs) : fmaf(x1, cs, -x2 * sn);
}

// ---------------- assemble Q: [b,h][s][192] = [q_nope | rope(q_pe)] ----------------
__global__ __launch_bounds__(256) void assemble_q(const float* __restrict__ qn,
                                                  const float* __restrict__ qp,
                                                  float* __restrict__ Qg) {
    const int idx = blockIdx.x * 256 + threadIdx.x;
    const int total = 32 * 2048 * 192;
    if (idx >= total) return;
    const int d  = idx % 192;
    const int t  = idx / 192;
    const int s  = t & 2047;
    const int bh = t >> 11;
    const int b = bh >> 4, h = bh & 15;
    const int m = b * 2048 + s;
    float val;
    if (d < 128) val = qn[(size_t)m * 2048 + h * 128 + d];
    else         val = rope_val(qp, m * 1024 + h * 64, d - 128, s);
    Qg[idx] = val;
}

// ---------------- assemble K^T: [b,h][d][s] = [k_nope | rope(k_rope)]^T ----------------
__global__ void assemble_kt(const float* __restrict__ kvup,
                            const float* __restrict__ krope,
                            float* __restrict__ Kt) {
    __shared__ float tile[32][33];
    const int bh = blockIdx.z;
    const int b = bh >> 4, h = bh & 15;
    const int d0 = blockIdx.y * 32, s0 = blockIdx.x * 32;
    const int txi = threadIdx.x, tyi = threadIdx.y;
    const int s = s0 + tyi, d = d0 + txi;
    const int m = b * 2048 + s;
    float val;
    if (d < 128) val = kvup[(size_t)m * 4096 + h * 256 + d];
    else         val = rope_val(krope, m * 64, d - 128, s);
    tile[tyi][txi] = val;
    __syncthreads();
    Kt[((size_t)bh * 192 + d0 + tyi) * 2048 + s0 + txi] = tile[txi][tyi];
}

// ---------------- flash attention (causal, fp32, 64x64 tiles) ----------------
#define FLASH_SMEM_FLOATS (64*192 + 192*68 + 64*128 + 64*64)
__global__ __launch_bounds__(256) void flash_kernel(const float* __restrict__ Qg,
                                                    const float* __restrict__ Ktg,
                                                    const float* __restrict__ kvup,
                                                    float* __restrict__ Og) {
    extern __shared__ float sm[];
    float* Qs = sm;                    // [64][192] row-major
    float* Ks = sm + 64*192;           // [192][68] k-major (pad 64->68)
    float* Vs = Ks + 192*68;           // [64][128] row-major
    float* Ps = Vs + 64*128;           // [64][64]

    const int qt = blockIdx.x, h = blockIdx.y, b = blockIdx.z;
    const int bh = b * 16 + h;
    const int tid = threadIdx.x, tx = tid & 15, ty = tid >> 4;

    const float4* qg4 = (const float4*)(Qg + ((size_t)bh * 2048 + qt * 64) * 192);
    for (int i = tid; i < 64 * 48; i += 256) ((float4*)Qs)[i] = qg4[i];

    float m_i[4], l_i[4], o[4][8];
    #pragma unroll
    for (int i = 0; i < 4; i++) {
        m_i[i] = -INFINITY; l_i[i] = 0.f;
        #pragma unroll
        for (int j = 0; j < 8; j++) o[i][j] = 0.f;
    }
    __syncthreads();

    const float* ktg = Ktg + (size_t)bh * 192 * 2048;
    const float* vg0 = kvup + (size_t)b * 2048 * 4096 + h * 256 + 128;
    const float scale = 0.07216878364870323f;   // 1/sqrt(192)

    for (int kt = 0; kt <= qt; kt++) {
        for (int i = tid; i < 192 * 16; i += 256) {
            int dd = i >> 4, q4 = i & 15;
            float4 v = *(const float4*)(ktg + (size_t)dd * 2048 + kt * 64 + q4 * 4);
            *(float4*)&Ks[dd * 68 + q4 * 4] = v;
        }
        const float* vg = vg0 + (size_t)kt * 64 * 4096;
        for (int i = tid; i < 64 * 32; i += 256) {
            int r = i >> 5, c4 = i & 31;
            *(float4*)&Vs[r * 128 + c4 * 4] = *(const float4*)(vg + (size_t)r * 4096 + c4 * 4);
        }
        __syncthreads();

        float sacc[4][4];
        #pragma unroll
        for (int i = 0; i < 4; i++)
            #pragma unroll
            for (int j = 0; j < 4; j++) sacc[i][j] = 0.f;

        for (int k0 = 0; k0 < 192; k0 += 4) {
            float qv[4][4];
            #pragma unroll
            for (int i = 0; i < 4; i++) {
                float4 tq = *(const float4*)&Qs[(ty * 4 + i) * 192 + k0];
                qv[i][0]=tq.x; qv[i][1]=tq.y; qv[i][2]=tq.z; qv[i][3]=tq.w;
            }
            #pragma unroll
            for (int kk = 0; kk < 4; kk++) {
                float4 kvv = *(const float4*)&Ks[(k0 + kk) * 68 + tx * 4];
                float kv[4] = {kvv.x, kvv.y, kvv.z, kvv.w};
                #pragma unroll
                for (int i = 0; i < 4; i++)
                    #pragma unroll
                    for (int j = 0; j < 4; j++)
                        sacc[i][j] = fmaf(qv[i][kk], kv[j], sacc[i][j]);
            }
        }

        const bool diag = (kt == qt);
        #pragma unroll
        for (int i = 0; i < 4; i++) {
            const int rg = (qt << 6) + (ty << 2) + i;
            float sv[4];
            float rmax = -INFINITY;
            #pragma unroll
            for (int j = 0; j < 4; j++) {
                float v = sacc[i][j] * scale;
                if (diag) {
                    int cg = (kt << 6) + (tx << 2) + j;
                    if (cg > rg) v = -INFINITY;
                }
                sv[j] = v;
                rmax = fmaxf(rmax, v);
            }
            #pragma unroll
            for (int off = 8; off > 0; off >>= 1)
                rmax = fmaxf(rmax, __shfl_xor_sync(0xffffffffu, rmax, off, 16));
            const float mnew  = fmaxf(m_i[i], rmax);
            const float alpha = expf(m_i[i] - mnew);
            float ps = 0.f;
            #pragma unroll
            for (int j = 0; j < 4; j++) {
                float p = expf(sv[j] - mnew);
                Ps[(ty * 4 + i) * 64 + tx * 4 + j] = p;
                ps += p;
            }
            #pragma unroll
            for (int off = 8; off > 0; off >>= 1)
                ps += __shfl_xor_sync(0xffffffffu, ps, off, 16);
            l_i[i] = l_i[i] * alpha + ps;
            m_i[i] = mnew;
            #pragma unroll
            for (int j = 0; j < 8; j++) o[i][j] *= alpha;
        }
        __syncthreads();

        for (int k0 = 0; k0 < 64; k0 += 4) {
            float pv[4][4];
            #pragma unroll
            for (int i = 0; i < 4; i++) {
                float4 tp = *(const float4*)&Ps[(ty * 4 + i) * 64 + k0];
                pv[i][0]=tp.x; pv[i][1]=tp.y; pv[i][2]=tp.z; pv[i][3]=tp.w;
            }
            #pragma unroll
            for (int kk = 0; kk < 4; kk++) {
                const float* vr = &Vs[(k0 + kk) * 128 + tx * 8];
                float4 v0 = *(const float4*)vr;
                float4 v1 = *(const float4*)(vr + 4);
                float vv[8] = {v0.x,v0.y,v0.z,v0.w,v1.x,v1.y,v1.z,v1.w};
                #pragma unroll
                for (int i = 0; i < 4; i++)
                    #pragma unroll
                    for (int j = 0; j < 8; j++)
                        o[i][j] = fmaf(pv[i][kk], vv[j], o[i][j]);
            }
        }
        __syncthreads();
    }

    #pragma unroll
    for (int i = 0; i < 4; i++) {
        const float inv = 1.f / l_i[i];
        const int s = (qt << 6) + (ty << 2) + i;
        float* orow = Og + ((size_t)(b * 2048 + s)) * 2048 + h * 128 + tx * 8;
        *(float4*)orow       = make_float4(o[i][0]*inv, o[i][1]*inv, o[i][2]*inv, o[i][3]*inv);
        *(float4*)(orow + 4) = make_float4(o[i][4]*inv, o[i][5]*inv, o[i][6]*inv, o[i][7]*inv);
    }
}

// ---------------- host orchestration ----------------
extern "C" void kernel_launch(void* const* d_in, const int* in_sizes, int n_in,
                              void* d_out, int out_size) {
    const float* x        = (const float*)d_in[0];
    const float* wq_down  = (const float*)d_in[1];
    const float* q_norm_w = (const float*)d_in[2];
    const float* wq_up    = (const float*)d_in[3];
    const float* wq_rope  = (const float*)d_in[4];
    const float* wkv_down = (const float*)d_in[5];
    const float* kv_norm_w= (const float*)d_in[6];
    const float* wkv_up   = (const float*)d_in[7];
    const float* wk_rope  = (const float*)d_in[8];
    const float* wo       = (const float*)d_in[9];
    float* out = (float*)d_out;

    float *qc, *kvc, *krope, *qnope, *qpe, *kvup, *Q, *Kt, *attn;
    cudaGetSymbolAddress((void**)&qc,    g_qc);
    cudaGetSymbolAddress((void**)&kvc,   g_kvc);
    cudaGetSymbolAddress((void**)&krope, g_krope);
    cudaGetSymbolAddress((void**)&qnope, g_qnope);
    cudaGetSymbolAddress((void**)&qpe,   g_qpe);
    cudaGetSymbolAddress((void**)&kvup,  g_kvup);
    cudaGetSymbolAddress((void**)&Q,     g_Q);
    cudaGetSymbolAddress((void**)&Kt,    g_Kt);
    cudaGetSymbolAddress((void**)&attn,  g_attn);

    // down projections + shared rope key (tensor cores, 3xTF32)
    gemm_tf32<<<dim3(12, 32), 256>>>(x, wq_down,  qc,    4096, 1536, 2048);
    gemm_tf32<<<dim3(4,  32), 256>>>(x, wkv_down, kvc,   4096, 512,  2048);
    gemm_tf32<<<dim3(1,  32), 256>>>(x, wk_rope,  krope, 4096, 64,   2048);

    rmsnorm_k<<<4096, 256>>>(qc,  q_norm_w,  1536);
    rmsnorm_k<<<4096, 256>>>(kvc, kv_norm_w, 512);

    // up projections
    gemm_tf32<<<dim3(16, 32), 256>>>(qc,  wq_up,   qnope, 4096, 2048, 1536);
    gemm_tf32<<<dim3(8,  32), 256>>>(qc,  wq_rope, qpe,   4096, 1024, 1536);
    gemm_tf32<<<dim3(32, 32), 256>>>(kvc, wkv_up,  kvup,  4096, 4096, 512);

    // assemble Q / K^T with RoPE fused
    assemble_q <<<(32*2048*192 + 255)/256, 256>>>(qnope, qpe, Q);
    assemble_kt<<<dim3(64, 6, 32), dim3(32, 32)>>>(kvup, krope, Kt);

    // flash attention
    const int smem = FLASH_SMEM_FLOATS * (int)sizeof(float);   // 150528 B
    cudaFuncSetAttribute(flash_kernel, cudaFuncAttributeMaxDynamicSharedMemorySize, smem);
    flash_kernel<<<dim3(32, 16, 2), 256, smem>>>(Q, Kt, kvup, attn);

    // output projection
    gemm_tf32<<<dim3(16, 32), 256>>>(attn, wo, out, 4096, 2048, 2048);
}

// round 3
// speedup vs baseline: 1.4730x; 1.1449x over previous
#include <cuda_runtime.h>
#include <math.h>
#include <stdint.h>

// ---------------- static scratch (no allocations allowed) ----------------
__device__ float g_qc   [4096*1536];          // q_c (rmsnormed in place)
__device__ float g_kvc  [4096*512];           // kv_c
__device__ float g_krope[4096*64];            // x @ wk_rope^T (pre-rope)
__device__ float g_qnope[4096*2048];          // q_c @ wq_up^T
__device__ float g_qpe  [4096*1024];          // q_c @ wq_rope^T (pre-rope)
__device__ float g_kvup [4096ull*4096];       // kv_c @ wkv_up^T  (k_nope | v interleaved per head)
__device__ float g_Q    [32ull*2048*192];     // assembled Q  [b,h][s][192]
__device__ float g_K    [32ull*2048*192];     // assembled K  [b,h][s][192]  (row-major, like Q)
__device__ float g_attn [4096*2048];          // attention out [m][h*128+c]

// ---------------- tf32 helpers ----------------
__device__ __forceinline__ uint32_t f2tf32(float x) {
    uint32_t u; asm("cvt.rna.tf32.f32 %0, %1;" : "=r"(u) : "f"(x));
    return u;
}
// hi = rna-tf32(x); lo = x - hi (raw fp32 bits; mma truncates low mantissa, err ~2^-22)
__device__ __forceinline__ void split1(float x, uint32_t& h, uint32_t& l) {
    h = f2tf32(x);
    l = __float_as_uint(x - __uint_as_float(h));
}

__device__ __forceinline__ void mma8(float* d, const uint32_t* a, const uint32_t* b) {
    asm volatile("mma.sync.aligned.m16n8k8.row.col.f32.tf32.tf32.f32 "
        "{%0,%1,%2,%3}, {%4,%5,%6,%7}, {%8,%9}, {%0,%1,%2,%3};"
        : "+f"(d[0]), "+f"(d[1]), "+f"(d[2]), "+f"(d[3])
        : "r"(a[0]), "r"(a[1]), "r"(a[2]), "r"(a[3]), "r"(b[0]), "r"(b[1]));
}

// ---------------- tensor-core GEMM: C[M,N] = A[M,K] @ B[N,K]^T (3xTF32) ----------------
#define SPAD 20
__global__ __launch_bounds__(256) void gemm_tf32(const float* __restrict__ A,
                                                 const float* __restrict__ B,
                                                 float* __restrict__ C,
                                                 int M, int N, int K) {
    __shared__ float Ah[128*SPAD], Al[128*SPAD], Bh[128*SPAD], Bl[128*SPAD];
    const int tid = threadIdx.x;
    const int bx = blockIdx.x, by = blockIdx.y;
    const int w = tid >> 5, lane = tid & 31;
    const int wm = (w >> 2) * 64;
    const int wn = (w & 3) * 32;
    const int g = lane >> 2, t = lane & 3;

    const int lrow = tid >> 2;
    const int lk   = (tid & 3) * 4;
    const float* Ap0 = A + (size_t)(by * 128 + lrow) * K + lk;
    const float* Ap1 = Ap0 + (size_t)64 * K;
    const int nrow0 = bx * 128 + lrow, nrow1 = nrow0 + 64;
    const float* Bp0 = B + (size_t)nrow0 * K + lk;
    const float* Bp1 = B + (size_t)nrow1 * K + lk;
    const bool b0ok = nrow0 < N, b1ok = nrow1 < N;

    float acc[4][4][4];
    #pragma unroll
    for (int mt = 0; mt < 4; mt++)
        #pragma unroll
        for (int nt = 0; nt < 4; nt++)
            #pragma unroll
            for (int i = 0; i < 4; i++) acc[mt][nt][i] = 0.f;

    const float4 z4 = make_float4(0.f, 0.f, 0.f, 0.f);
    float4 fa0 = *(const float4*)(Ap0);
    float4 fa1 = *(const float4*)(Ap1);
    float4 fb0 = b0ok ? *(const float4*)(Bp0) : z4;
    float4 fb1 = b1ok ? *(const float4*)(Bp1) : z4;

    for (int k0 = 0; ; ) {
        {
            float4 h, l;
            #define SPLIT_ST(H, L, ROW, V) do { \
                h.x = __uint_as_float(f2tf32((V).x)); l.x = (V).x - h.x; \
                h.y = __uint_as_float(f2tf32((V).y)); l.y = (V).y - h.y; \
                h.z = __uint_as_float(f2tf32((V).z)); l.z = (V).z - h.z; \
                h.w = __uint_as_float(f2tf32((V).w)); l.w = (V).w - h.w; \
                *(float4*)&(H)[(ROW) * SPAD + lk] = h; \
                *(float4*)&(L)[(ROW) * SPAD + lk] = l; } while (0)
            SPLIT_ST(Ah, Al, lrow,      fa0);
            SPLIT_ST(Ah, Al, lrow + 64, fa1);
            SPLIT_ST(Bh, Bl, lrow,      fb0);
            SPLIT_ST(Bh, Bl, lrow + 64, fb1);
            #undef SPLIT_ST
        }
        __syncthreads();

        const bool more = (k0 + 16) < K;
        if (more) {
            fa0 = *(const float4*)(Ap0 + k0 + 16);
            fa1 = *(const float4*)(Ap1 + k0 + 16);
            fb0 = b0ok ? *(const float4*)(Bp0 + k0 + 16) : z4;
            fb1 = b1ok ? *(const float4*)(Bp1 + k0 + 16) : z4;
        }

        #pragma unroll
        for (int ks = 0; ks < 16; ks += 8) {
            uint32_t ah[4][4], al[4][4], bh[4][2], bl[4][2];
            #pragma unroll
            for (int mt = 0; mt < 4; mt++) {
                const int ra = (wm + mt * 16 + g) * SPAD + ks + t;
                const int rb = ra + 8 * SPAD;
                ah[mt][0] = __float_as_uint(Ah[ra]);
                ah[mt][1] = __float_as_uint(Ah[rb]);
                ah[mt][2] = __float_as_uint(Ah[ra + 4]);
                ah[mt][3] = __float_as_uint(Ah[rb + 4]);
                al[mt][0] = __float_as_uint(Al[ra]);
                al[mt][1] = __float_as_uint(Al[rb]);
                al[mt][2] = __float_as_uint(Al[ra + 4]);
                al[mt][3] = __float_as_uint(Al[rb + 4]);
            }
            #pragma unroll
            for (int nt = 0; nt < 4; nt++) {
                const int rn = (wn + nt * 8 + g) * SPAD + ks + t;
                bh[nt][0] = __float_as_uint(Bh[rn]);
                bh[nt][1] = __float_as_uint(Bh[rn + 4]);
                bl[nt][0] = __float_as_uint(Bl[rn]);
                bl[nt][1] = __float_as_uint(Bl[rn + 4]);
            }
            #pragma unroll
            for (int mt = 0; mt < 4; mt++)
                #pragma unroll
                for (int nt = 0; nt < 4; nt++) {
                    mma8(acc[mt][nt], ah[mt], bh[nt]);
                    mma8(acc[mt][nt], ah[mt], bl[nt]);
                    mma8(acc[mt][nt], al[mt], bh[nt]);
                }
        }
        k0 += 16;
        if (!more) break;
        __syncthreads();
    }

    #pragma unroll
    for (int mt = 0; mt < 4; mt++) {
        const int row = by * 128 + wm + mt * 16 + g;
        #pragma unroll
        for (int nt = 0; nt < 4; nt++) {
            const int col = bx * 128 + wn + nt * 8 + 2 * t;
            if (col < N) {
                float* cp = C + (size_t)row * N + col;
                *(float2*)cp                   = make_float2(acc[mt][nt][0], acc[mt][nt][1]);
                *(float2*)(cp + 8 * (size_t)N) = make_float2(acc[mt][nt][2], acc[mt][nt][3]);
            }
        }
    }
}

// ---------------- RMSNorm ----------------
__global__ __launch_bounds__(256) void rmsnorm_k(float* __restrict__ x,
                                                 const float* __restrict__ w, int cols) {
    const int row = blockIdx.x;
    float* xr = x + (size_t)row * cols;
    const int tid = threadIdx.x;
    float s = 0.f;
    for (int c = tid; c < cols; c += 256) { float v = xr[c]; s = fmaf(v, v, s); }
    __shared__ float red[256];
    red[tid] = s; __syncthreads();
    for (int st = 128; st > 0; st >>= 1) {
        if (tid < st) red[tid] += red[tid + st];
        __syncthreads();
    }
    const float inv = rsqrtf(red[0] / (float)cols + 1e-6f);
    for (int c = tid; c < cols; c += 256) xr[c] = xr[c] * inv * w[c];
}

// ---------------- RoPE helper ----------------
__device__ __forceinline__ float rope_val(const float* __restrict__ src, int base, int j, int s) {
    const int p = j & ~1;
    const float inv = powf(10000.0f, -(float)p * (1.0f/64.0f));
    const float ang = (float)s * inv;
    float sn, cs; sincosf(ang, &sn, &cs);
    const float x1 = src[base + p], x2 = src[base + p + 1];
    return (j & 1) ? fmaf(x1, sn, x2 * cs) : fmaf(x1, cs, -x2 * sn);
}

// ---------------- assemble Q: [b,h][s][192] ----------------
__global__ __launch_bounds__(256) void assemble_q(const float* __restrict__ qn,
                                                  const float* __restrict__ qp,
                                                  float* __restrict__ Qg) {
    const int idx = blockIdx.x * 256 + threadIdx.x;
    const int total = 32 * 2048 * 192;
    if (idx >= total) return;
    const int d  = idx % 192;
    const int t  = idx / 192;
    const int s  = t & 2047;
    const int bh = t >> 11;
    const int b = bh >> 4, h = bh & 15;
    const int m = b * 2048 + s;
    float val;
    if (d < 128) val = qn[(size_t)m * 2048 + h * 128 + d];
    else         val = rope_val(qp, m * 1024 + h * 64, d - 128, s);
    Qg[idx] = val;
}

// ---------------- assemble K: [b,h][s][192] row-major (like Q) ----------------
__global__ __launch_bounds__(256) void assemble_k(const float* __restrict__ kvup,
                                                  const float* __restrict__ krope,
                                                  float* __restrict__ Kg) {
    const int idx = blockIdx.x * 256 + threadIdx.x;
    const int total = 32 * 2048 * 192;
    if (idx >= total) return;
    const int d  = idx % 192;
    const int t  = idx / 192;
    const int s  = t & 2047;
    const int bh = t >> 11;
    const int b = bh >> 4, h = bh & 15;
    const int m = b * 2048 + s;
    float val;
    if (d < 128) val = kvup[(size_t)m * 4096 + h * 256 + d];
    else         val = rope_val(krope, m * 64, d - 128, s);
    Kg[idx] = val;
}

// ---------------- tensor-core flash attention (causal, 3xTF32) ----------------
// block: 256 thr = 8 warps = (qg 0..3 owns 16 q-rows) x (nhalf 0..1 owns 32 S-cols / 64 dv-cols)
// q tile 64, kv tile 64. Smem strides: 196 (Q,K), 136 (V), 68 (P) -> conflict-free frags.
#define SQ 196
#define SV 136
#define SP 68
#define FL_SMEM ((64*SQ*2 + 64*SV + 64*SP + 4*64) * 4)
__global__ __launch_bounds__(256) void flash_mma(const float* __restrict__ Qg,
                                                 const float* __restrict__ Kg,
                                                 const float* __restrict__ kvup,
                                                 float* __restrict__ Og) {
    extern __shared__ float sm[];
    float* Qs   = sm;                    // [64][196]
    float* Ks   = Qs + 64*SQ;            // [64][196]
    float* Vs   = Ks + 64*SQ;            // [64][136]
    float* Ps   = Vs + 64*SV;            // [64][68]
    float* sMax = Ps + 64*SP;            // [2][64]
    float* sSum = sMax + 2*64;           // [2][64]

    const int qt = 31 - blockIdx.x;      // reversed: big workloads scheduled first
    const int bh = blockIdx.y;
    const int b = bh >> 4, h = bh & 15;
    const int tid = threadIdx.x;
    const int w = tid >> 5, lane = tid & 31;
    const int qg = w & 3, nhalf = w >> 2;
    const int g = lane >> 2, t = lane & 3;
    const int qrow = qg * 16;

    // load Q tile (64 x 192)
    const int lr = tid >> 2, lc = tid & 3;
    {
        const float4* Qg4 = (const float4*)(Qg + ((size_t)bh * 2048 + qt * 64) * 192);
        #pragma unroll
        for (int c = lc; c < 48; c += 4)
            *(float4*)&Qs[lr * SQ + c * 4] = Qg4[lr * 48 + c];
    }

    float m0 = -INFINITY, m1 = -INFINITY, l0 = 0.f, l1 = 0.f;
    float o[8][4];
    #pragma unroll
    for (int nt = 0; nt < 8; nt++)
        #pragma unroll
        for (int e = 0; e < 4; e++) o[nt][e] = 0.f;

    const float scale = 0.07216878364870323f;   // 1/sqrt(192)
    const float4* Kg4base = (const float4*)(Kg + (size_t)bh * 2048 * 192);
    const float*  vbase   = kvup + (size_t)b * 2048 * 4096 + h * 256 + 128;

    for (int kt = 0; kt <= qt; kt++) {
        __syncthreads();   // previous iteration done with Ks/Vs/Ps
        // load K tile
        {
            const float4* Kg4 = Kg4base + (size_t)(kt * 64) * 48;
            #pragma unroll
            for (int c = lc; c < 48; c += 4)
                *(float4*)&Ks[lr * SQ + c * 4] = Kg4[lr * 48 + c];
        }
        // load V tile
        {
            const float* vg = vbase + (size_t)(kt * 64 + lr) * 4096;
            #pragma unroll
            for (int c = lc; c < 32; c += 4)
                *(float4*)&Vs[lr * SV + c * 4] = *(const float4*)(vg + c * 4);
        }
        __syncthreads();

        // ---- S = Q K^T (m16 x n32 per warp), 3xTF32 ----
        float sa[4][4];
        #pragma unroll
        for (int nt = 0; nt < 4; nt++)
            #pragma unroll
            for (int e = 0; e < 4; e++) sa[nt][e] = 0.f;

        #pragma unroll 4
        for (int ks = 0; ks < 24; ks++) {
            const int d0 = ks * 8;
            uint32_t ah[4], al[4];
            split1(Qs[(qrow + g)     * SQ + d0 + t],     ah[0], al[0]);
            split1(Qs[(qrow + g + 8) * SQ + d0 + t],     ah[1], al[1]);
            split1(Qs[(qrow + g)     * SQ + d0 + t + 4], ah[2], al[2]);
            split1(Qs[(qrow + g + 8) * SQ + d0 + t + 4], ah[3], al[3]);
            #pragma unroll
            for (int nt = 0; nt < 4; nt++) {
                const int kr = (nhalf * 32 + nt * 8 + g) * SQ + d0;
                uint32_t bhh[2], bll[2];
                split1(Ks[kr + t],     bhh[0], bll[0]);
                split1(Ks[kr + t + 4], bhh[1], bll[1]);
                mma8(sa[nt], ah, bhh);
                mma8(sa[nt], ah, bll);
                mma8(sa[nt], al, bhh);
            }
        }

        // ---- scale + causal mask + partial row max ----
        const bool diag = (kt == qt);
        float pm0 = -INFINITY, pm1 = -INFINITY;
        #pragma unroll
        for (int nt = 0; nt < 4; nt++) {
            const int colb = nhalf * 32 + nt * 8 + 2 * t;
            #pragma unroll
            for (int e = 0; e < 4; e++) {
                float v = sa[nt][e] * scale;
                if (diag) {
                    const int col = colb + (e & 1);
                    const int row = qrow + g + ((e >> 1) << 3);
                    if (col > row) v = -INFINITY;
                }
                sa[nt][e] = v;
                if (e < 2) pm0 = fmaxf(pm0, v); else pm1 = fmaxf(pm1, v);
            }
        }
        pm0 = fmaxf(pm0, __shfl_xor_sync(0xffffffffu, pm0, 1));
        pm0 = fmaxf(pm0, __shfl_xor_sync(0xffffffffu, pm0, 2));
        pm1 = fmaxf(pm1, __shfl_xor_sync(0xffffffffu, pm1, 1));
        pm1 = fmaxf(pm1, __shfl_xor_sync(0xffffffffu, pm1, 2));
        if (t == 0) {
            sMax[nhalf * 64 + qrow + g]     = pm0;
            sMax[nhalf * 64 + qrow + g + 8] = pm1;
        }
        __syncthreads();
        const float mn0 = fmaxf(m0, fmaxf(pm0, sMax[(1 - nhalf) * 64 + qrow + g]));
        const float mn1 = fmaxf(m1, fmaxf(pm1, sMax[(1 - nhalf) * 64 + qrow + g + 8]));
        const float al0 = __expf(m0 - mn0);
        const float al1 = __expf(m1 - mn1);

        // ---- exp + store P + partial row sum ----
        float ps0 = 0.f, ps1 = 0.f;
        #pragma unroll
        for (int nt = 0; nt < 4; nt++) {
            const int colb = nhalf * 32 + nt * 8 + 2 * t;
            float p0 = __expf(sa[nt][0] - mn0);
            float p1 = __expf(sa[nt][1] - mn0);
            float p2 = __expf(sa[nt][2] - mn1);
            float p3 = __expf(sa[nt][3] - mn1);
            ps0 += p0 + p1; ps1 += p2 + p3;
            *(float2*)&Ps[(qrow + g)     * SP + colb] = make_float2(p0, p1);
            *(float2*)&Ps[(qrow + g + 8) * SP + colb] = make_float2(p2, p3);
        }
        ps0 += __shfl_xor_sync(0xffffffffu, ps0, 1);
        ps0 += __shfl_xor_sync(0xffffffffu, ps0, 2);
        ps1 += __shfl_xor_sync(0xffffffffu, ps1, 1);
        ps1 += __shfl_xor_sync(0xffffffffu, ps1, 2);
        if (t == 0) {
            sSum[nhalf * 64 + qrow + g]     = ps0;
            sSum[nhalf * 64 + qrow + g + 8] = ps1;
        }
        __syncthreads();
        l0 = l0 * al0 + ps0 + sSum[(1 - nhalf) * 64 + qrow + g];
        l1 = l1 * al1 + ps1 + sSum[(1 - nhalf) * 64 + qrow + g + 8];
        m0 = mn0; m1 = mn1;

        // rescale O
        #pragma unroll
        for (int nt = 0; nt < 8; nt++) {
            o[nt][0] *= al0; o[nt][1] *= al0;
            o[nt][2] *= al1; o[nt][3] *= al1;
        }

        // ---- O += P V (m16 x n64 per warp, k=64), 3xTF32 ----
        #pragma unroll
        for (int kk = 0; kk < 8; kk++) {
            const int k0 = kk * 8;
            uint32_t ah[4], al_[4];
            split1(Ps[(qrow + g)     * SP + k0 + t],     ah[0], al_[0]);
            split1(Ps[(qrow + g + 8) * SP + k0 + t],     ah[1], al_[1]);
            split1(Ps[(qrow + g)     * SP + k0 + t + 4], ah[2], al_[2]);
            split1(Ps[(qrow + g + 8) * SP + k0 + t + 4], ah[3], al_[3]);
            #pragma unroll
            for (int nt = 0; nt < 8; nt++) {
                const int vc = nhalf * 64 + nt * 8 + g;
                uint32_t bhh[2], bll[2];
                split1(Vs[(k0 + t)     * SV + vc], bhh[0], bll[0]);
                split1(Vs[(k0 + t + 4) * SV + vc], bhh[1], bll[1]);
                mma8(o[nt], ah, bhh);
                mma8(o[nt], ah, bll);
                mma8(o[nt], al_, bhh);
            }
        }
    }

    // epilogue
    const float il0 = 1.f / l0, il1 = 1.f / l1;
    const int row0 = b * 2048 + qt * 64 + qrow + g;
    #pragma unroll
    for (int nt = 0; nt < 8; nt++) {
        const int col = h * 128 + nhalf * 64 + nt * 8 + 2 * t;
        float* p0 = Og + (size_t)row0 * 2048 + col;
        *(float2*)p0              = make_float2(o[nt][0] * il0, o[nt][1] * il0);
        *(float2*)(p0 + 8 * 2048) = make_float2(o[nt][2] * il1, o[nt][3] * il1);
    }
}

// ---------------- host orchestration ----------------
extern "C" void kernel_launch(void* const* d_in, const int* in_sizes, int n_in,
                              void* d_out, int out_size) {
    const float* x        = (const float*)d_in[0];
    const float* wq_down  = (const float*)d_in[1];
    const float* q_norm_w = (const float*)d_in[2];
    const float* wq_up    = (const float*)d_in[3];
    const float* wq_rope  = (const float*)d_in[4];
    const float* wkv_down = (const float*)d_in[5];
    const float* kv_norm_w= (const float*)d_in[6];
    const float* wkv_up   = (const float*)d_in[7];
    const float* wk_rope  = (const float*)d_in[8];
    const float* wo       = (const float*)d_in[9];
    float* out = (float*)d_out;

    float *qc, *kvc, *krope, *qnope, *qpe, *kvup, *Q, *K, *attn;
    cudaGetSymbolAddress((void**)&qc,    g_qc);
    cudaGetSymbolAddress((void**)&kvc,   g_kvc);
    cudaGetSymbolAddress((void**)&krope, g_krope);
    cudaGetSymbolAddress((void**)&qnope, g_qnope);
    cudaGetSymbolAddress((void**)&qpe,   g_qpe);
    cudaGetSymbolAddress((void**)&kvup,  g_kvup);
    cudaGetSymbolAddress((void**)&Q,     g_Q);
    cudaGetSymbolAddress((void**)&K,     g_K);
    cudaGetSymbolAddress((void**)&attn,  g_attn);

    gemm_tf32<<<dim3(12, 32), 256>>>(x, wq_down,  qc,    4096, 1536, 2048);
    gemm_tf32<<<dim3(4,  32), 256>>>(x, wkv_down, kvc,   4096, 512,  2048);
    gemm_tf32<<<dim3(1,  32), 256>>>(x, wk_rope,  krope, 4096, 64,   2048);

    rmsnorm_k<<<4096, 256>>>(qc,  q_norm_w,  1536);
    rmsnorm_k<<<4096, 256>>>(kvc, kv_norm_w, 512);

    gemm_tf32<<<dim3(16, 32), 256>>>(qc,  wq_up,   qnope, 4096, 2048, 1536);
    gemm_tf32<<<dim3(8,  32), 256>>>(qc,  wq_rope, qpe,   4096, 1024, 1536);
    gemm_tf32<<<dim3(32, 32), 256>>>(kvc, wkv_up,  kvup,  4096, 4096, 512);

    assemble_q<<<(32*2048*192 + 255)/256, 256>>>(qnope, qpe, Q);
    assemble_k<<<(32*2048*192 + 255)/256, 256>>>(kvup, krope, K);

    cudaFuncSetAttribute(flash_mma, cudaFuncAttributeMaxDynamicSharedMemorySize, FL_SMEM);
    flash_mma<<<dim3(32, 32), 256, FL_SMEM>>>(Q, K, kvup, attn);

    gemm_tf32<<<dim3(16, 32), 256>>>(attn, wo, out, 4096, 2048, 2048);
}

// round 4
// speedup vs baseline: 1.9239x; 1.3061x over previous
#include <cuda_runtime.h>
#include <math.h>
#include <stdint.h>

// ================= static scratch (no allocations allowed) =================
__device__ uint32_t g_xs_h [4096u*1024], g_xs_l [4096u*1024];   // x split [4096][1024p]
__device__ uint32_t g_wqd_h[1536u*1024], g_wqd_l[1536u*1024];   // wq_down
__device__ uint32_t g_wkvc_h[576u*1024], g_wkvc_l[576u*1024];   // wkv_down(512) | wk_rope(64)
__device__ uint32_t g_wqc_h[3072u*768],  g_wqc_l[3072u*768];    // wq_up(2048) | wq_rope(1024)
__device__ uint32_t g_wkvu_h[4096u*256], g_wkvu_l[4096u*256];   // wkv_up
__device__ uint32_t g_wo_h [2048u*1024], g_wo_l [2048u*1024];   // wo
__device__ float    g_qc   [4096u*1536];                        // pre-norm q_c
__device__ float    g_kvcat[4096u*576];                         // kv_c(512) | krope(64)
__device__ uint32_t g_qcs_h[4096u*768],  g_qcs_l[4096u*768];    // normed q_c split
__device__ uint32_t g_kvcs_h[4096u*256], g_kvcs_l[4096u*256];   // normed kv_c split
__device__ float    g_qup  [4096ull*3072];                      // qnope(2048) | qpe(1024)
__device__ float    g_kvup [4096ull*4096];                      // per head: k_nope(128)|v(128)
__device__ uint32_t g_Qh[32ull*2048*96], g_Ql[32ull*2048*96];   // Q packed [bh][s][96p]
__device__ uint32_t g_Kh[32ull*2048*96], g_Kl[32ull*2048*96];   // K packed
__device__ uint32_t g_Vh[32ull*128*1024], g_Vl[32ull*128*1024]; // V^T packed [bh][dv][1024 s-pairs]
__device__ uint32_t g_at_h[4096u*1024], g_at_l[4096u*1024];     // attn out packed [4096][1024p]
__device__ float    g_ropeC[2048*32], g_ropeS[2048*32];

// ================= helpers =================
// pack (x0,x1) -> bf16x2 hi, and residual lo (also bf16x2). hi.lo16 = x0.
__device__ __forceinline__ void splitpack(float x0, float x1, uint32_t& h, uint32_t& l) {
    uint32_t hb;
    asm("cvt.rn.bf16x2.f32 %0, %1, %2;" : "=r"(hb) : "f"(x1), "f"(x0));
    const float h0 = __uint_as_float(hb << 16);
    const float h1 = __uint_as_float(hb & 0xffff0000u);
    uint32_t lb;
    asm("cvt.rn.bf16x2.f32 %0, %1, %2;" : "=r"(lb) : "f"(x1 - h1), "f"(x0 - h0));
    h = hb; l = lb;
}

__device__ __forceinline__ void mma16(float* d, const uint32_t* a, const uint32_t* b) {
    asm volatile("mma.sync.aligned.m16n8k16.row.col.f32.bf16.bf16.f32 "
        "{%0,%1,%2,%3}, {%4,%5,%6,%7}, {%8,%9}, {%0,%1,%2,%3};"
        : "+f"(d[0]), "+f"(d[1]), "+f"(d[2]), "+f"(d[3])
        : "r"(a[0]), "r"(a[1]), "r"(a[2]), "r"(a[3]), "r"(b[0]), "r"(b[1]));
}

// ================= split fp32 -> packed bf16 hi/lo =================
__global__ __launch_bounds__(256) void split_pairs(const float* __restrict__ src,
                                                   uint32_t* __restrict__ h,
                                                   uint32_t* __restrict__ l, int npairs) {
    const int i = blockIdx.x * 256 + threadIdx.x;
    if (i >= npairs) return;
    const float2 v = ((const float2*)src)[i];
    splitpack(v.x, v.y, h[i], l[i]);
}

// ================= packed bf16x3 GEMM: C[M,N] = A[M,K] @ B[N,K]^T =================
// BM=BN=128, BK=16 pairs, 256 thr (8 warps 2x4), warp tile 64x32.
#define GP 20   // smem pair stride (conflict-free: 20g+t covers all banks)
__global__ __launch_bounds__(256) void gemm_pk(
    const uint32_t* __restrict__ Ahg, const uint32_t* __restrict__ Alg,
    const uint32_t* __restrict__ Bhg, const uint32_t* __restrict__ Blg,
    float* __restrict__ C, int M, int N, int Kp) {
    __shared__ uint32_t Ash[128*GP], Asl[128*GP], Bsh[128*GP], Bsl[128*GP];
    const int tid = threadIdx.x, bx = blockIdx.x, by = blockIdx.y;
    const int w = tid >> 5, lane = tid & 31;
    const int wm = (w >> 2) * 64, wn = (w & 3) * 32;
    const int g = lane >> 2, t = lane & 3;
    const int lrow = tid >> 1;
    const int lp   = (tid & 1) * 8;

    const uint32_t* Aph = Ahg + (size_t)(by*128 + lrow) * Kp + lp;
    const uint32_t* Apl = Alg + (size_t)(by*128 + lrow) * Kp + lp;
    const int brow = bx*128 + lrow;
    const uint32_t* Bph = Bhg + (size_t)brow * Kp + lp;
    const uint32_t* Bpl = Blg + (size_t)brow * Kp + lp;
    const bool bok = brow < N;

    float acc[4][4][4];
    #pragma unroll
    for (int mt = 0; mt < 4; mt++)
        #pragma unroll
        for (int nt = 0; nt < 4; nt++)
            #pragma unroll
            for (int i = 0; i < 4; i++) acc[mt][nt][i] = 0.f;

    const uint4 z4 = make_uint4(0,0,0,0);
    uint4 ah0 = *(const uint4*)(Aph),     ah1 = *(const uint4*)(Aph + 4);
    uint4 al0 = *(const uint4*)(Apl),     al1 = *(const uint4*)(Apl + 4);
    uint4 bh0 = bok ? *(const uint4*)(Bph)     : z4;
    uint4 bh1 = bok ? *(const uint4*)(Bph + 4) : z4;
    uint4 bl0 = bok ? *(const uint4*)(Bpl)     : z4;
    uint4 bl1 = bok ? *(const uint4*)(Bpl + 4) : z4;

    for (int kp = 0;;) {
        *(uint4*)&Ash[lrow*GP + lp]     = ah0; *(uint4*)&Ash[lrow*GP + lp + 4] = ah1;
        *(uint4*)&Asl[lrow*GP + lp]     = al0; *(uint4*)&Asl[lrow*GP + lp + 4] = al1;
        *(uint4*)&Bsh[lrow*GP + lp]     = bh0; *(uint4*)&Bsh[lrow*GP + lp + 4] = bh1;
        *(uint4*)&Bsl[lrow*GP + lp]     = bl0; *(uint4*)&Bsl[lrow*GP + lp + 4] = bl1;
        __syncthreads();
        const bool more = (kp + 16) < Kp;
        if (more) {
            ah0 = *(const uint4*)(Aph + kp + 16); ah1 = *(const uint4*)(Aph + kp + 20);
            al0 = *(const uint4*)(Apl + kp + 16); al1 = *(const uint4*)(Apl + kp + 20);
            bh0 = bok ? *(const uint4*)(Bph + kp + 16) : z4;
            bh1 = bok ? *(const uint4*)(Bph + kp + 20) : z4;
            bl0 = bok ? *(const uint4*)(Bpl + kp + 16) : z4;
            bl1 = bok ? *(const uint4*)(Bpl + kp + 20) : z4;
        }
        #pragma unroll
        for (int stp = 0; stp < 2; stp++) {
            const int p0 = stp * 8;
            uint32_t fbh[4][2], fbl[4][2];
            #pragma unroll
            for (int nt = 0; nt < 4; nt++) {
                const int rn = (wn + nt*8 + g) * GP + p0 + t;
                fbh[nt][0] = Bsh[rn]; fbh[nt][1] = Bsh[rn + 4];
                fbl[nt][0] = Bsl[rn]; fbl[nt][1] = Bsl[rn + 4];
            }
            #pragma unroll
            for (int mt = 0; mt < 4; mt++) {
                const int ra = (wm + mt*16 + g) * GP + p0 + t;
                const int rb = ra + 8 * GP;
                uint32_t fah[4] = {Ash[ra], Ash[rb], Ash[ra + 4], Ash[rb + 4]};
                uint32_t fal[4] = {Asl[ra], Asl[rb], Asl[ra + 4], Asl[rb + 4]};
                #pragma unroll
                for (int nt = 0; nt < 4; nt++) {
                    mma16(acc[mt][nt], fah, fbh[nt]);
                    mma16(acc[mt][nt], fah, fbl[nt]);
                    mma16(acc[mt][nt], fal, fbh[nt]);
                }
            }
        }
        kp += 16;
        if (!more) break;
        __syncthreads();
    }

    #pragma unroll
    for (int mt = 0; mt < 4; mt++) {
        const int row = by*128 + wm + mt*16 + g;
        #pragma unroll
        for (int nt = 0; nt < 4; nt++) {
            const int col = bx*128 + wn + nt*8 + 2*t;
            if (col < N) {
                float* cp = C + (size_t)row * N + col;
                *(float2*)cp                   = make_float2(acc[mt][nt][0], acc[mt][nt][1]);
                *(float2*)(cp + 8 * (size_t)N) = make_float2(acc[mt][nt][2], acc[mt][nt][3]);
            }
        }
    }
}

// ================= RMSNorm + split (writes packed bf16 hi/lo) =================
__global__ __launch_bounds__(256) void rmsnorm_split(const float* __restrict__ x, int stride,
                                                     const float* __restrict__ w, int cols,
                                                     uint32_t* __restrict__ oh,
                                                     uint32_t* __restrict__ ol) {
    const int row = blockIdx.x;
    const float* xr = x + (size_t)row * stride;
    const int tid = threadIdx.x;
    float s = 0.f;
    for (int c = tid; c < cols; c += 256) { float v = xr[c]; s = fmaf(v, v, s); }
    __shared__ float red[256];
    red[tid] = s; __syncthreads();
    for (int st = 128; st > 0; st >>= 1) {
        if (tid < st) red[tid] += red[tid + st];
        __syncthreads();
    }
    const float inv = rsqrtf(red[0] / (float)cols + 1e-6f);
    const int pairs = cols >> 1;
    for (int p = tid; p < pairs; p += 256) {
        const float x0 = xr[2*p]     * inv * w[2*p];
        const float x1 = xr[2*p + 1] * inv * w[2*p + 1];
        splitpack(x0, x1, oh[(size_t)row * pairs + p], ol[(size_t)row * pairs + p]);
    }
}

// ================= RoPE table =================
__global__ void rope_table(float* __restrict__ cosT, float* __restrict__ sinT) {
    const int idx = blockIdx.x * 256 + threadIdx.x;
    if (idx >= 2048 * 32) return;
    const int s = idx >> 5, jp = idx & 31;
    const float inv = powf(10000.0f, -(float)(2*jp) * (1.0f/64.0f));
    float sn, cs; sincosf((float)s * inv, &sn, &cs);
    cosT[idx] = cs; sinT[idx] = sn;
}

// ================= assemble Q packed: [bh][s][96p] =================
__global__ __launch_bounds__(256) void assemble_q_pk(const float* __restrict__ qup,
        const float* __restrict__ cosT, const float* __restrict__ sinT,
        uint32_t* __restrict__ Qh, uint32_t* __restrict__ Ql) {
    const int idx = blockIdx.x * 256 + threadIdx.x;
    if (idx >= 32*2048*96) return;
    const int p  = idx % 96;
    const int ts = idx / 96;
    const int s  = ts & 2047;
    const int bh = ts >> 11;
    const int b = bh >> 4, h = bh & 15;
    const int m = b*2048 + s;
    float x0, x1;
    if (p < 64) {
        const float* src = qup + (size_t)m*3072 + h*128 + 2*p;
        x0 = src[0]; x1 = src[1];
    } else {
        const int jp = p - 64;
        const float* src = qup + (size_t)m*3072 + 2048 + h*64 + 2*jp;
        const float c = cosT[s*32 + jp], sn = sinT[s*32 + jp];
        const float a = src[0], bb = src[1];
        x0 = a*c - bb*sn;
        x1 = a*sn + bb*c;
    }
    splitpack(x0, x1, Qh[idx], Ql[idx]);
}

// ================= assemble K packed: [bh][s][96p] =================
__global__ __launch_bounds__(256) void assemble_k_pk(const float* __restrict__ kvup,
        const float* __restrict__ kvcat,
        const float* __restrict__ cosT, const float* __restrict__ sinT,
        uint32_t* __restrict__ Kh, uint32_t* __restrict__ Kl) {
    const int idx = blockIdx.x * 256 + threadIdx.x;
    if (idx >= 32*2048*96) return;
    const int p  = idx % 96;
    const int ts = idx / 96;
    const int s  = ts & 2047;
    const int bh = ts >> 11;
    const int b = bh >> 4, h = bh & 15;
    const int m = b*2048 + s;
    float x0, x1;
    if (p < 64) {
        const float* src = kvup + (size_t)m*4096 + h*256 + 2*p;
        x0 = src[0]; x1 = src[1];
    } else {
        const int jp = p - 64;
        const float* src = kvcat + (size_t)m*576 + 512 + 2*jp;
        const float c = cosT[s*32 + jp], sn = sinT[s*32 + jp];
        const float a = src[0], bb = src[1];
        x0 = a*c - bb*sn;
        x1 = a*sn + bb*c;
    }
    splitpack(x0, x1, Kh[idx], Kl[idx]);
}

// ================= V transpose + split: [bh][dv=128][s-pairs=1024] =================
__global__ void split_v(const float* __restrict__ kvup,
                        uint32_t* __restrict__ Vh, uint32_t* __restrict__ Vl) {
    __shared__ float tile[64][33];
    const int bh = blockIdx.z, b = bh >> 4, h = bh & 15;
    const int s0 = blockIdx.x * 64, dv0 = blockIdx.y * 32;
    const int tx = threadIdx.x, ty = threadIdx.y;
    #pragma unroll
    for (int half = 0; half < 2; half++) {
        const int s = s0 + half*32 + ty;
        tile[half*32 + ty][tx] =
            kvup[((size_t)(b*2048 + s))*4096 + h*256 + 128 + dv0 + tx];
    }
    __syncthreads();
    const float x0 = tile[2*tx][ty], x1 = tile[2*tx + 1][ty];
    uint32_t hh, ll; splitpack(x0, x1, hh, ll);
    const size_t o = ((size_t)bh*128 + dv0 + ty)*1024 + (s0 >> 1) + tx;
    Vh[o] = hh; Vl[o] = ll;
}

// ================= flash attention (causal, packed bf16x3) =================
#define FQP 100
#define FVP 36
#define FPP 36
#define FL_BYTES ((4*64*FQP + 2*128*FVP + 2*64*FPP + 2*128) * 4)
__global__ __launch_bounds__(256) void flash_pk(
    const uint32_t* __restrict__ Qhg, const uint32_t* __restrict__ Qlg,
    const uint32_t* __restrict__ Khg, const uint32_t* __restrict__ Klg,
    const uint32_t* __restrict__ Vhg, const uint32_t* __restrict__ Vlg,
    uint32_t* __restrict__ Oh, uint32_t* __restrict__ Ol) {
    extern __shared__ uint32_t sw[];
    uint32_t* Qsh = sw;
    uint32_t* Qsl = Qsh + 64*FQP;
    uint32_t* Ksh = Qsl + 64*FQP;
    uint32_t* Ksl = Ksh + 64*FQP;
    uint32_t* Vsh = Ksl + 64*FQP;
    uint32_t* Vsl = Vsh + 128*FVP;
    uint32_t* Psh = Vsl + 128*FVP;
    uint32_t* Psl = Psh + 64*FPP;
    float* sMax = (float*)(Psl + 64*FPP);
    float* sSum = sMax + 128;

    const int qt = 31 - blockIdx.x;   // big tiles first
    const int bh = blockIdx.y;
    const int b = bh >> 4, h = bh & 15;
    const int tid = threadIdx.x;
    const int w = tid >> 5, lane = tid & 31;
    const int qg = w & 3, nhalf = w >> 2;
    const int g = lane >> 2, t = lane & 3;
    const int qrow = qg * 16;

    {   // load Q tile
        const size_t base = ((size_t)bh*2048 + qt*64) * 96;
        for (int i = tid; i < 64*24; i += 256) {
            const int r = i / 24, c = i % 24;
            *(uint4*)&Qsh[r*FQP + c*4] = *(const uint4*)(Qhg + base + (size_t)r*96 + c*4);
            *(uint4*)&Qsl[r*FQP + c*4] = *(const uint4*)(Qlg + base + (size_t)r*96 + c*4);
        }
    }

    float m0 = -INFINITY, m1 = -INFINITY, l0 = 0.f, l1 = 0.f;
    float o[8][4];
    #pragma unroll
    for (int nt = 0; nt < 8; nt++)
        #pragma unroll
        for (int e = 0; e < 4; e++) o[nt][e] = 0.f;

    const float scale = 0.07216878364870323f;   // 1/sqrt(192)

    for (int kt = 0; kt <= qt; kt++) {
        __syncthreads();
        {   // load K tile
            const size_t base = ((size_t)bh*2048 + kt*64) * 96;
            for (int i = tid; i < 64*24; i += 256) {
                const int r = i / 24, c = i % 24;
                *(uint4*)&Ksh[r*FQP + c*4] = *(const uint4*)(Khg + base + (size_t)r*96 + c*4);
                *(uint4*)&Ksl[r*FQP + c*4] = *(const uint4*)(Klg + base + (size_t)r*96 + c*4);
            }
            // load V tile (pre-transposed: [dv][s-pair])
            const size_t vb = (size_t)bh*128*1024 + kt*32;
            for (int i = tid; i < 128*8; i += 256) {
                const int r = i / 8, c = i % 8;
                *(uint4*)&Vsh[r*FVP + c*4] = *(const uint4*)(Vhg + vb + (size_t)r*1024 + c*4);
                *(uint4*)&Vsl[r*FVP + c*4] = *(const uint4*)(Vlg + vb + (size_t)r*1024 + c*4);
            }
        }
        __syncthreads();

        // ---- S = Q K^T : 12 k16 steps ----
        float sa[4][4];
        #pragma unroll
        for (int nt = 0; nt < 4; nt++)
            #pragma unroll
            for (int e = 0; e < 4; e++) sa[nt][e] = 0.f;

        #pragma unroll 4
        for (int st = 0; st < 12; st++) {
            const int p0 = st * 8;
            const int r0 = (qrow + g)*FQP + p0 + t, r1 = r0 + 8*FQP;
            uint32_t fah[4] = {Qsh[r0], Qsh[r1], Qsh[r0+4], Qsh[r1+4]};
            uint32_t fal[4] = {Qsl[r0], Qsl[r1], Qsl[r0+4], Qsl[r1+4]};
            #pragma unroll
            for (int nt = 0; nt < 4; nt++) {
                const int kr = (nhalf*32 + nt*8 + g)*FQP + p0 + t;
                uint32_t fbh[2] = {Ksh[kr], Ksh[kr+4]};
                uint32_t fbl[2] = {Ksl[kr], Ksl[kr+4]};
                mma16(sa[nt], fah, fbh);
                mma16(sa[nt], fah, fbl);
                mma16(sa[nt], fal, fbh);
            }
        }

        // ---- scale + causal mask + row max ----
        const bool diag = (kt == qt);
        float pm0 = -INFINITY, pm1 = -INFINITY;
        #pragma unroll
        for (int nt = 0; nt < 4; nt++) {
            const int colb = nhalf*32 + nt*8 + 2*t;
            #pragma unroll
            for (int e = 0; e < 4; e++) {
                float v = sa[nt][e] * scale;
                if (diag) {
                    const int col = colb + (e & 1);
                    const int row = qrow + g + ((e >> 1) << 3);
                    if (col > row) v = -INFINITY;
                }
                sa[nt][e] = v;
                if (e < 2) pm0 = fmaxf(pm0, v); else pm1 = fmaxf(pm1, v);
            }
        }
        pm0 = fmaxf(pm0, __shfl_xor_sync(0xffffffffu, pm0, 1));
        pm0 = fmaxf(pm0, __shfl_xor_sync(0xffffffffu, pm0, 2));
        pm1 = fmaxf(pm1, __shfl_xor_sync(0xffffffffu, pm1, 1));
        pm1 = fmaxf(pm1, __shfl_xor_sync(0xffffffffu, pm1, 2));
        if (t == 0) {
            sMax[nhalf*64 + qrow + g]     = pm0;
            sMax[nhalf*64 + qrow + g + 8] = pm1;
        }
        __syncthreads();
        const float mn0 = fmaxf(m0, fmaxf(pm0, sMax[(1 - nhalf)*64 + qrow + g]));
        const float mn1 = fmaxf(m1, fmaxf(pm1, sMax[(1 - nhalf)*64 + qrow + g + 8]));
        const float al0 = __expf(m0 - mn0);
        const float al1 = __expf(m1 - mn1);

        // ---- exp + packed P store + row sum ----
        float ps0 = 0.f, ps1 = 0.f;
        #pragma unroll
        for (int nt = 0; nt < 4; nt++) {
            const int pidx = nhalf*16 + nt*4 + t;
            const float p0v = __expf(sa[nt][0] - mn0);
            const float p1v = __expf(sa[nt][1] - mn0);
            const float p2v = __expf(sa[nt][2] - mn1);
            const float p3v = __expf(sa[nt][3] - mn1);
            ps0 += p0v + p1v; ps1 += p2v + p3v;
            splitpack(p0v, p1v, Psh[(qrow + g)*FPP + pidx],     Psl[(qrow + g)*FPP + pidx]);
            splitpack(p2v, p3v, Psh[(qrow + g + 8)*FPP + pidx], Psl[(qrow + g + 8)*FPP + pidx]);
        }
        ps0 += __shfl_xor_sync(0xffffffffu, ps0, 1);
        ps0 += __shfl_xor_sync(0xffffffffu, ps0, 2);
        ps1 += __shfl_xor_sync(0xffffffffu, ps1, 1);
        ps1 += __shfl_xor_sync(0xffffffffu, ps1, 2);
        if (t == 0) {
            sSum[nhalf*64 + qrow + g]     = ps0;
            sSum[nhalf*64 + qrow + g + 8] = ps1;
        }
        __syncthreads();
        l0 = l0 * al0 + ps0 + sSum[(1 - nhalf)*64 + qrow + g];
        l1 = l1 * al1 + ps1 + sSum[(1 - nhalf)*64 + qrow + g + 8];
        m0 = mn0; m1 = mn1;

        #pragma unroll
        for (int nt = 0; nt < 8; nt++) {
            o[nt][0] *= al0; o[nt][1] *= al0;
            o[nt][2] *= al1; o[nt][3] *= al1;
        }

        // ---- O += P V : 4 k16 steps ----
        #pragma unroll
        for (int st = 0; st < 4; st++) {
            const int p0 = st * 8;
            const int r0 = (qrow + g)*FPP + p0 + t, r1 = r0 + 8*FPP;
            uint32_t fah[4] = {Psh[r0], Psh[r1], Psh[r0+4], Psh[r1+4]};
            uint32_t fal[4] = {Psl[r0], Psl[r1], Psl[r0+4], Psl[r1+4]};
            #pragma unroll
            for (int nt = 0; nt < 8; nt++) {
                const int vr = (nhalf*64 + nt*8 + g)*FVP + p0 + t;
                uint32_t fbh[2] = {Vsh[vr], Vsh[vr+4]};
                uint32_t fbl[2] = {Vsl[vr], Vsl[vr+4]};
                mma16(o[nt], fah, fbh);
                mma16(o[nt], fah, fbl);
                mma16(o[nt], fal, fbh);
            }
        }
    }

    // ---- epilogue: normalize, split-pack attn ----
    const float il0 = 1.f / l0, il1 = 1.f / l1;
    const int row0 = b*2048 + qt*64 + qrow + g;
    #pragma unroll
    for (int nt = 0; nt < 8; nt++) {
        const int cp = h*64 + nhalf*32 + nt*4 + t;
        splitpack(o[nt][0]*il0, o[nt][1]*il0, Oh[(size_t)row0*1024 + cp],       Ol[(size_t)row0*1024 + cp]);
        splitpack(o[nt][2]*il1, o[nt][3]*il1, Oh[(size_t)(row0 + 8)*1024 + cp], Ol[(size_t)(row0 + 8)*1024 + cp]);
    }
}

// ================= host orchestration =================
static inline int cdiv(int a, int b) { return (a + b - 1) / b; }

extern "C" void kernel_launch(void* const* d_in, const int* in_sizes, int n_in,
                              void* d_out, int out_size) {
    const float* x        = (const float*)d_in[0];
    const float* wq_down  = (const float*)d_in[1];
    const float* q_norm_w = (const float*)d_in[2];
    const float* wq_up    = (const float*)d_in[3];
    const float* wq_rope  = (const float*)d_in[4];
    const float* wkv_down = (const float*)d_in[5];
    const float* kv_norm_w= (const float*)d_in[6];
    const float* wkv_up   = (const float*)d_in[7];
    const float* wk_rope  = (const float*)d_in[8];
    const float* wo       = (const float*)d_in[9];
    float* out = (float*)d_out;

    uint32_t *xs_h,*xs_l,*wqd_h,*wqd_l,*wkvc_h,*wkvc_l,*wqc_h,*wqc_l,*wkvu_h,*wkvu_l,*wo_h,*wo_l;
    uint32_t *qcs_h,*qcs_l,*kvcs_h,*kvcs_l,*Qh,*Ql,*Kh,*Kl,*Vh,*Vl,*at_h,*at_l;
    float *qc,*kvcat,*qup,*kvup,*ropeC,*ropeS;
    cudaGetSymbolAddress((void**)&xs_h,  g_xs_h);  cudaGetSymbolAddress((void**)&xs_l,  g_xs_l);
    cudaGetSymbolAddress((void**)&wqd_h, g_wqd_h); cudaGetSymbolAddress((void**)&wqd_l, g_wqd_l);
    cudaGetSymbolAddress((void**)&wkvc_h,g_wkvc_h);cudaGetSymbolAddress((void**)&wkvc_l,g_wkvc_l);
    cudaGetSymbolAddress((void**)&wqc_h, g_wqc_h); cudaGetSymbolAddress((void**)&wqc_l, g_wqc_l);
    cudaGetSymbolAddress((void**)&wkvu_h,g_wkvu_h);cudaGetSymbolAddress((void**)&wkvu_l,g_wkvu_l);
    cudaGetSymbolAddress((void**)&wo_h,  g_wo_h);  cudaGetSymbolAddress((void**)&wo_l,  g_wo_l);
    cudaGetSymbolAddress((void**)&qc,    g_qc);    cudaGetSymbolAddress((void**)&kvcat, g_kvcat);
    cudaGetSymbolAddress((void**)&qcs_h, g_qcs_h); cudaGetSymbolAddress((void**)&qcs_l, g_qcs_l);
    cudaGetSymbolAddress((void**)&kvcs_h,g_kvcs_h);cudaGetSymbolAddress((void**)&kvcs_l,g_kvcs_l);
    cudaGetSymbolAddress((void**)&qup,   g_qup);   cudaGetSymbolAddress((void**)&kvup,  g_kvup);
    cudaGetSymbolAddress((void**)&Qh,    g_Qh);    cudaGetSymbolAddress((void**)&Ql,    g_Ql);
    cudaGetSymbolAddress((void**)&Kh,    g_Kh);    cudaGetSymbolAddress((void**)&Kl,    g_Kl);
    cudaGetSymbolAddress((void**)&Vh,    g_Vh);    cudaGetSymbolAddress((void**)&Vl,    g_Vl);
    cudaGetSymbolAddress((void**)&at_h,  g_at_h);  cudaGetSymbolAddress((void**)&at_l,  g_at_l);
    cudaGetSymbolAddress((void**)&ropeC, g_ropeC); cudaGetSymbolAddress((void**)&ropeS, g_ropeS);

    // ---- split inputs into packed bf16 hi/lo ----
    auto sp = [](const float* s, uint32_t* h, uint32_t* l, int np) {
        split_pairs<<<cdiv(np, 256), 256>>>(s, h, l, np);
    };
    sp(x,        xs_h,   xs_l,   4096*1024);
    sp(wq_down,  wqd_h,  wqd_l,  1536*1024);
    sp(wkv_down, wkvc_h, wkvc_l, 512*1024);
    sp(wk_rope,  wkvc_h + 512*1024, wkvc_l + 512*1024, 64*1024);
    sp(wq_up,    wqc_h,  wqc_l,  2048*768);
    sp(wq_rope,  wqc_h + 2048*768, wqc_l + 2048*768, 1024*768);
    sp(wkv_up,   wkvu_h, wkvu_l, 4096*256);
    sp(wo,       wo_h,   wo_l,   2048*1024);
    rope_table<<<cdiv(2048*32, 256), 256>>>(ropeC, ropeS);

    // ---- down projections ----
    gemm_pk<<<dim3(12, 32), 256>>>(xs_h, xs_l, wqd_h,  wqd_l,  qc,    4096, 1536, 1024);
    gemm_pk<<<dim3(5,  32), 256>>>(xs_h, xs_l, wkvc_h, wkvc_l, kvcat, 4096, 576,  1024);

    rmsnorm_split<<<4096, 256>>>(qc,    1536, q_norm_w,  1536, qcs_h,  qcs_l);
    rmsnorm_split<<<4096, 256>>>(kvcat, 576,  kv_norm_w, 512,  kvcs_h, kvcs_l);

    // ---- up projections ----
    gemm_pk<<<dim3(24, 32), 256>>>(qcs_h,  qcs_l,  wqc_h,  wqc_l,  qup,  4096, 3072, 768);
    gemm_pk<<<dim3(32, 32), 256>>>(kvcs_h, kvcs_l, wkvu_h, wkvu_l, kvup, 4096, 4096, 256);

    // ---- assemble packed Q/K/V ----
    assemble_q_pk<<<cdiv(32*2048*96, 256), 256>>>(qup, ropeC, ropeS, Qh, Ql);
    assemble_k_pk<<<cdiv(32*2048*96, 256), 256>>>(kvup, kvcat, ropeC, ropeS, Kh, Kl);
    split_v<<<dim3(32, 4, 32), dim3(32, 32)>>>(kvup, Vh, Vl);

    // ---- flash attention ----
    cudaFuncSetAttribute(flash_pk, cudaFuncAttributeMaxDynamicSharedMemorySize, FL_BYTES);
    flash_pk<<<dim3(32, 32), 256, FL_BYTES>>>(Qh, Ql, Kh, Kl, Vh, Vl, at_h, at_l);

    // ---- output projection ----
    gemm_pk<<<dim3(16, 32), 256>>>(at_h, at_l, wo_h, wo_l, out, 4096, 2048, 1024);
}

// round 6
// speedup vs baseline: 2.2013x; 1.1442x over previous
#include <cuda_runtime.h>
#include <math.h>
#include <stdint.h>

// ================= static scratch (no allocations allowed) =================
__device__ uint32_t g_xs_h [4096u*1024], g_xs_l [4096u*1024];   // x split [4096][1024p]
__device__ uint32_t g_wqd_h[1536u*1024], g_wqd_l[1536u*1024];   // wq_down
__device__ uint32_t g_wkvc_h[576u*1024], g_wkvc_l[576u*1024];   // wkv_down(512) | wk_rope(64)
__device__ uint32_t g_wqc_h[3072u*768],  g_wqc_l[3072u*768];    // wq_up(2048) | wq_rope(1024)
__device__ uint32_t g_wkvu_h[4096u*256], g_wkvu_l[4096u*256];   // wkv_up
__device__ uint32_t g_wo_h [2048u*1024], g_wo_l [2048u*1024];   // wo
__device__ float    g_qc   [4096u*1536];                        // pre-norm q_c
__device__ float    g_kvcat[4096u*576];                         // kv_c(512) | krope(64)
__device__ uint32_t g_qcs_h[4096u*768],  g_qcs_l[4096u*768];    // normed q_c split
__device__ uint32_t g_kvcs_h[4096u*256], g_kvcs_l[4096u*256];   // normed kv_c split
__device__ float    g_qup  [4096ull*3072];                      // qnope(2048) | qpe(1024)
__device__ float    g_kvup [4096ull*4096];                      // per head: k_nope(128)|v(128)
__device__ uint32_t g_Qh[32ull*2048*96], g_Ql[32ull*2048*96];   // Q packed [bh][s][96p]
__device__ uint32_t g_Kh[32ull*2048*96], g_Kl[32ull*2048*96];   // K packed
__device__ uint32_t g_Vh[32ull*128*1024], g_Vl[32ull*128*1024]; // V^T packed [bh][dv][1024 s-pairs]
__device__ uint32_t g_at_h[4096u*1024], g_at_l[4096u*1024];     // attn out packed [4096][1024p]
__device__ float    g_ropeC[2048*32], g_ropeS[2048*32];

// ================= helpers =================
__device__ __forceinline__ void splitpack(float x0, float x1, uint32_t& h, uint32_t& l) {
    uint32_t hb;
    asm("cvt.rn.bf16x2.f32 %0, %1, %2;" : "=r"(hb) : "f"(x1), "f"(x0));
    const float h0 = __uint_as_float(hb << 16);
    const float h1 = __uint_as_float(hb & 0xffff0000u);
    uint32_t lb;
    asm("cvt.rn.bf16x2.f32 %0, %1, %2;" : "=r"(lb) : "f"(x1 - h1), "f"(x0 - h0));
    h = hb; l = lb;
}

__device__ __forceinline__ void mma16(float* d, const uint32_t* a, const uint32_t* b) {
    asm volatile("mma.sync.aligned.m16n8k16.row.col.f32.bf16.bf16.f32 "
        "{%0,%1,%2,%3}, {%4,%5,%6,%7}, {%8,%9}, {%0,%1,%2,%3};"
        : "+f"(d[0]), "+f"(d[1]), "+f"(d[2]), "+f"(d[3])
        : "r"(a[0]), "r"(a[1]), "r"(a[2]), "r"(a[3]), "r"(b[0]), "r"(b[1]));
}

__device__ __forceinline__ uint32_t smem_u32(const void* p) {
    uint32_t a;
    asm("{ .reg .u64 t; cvta.to.shared.u64 t, %1; cvt.u32.u64 %0, t; }" : "=r"(a) : "l"(p));
    return a;
}
__device__ __forceinline__ void ldsm4(uint32_t* r, uint32_t addr) {
    asm volatile("ldmatrix.sync.aligned.m8n8.x4.shared.b16 {%0,%1,%2,%3}, [%4];"
        : "=r"(r[0]), "=r"(r[1]), "=r"(r[2]), "=r"(r[3]) : "r"(addr));
}
__device__ __forceinline__ void ldsm2(uint32_t* r, uint32_t addr) {
    asm volatile("ldmatrix.sync.aligned.m8n8.x2.shared.b16 {%0,%1}, [%2];"
        : "=r"(r[0]), "=r"(r[1]) : "r"(addr));
}

// ================= split fp32 -> packed bf16 hi/lo =================
__global__ __launch_bounds__(256) void split_pairs(const float* __restrict__ src,
                                                   uint32_t* __restrict__ h,
                                                   uint32_t* __restrict__ l, int npairs) {
    const int i = blockIdx.x * 256 + threadIdx.x;
    if (i >= npairs) return;
    const float2 v = ((const float2*)src)[i];
    splitpack(v.x, v.y, h[i], l[i]);
}

// ================= packed bf16x3 GEMM: C[M,N] = A[M,K] @ B[N,K]^T =================
// BM=BN=128, BK=16 pairs, 256 thr (8 warps 2x4), warp tile 64x32, ldmatrix frags.
#define GP 20   // smem pair stride (conflict-free for ldmatrix phases: 20 ≡ 4 mod 32)
__global__ __launch_bounds__(256) void gemm_pk(
    const uint32_t* __restrict__ Ahg, const uint32_t* __restrict__ Alg,
    const uint32_t* __restrict__ Bhg, const uint32_t* __restrict__ Blg,
    float* __restrict__ C, int M, int N, int Kp) {
    __shared__ uint32_t Ash[128*GP], Asl[128*GP], Bsh[128*GP], Bsl[128*GP];
    const int tid = threadIdx.x, bx = blockIdx.x, by = blockIdx.y;
    const int w = tid >> 5, lane = tid & 31;
    const int wm = (w >> 2) * 64, wn = (w & 3) * 32;
    const int lrow = tid >> 1;
    const int lp   = (tid & 1) * 8;

    // ldmatrix lane address components
    const int rowA = lane & 15, kselA = (lane >> 4) << 2;        // x4: rows 0-15, col halves
    const int rowB = lane & 7,  kselB = ((lane >> 3) & 1) << 2;  // x2: rows 0-7, col halves
    const uint32_t aAsh = smem_u32(Ash), aAsl = smem_u32(Asl);
    const uint32_t aBsh = smem_u32(Bsh), aBsl = smem_u32(Bsl);

    const uint32_t* Aph = Ahg + (size_t)(by*128 + lrow) * Kp + lp;
    const uint32_t* Apl = Alg + (size_t)(by*128 + lrow) * Kp + lp;
    const int brow = bx*128 + lrow;
    const uint32_t* Bph = Bhg + (size_t)brow * Kp + lp;
    const uint32_t* Bpl = Blg + (size_t)brow * Kp + lp;
    const bool bok = brow < N;

    float acc[4][4][4];
    #pragma unroll
    for (int mt = 0; mt < 4; mt++)
        #pragma unroll
        for (int nt = 0; nt < 4; nt++)
            #pragma unroll
            for (int i = 0; i < 4; i++) acc[mt][nt][i] = 0.f;

    const uint4 z4 = make_uint4(0,0,0,0);
    uint4 ah0 = *(const uint4*)(Aph),     ah1 = *(const uint4*)(Aph + 4);
    uint4 al0 = *(const uint4*)(Apl),     al1 = *(const uint4*)(Apl + 4);
    uint4 bh0 = bok ? *(const uint4*)(Bph)     : z4;
    uint4 bh1 = bok ? *(const uint4*)(Bph + 4) : z4;
    uint4 bl0 = bok ? *(const uint4*)(Bpl)     : z4;
    uint4 bl1 = bok ? *(const uint4*)(Bpl + 4) : z4;

    for (int kp = 0;;) {
        *(uint4*)&Ash[lrow*GP + lp]     = ah0; *(uint4*)&Ash[lrow*GP + lp + 4] = ah1;
        *(uint4*)&Asl[lrow*GP + lp]     = al0; *(uint4*)&Asl[lrow*GP + lp + 4] = al1;
        *(uint4*)&Bsh[lrow*GP + lp]     = bh0; *(uint4*)&Bsh[lrow*GP + lp + 4] = bh1;
        *(uint4*)&Bsl[lrow*GP + lp]     = bl0; *(uint4*)&Bsl[lrow*GP + lp + 4] = bl1;
        __syncthreads();
        const bool more = (kp + 16) < Kp;
        if (more) {
            ah0 = *(const uint4*)(Aph + kp + 16); ah1 = *(const uint4*)(Aph + kp + 20);
            al0 = *(const uint4*)(Apl + kp + 16); al1 = *(const uint4*)(Apl + kp + 20);
            bh0 = bok ? *(const uint4*)(Bph + kp + 16) : z4;
            bh1 = bok ? *(const uint4*)(Bph + kp + 20) : z4;
            bl0 = bok ? *(const uint4*)(Bpl + kp + 16) : z4;
            bl1 = bok ? *(const uint4*)(Bpl + kp + 20) : z4;
        }
        #pragma unroll
        for (int stp = 0; stp < 2; stp++) {
            const int p0 = stp * 8;
            uint32_t fbh[4][2], fbl[4][2];
            #pragma unroll
            for (int nt = 0; nt < 4; nt++) {
                const uint32_t ob = (uint32_t)((wn + nt*8 + rowB)*GP + p0 + kselB) * 4u;
                ldsm2(fbh[nt], aBsh + ob);
                ldsm2(fbl[nt], aBsl + ob);
            }
            #pragma unroll
            for (int mt = 0; mt < 4; mt++) {
                const uint32_t oa = (uint32_t)((wm + mt*16 + rowA)*GP + p0 + kselA) * 4u;
                uint32_t fah[4], fal[4];
                ldsm4(fah, aAsh + oa);
                ldsm4(fal, aAsl + oa);
                #pragma unroll
                for (int nt = 0; nt < 4; nt++) {
                    mma16(acc[mt][nt], fah, fbh[nt]);
                    mma16(acc[mt][nt], fah, fbl[nt]);
                    mma16(acc[mt][nt], fal, fbh[nt]);
                }
            }
        }
        kp += 16;
        if (!more) break;
        __syncthreads();
    }

    const int g = lane >> 2, t = lane & 3;
    #pragma unroll
    for (int mt = 0; mt < 4; mt++) {
        const int row = by*128 + wm + mt*16 + g;
        #pragma unroll
        for (int nt = 0; nt < 4; nt++) {
            const int col = bx*128 + wn + nt*8 + 2*t;
            if (col < N) {
                float* cp = C + (size_t)row * N + col;
                *(float2*)cp                   = make_float2(acc[mt][nt][0], acc[mt][nt][1]);
                *(float2*)(cp + 8 * (size_t)N) = make_float2(acc[mt][nt][2], acc[mt][nt][3]);
            }
        }
    }
}

// ================= RMSNorm + split =================
__global__ __launch_bounds__(256) void rmsnorm_split(const float* __restrict__ x, int stride,
                                                     const float* __restrict__ w, int cols,
                                                     uint32_t* __restrict__ oh,
                                                     uint32_t* __restrict__ ol) {
    const int row = blockIdx.x;
    const float* xr = x + (size_t)row * stride;
    const int tid = threadIdx.x;
    float s = 0.f;
    for (int c = tid; c < cols; c += 256) { float v = xr[c]; s = fmaf(v, v, s); }
    __shared__ float red[256];
    red[tid] = s; __syncthreads();
    for (int st = 128; st > 0; st >>= 1) {
        if (tid < st) red[tid] += red[tid + st];
        __syncthreads();
    }
    const float inv = rsqrtf(red[0] / (float)cols + 1e-6f);
    const int pairs = cols >> 1;
    for (int p = tid; p < pairs; p += 256) {
        const float x0 = xr[2*p]     * inv * w[2*p];
        const float x1 = xr[2*p + 1] * inv * w[2*p + 1];
        splitpack(x0, x1, oh[(size_t)row * pairs + p], ol[(size_t)row * pairs + p]);
    }
}

// ================= RoPE table =================
__global__ void rope_table(float* __restrict__ cosT, float* __restrict__ sinT) {
    const int idx = blockIdx.x * 256 + threadIdx.x;
    if (idx >= 2048 * 32) return;
    const int s = idx >> 5, jp = idx & 31;
    const float inv = powf(10000.0f, -(float)(2*jp) * (1.0f/64.0f));
    float sn, cs; sincosf((float)s * inv, &sn, &cs);
    cosT[idx] = cs; sinT[idx] = sn;
}

// ================= assemble Q packed =================
__global__ __launch_bounds__(256) void assemble_q_pk(const float* __restrict__ qup,
        const float* __restrict__ cosT, const float* __restrict__ sinT,
        uint32_t* __restrict__ Qh, uint32_t* __restrict__ Ql) {
    const int idx = blockIdx.x * 256 + threadIdx.x;
    if (idx >= 32*2048*96) return;
    const int p  = idx % 96;
    const int ts = idx / 96;
    const int s  = ts & 2047;
    const int bh = ts >> 11;
    const int b = bh >> 4, h = bh & 15;
    const int m = b*2048 + s;
    float x0, x1;
    if (p < 64) {
        const float* src = qup + (size_t)m*3072 + h*128 + 2*p;
        x0 = src[0]; x1 = src[1];
    } else {
        const int jp = p - 64;
        const float* src = qup + (size_t)m*3072 + 2048 + h*64 + 2*jp;
        const float c = cosT[s*32 + jp], sn = sinT[s*32 + jp];
        const float a = src[0], bb = src[1];
        x0 = a*c - bb*sn;
        x1 = a*sn + bb*c;
    }
    splitpack(x0, x1, Qh[idx], Ql[idx]);
}

// ================= assemble K packed =================
__global__ __launch_bounds__(256) void assemble_k_pk(const float* __restrict__ kvup,
        const float* __restrict__ kvcat,
        const float* __restrict__ cosT, const float* __restrict__ sinT,
        uint32_t* __restrict__ Kh, uint32_t* __restrict__ Kl) {
    const int idx = blockIdx.x * 256 + threadIdx.x;
    if (idx >= 32*2048*96) return;
    const int p  = idx % 96;
    const int ts = idx / 96;
    const int s  = ts & 2047;
    const int bh = ts >> 11;
    const int b = bh >> 4, h = bh & 15;
    const int m = b*2048 + s;
    float x0, x1;
    if (p < 64) {
        const float* src = kvup + (size_t)m*4096 + h*256 + 2*p;
        x0 = src[0]; x1 = src[1];
    } else {
        const int jp = p - 64;
        const float* src = kvcat + (size_t)m*576 + 512 + 2*jp;
        const float c = cosT[s*32 + jp], sn = sinT[s*32 + jp];
        const float a = src[0], bb = src[1];
        x0 = a*c - bb*sn;
        x1 = a*sn + bb*c;
    }
    splitpack(x0, x1, Kh[idx], Kl[idx]);
}

// ================= V transpose + split =================
__global__ void split_v(const float* __restrict__ kvup,
                        uint32_t* __restrict__ Vh, uint32_t* __restrict__ Vl) {
    __shared__ float tile[64][33];
    const int bh = blockIdx.z, b = bh >> 4, h = bh & 15;
    const int s0 = blockIdx.x * 64, dv0 = blockIdx.y * 32;
    const int tx = threadIdx.x, ty = threadIdx.y;
    #pragma unroll
    for (int half = 0; half < 2; half++) {
        const int s = s0 + half*32 + ty;
        tile[half*32 + ty][tx] =
            kvup[((size_t)(b*2048 + s))*4096 + h*256 + 128 + dv0 + tx];
    }
    __syncthreads();
    const float x0 = tile[2*tx][ty], x1 = tile[2*tx + 1][ty];
    uint32_t hh, ll; splitpack(x0, x1, hh, ll);
    const size_t o = ((size_t)bh*128 + dv0 + ty)*1024 + (s0 >> 1) + tx;
    Vh[o] = hh; Vl[o] = ll;
}

// ================= flash attention (causal, packed bf16x3, ldmatrix frags) =================
#define FQP 100
#define FVP 36
#define FPP 36
#define FL_BYTES ((4*64*FQP + 2*128*FVP + 2*64*FPP + 2*128) * 4)
__global__ __launch_bounds__(256) void flash_pk(
    const uint32_t* __restrict__ Qhg, const uint32_t* __restrict__ Qlg,
    const uint32_t* __restrict__ Khg, const uint32_t* __restrict__ Klg,
    const uint32_t* __restrict__ Vhg, const uint32_t* __restrict__ Vlg,
    uint32_t* __restrict__ Oh, uint32_t* __restrict__ Ol) {
    extern __shared__ uint32_t sw[];
    uint32_t* Qsh = sw;
    uint32_t* Qsl = Qsh + 64*FQP;
    uint32_t* Ksh = Qsl + 64*FQP;
    uint32_t* Ksl = Ksh + 64*FQP;
    uint32_t* Vsh = Ksl + 64*FQP;
    uint32_t* Vsl = Vsh + 128*FVP;
    uint32_t* Psh = Vsl + 128*FVP;
    uint32_t* Psl = Psh + 64*FPP;
    float* sMax = (float*)(Psl + 64*FPP);
    float* sSum = sMax + 128;

    const int qt = 31 - blockIdx.x;
    const int bh = blockIdx.y;
    const int b = bh >> 4, h = bh & 15;
    const int tid = threadIdx.x;
    const int w = tid >> 5, lane = tid & 31;
    const int qg = w & 3, nhalf = w >> 2;
    const int g = lane >> 2, t = lane & 3;
    const int qrow = qg * 16;

    // ldmatrix lane address components
    const int rowA = lane & 15, kselA = (lane >> 4) << 2;
    const int rowB = lane & 7,  kselB = ((lane >> 3) & 1) << 2;
    const uint32_t aQh = smem_u32(Qsh), aQl = smem_u32(Qsl);
    const uint32_t aKh = smem_u32(Ksh), aKl = smem_u32(Ksl);
    const uint32_t aVh = smem_u32(Vsh), aVl = smem_u32(Vsl);
    const uint32_t aPh = smem_u32(Psh), aPl = smem_u32(Psl);

    {
        const size_t base = ((size_t)bh*2048 + qt*64) * 96;
        for (int i = tid; i < 64*24; i += 256) {
            const int r = i / 24, c = i % 24;
            *(uint4*)&Qsh[r*FQP + c*4] = *(const uint4*)(Qhg + base + (size_t)r*96 + c*4);
            *(uint4*)&Qsl[r*FQP + c*4] = *(const uint4*)(Qlg + base + (size_t)r*96 + c*4);
        }
    }

    float m0 = -INFINITY, m1 = -INFINITY, l0 = 0.f, l1 = 0.f;
    float o[8][4];
    #pragma unroll
    for (int nt = 0; nt < 8; nt++)
        #pragma unroll
        for (int e = 0; e < 4; e++) o[nt][e] = 0.f;

    const float scale = 0.07216878364870323f;   // 1/sqrt(192)

    for (int kt = 0; kt <= qt; kt++) {
        __syncthreads();
        {
            const size_t base = ((size_t)bh*2048 + kt*64) * 96;
            for (int i = tid; i < 64*24; i += 256) {
                const int r = i / 24, c = i % 24;
                *(uint4*)&Ksh[r*FQP + c*4] = *(const uint4*)(Khg + base + (size_t)r*96 + c*4);
                *(uint4*)&Ksl[r*FQP + c*4] = *(const uint4*)(Klg + base + (size_t)r*96 + c*4);
            }
            const size_t vb = (size_t)bh*128*1024 + kt*32;
            for (int i = tid; i < 128*8; i += 256) {
                const int r = i / 8, c = i % 8;
                *(uint4*)&Vsh[r*FVP + c*4] = *(const uint4*)(Vhg + vb + (size_t)r*1024 + c*4);
                *(uint4*)&Vsl[r*FVP + c*4] = *(const uint4*)(Vlg + vb + (size_t)r*1024 + c*4);
            }
        }
        __syncthreads();

        // ---- S = Q K^T : 12 k16 steps, ldmatrix frags ----
        float sa[4][4];
        #pragma unroll
        for (int nt = 0; nt < 4; nt++)
            #pragma unroll
            for (int e = 0; e < 4; e++) sa[nt][e] = 0.f;

        #pragma unroll 4
        for (int st = 0; st < 12; st++) {
            const int p0 = st * 8;
            const uint32_t oq = (uint32_t)((qrow + rowA)*FQP + p0 + kselA) * 4u;
            uint32_t fah[4], fal[4];
            ldsm4(fah, aQh + oq);
            ldsm4(fal, aQl + oq);
            #pragma unroll
            for (int nt = 0; nt < 4; nt++) {
                const uint32_t ok = (uint32_t)((nhalf*32 + nt*8 + rowB)*FQP + p0 + kselB) * 4u;
                uint32_t fbh[2], fbl[2];
                ldsm2(fbh, aKh + ok);
                ldsm2(fbl, aKl + ok);
                mma16(sa[nt], fah, fbh);
                mma16(sa[nt], fah, fbl);
                mma16(sa[nt], fal, fbh);
            }
        }

        const bool diag = (kt == qt);
        float pm0 = -INFINITY, pm1 = -INFINITY;
        #pragma unroll
        for (int nt = 0; nt < 4; nt++) {
            const int colb = nhalf*32 + nt*8 + 2*t;
            #pragma unroll
            for (int e = 0; e < 4; e++) {
                float v = sa[nt][e] * scale;
                if (diag) {
                    const int col = colb + (e & 1);
                    const int row = qrow + g + ((e >> 1) << 3);
                    if (col > row) v = -INFINITY;
                }
                sa[nt][e] = v;
                if (e < 2) pm0 = fmaxf(pm0, v); else pm1 = fmaxf(pm1, v);
            }
        }
        pm0 = fmaxf(pm0, __shfl_xor_sync(0xffffffffu, pm0, 1));
        pm0 = fmaxf(pm0, __shfl_xor_sync(0xffffffffu, pm0, 2));
        pm1 = fmaxf(pm1, __shfl_xor_sync(0xffffffffu, pm1, 1));
        pm1 = fmaxf(pm1, __shfl_xor_sync(0xffffffffu, pm1, 2));
        if (t == 0) {
            sMax[nhalf*64 + qrow + g]     = pm0;
            sMax[nhalf*64 + qrow + g + 8] = pm1;
        }
        __syncthreads();
        const float mn0 = fmaxf(m0, fmaxf(pm0, sMax[(1 - nhalf)*64 + qrow + g]));
        const float mn1 = fmaxf(m1, fmaxf(pm1, sMax[(1 - nhalf)*64 + qrow + g + 8]));
        const float al0 = __expf(m0 - mn0);
        const float al1 = __expf(m1 - mn1);

        float ps0 = 0.f, ps1 = 0.f;
        #pragma unroll
        for (int nt = 0; nt < 4; nt++) {
            const int pidx = nhalf*16 + nt*4 + t;
            const float p0v = __expf(sa[nt][0] - mn0);
            const float p1v = __expf(sa[nt][1] - mn0);
            const float p2v = __expf(sa[nt][2] - mn1);
            const float p3v = __expf(sa[nt][3] - mn1);
            ps0 += p0v + p1v; ps1 += p2v + p3v;
            splitpack(p0v, p1v, Psh[(qrow + g)*FPP + pidx],     Psl[(qrow + g)*FPP + pidx]);
            splitpack(p2v, p3v, Psh[(qrow + g + 8)*FPP + pidx], Psl[(qrow + g + 8)*FPP + pidx]);
        }
        ps0 += __shfl_xor_sync(0xffffffffu, ps0, 1);
        ps0 += __shfl_xor_sync(0xffffffffu, ps0, 2);
        ps1 += __shfl_xor_sync(0xffffffffu, ps1, 1);
        ps1 += __shfl_xor_sync(0xffffffffu, ps1, 2);
        if (t == 0) {
            sSum[nhalf*64 + qrow + g]     = ps0;
            sSum[nhalf*64 + qrow + g + 8] = ps1;
        }
        __syncthreads();
        l0 = l0 * al0 + ps0 + sSum[(1 - nhalf)*64 + qrow + g];
        l1 = l1 * al1 + ps1 + sSum[(1 - nhalf)*64 + qrow + g + 8];
        m0 = mn0; m1 = mn1;

        #pragma unroll
        for (int nt = 0; nt < 8; nt++) {
            o[nt][0] *= al0; o[nt][1] *= al0;
            o[nt][2] *= al1; o[nt][3] *= al1;
        }

        // ---- O += P V : 4 k16 steps, ldmatrix frags ----
        #pragma unroll
        for (int st = 0; st < 4; st++) {
            const int p0 = st * 8;
            const uint32_t op = (uint32_t)((qrow + rowA)*FPP + p0 + kselA) * 4u;
            uint32_t fah[4], fal[4];
            ldsm4(fah, aPh + op);
            ldsm4(fal, aPl + op);
            #pragma unroll
            for (int nt = 0; nt < 8; nt++) {
                const uint32_t ov = (uint32_t)((nhalf*64 + nt*8 + rowB)*FVP + p0 + kselB) * 4u;
                uint32_t fbh[2], fbl[2];
                ldsm2(fbh, aVh + ov);
                ldsm2(fbl, aVl + ov);
                mma16(o[nt], fah, fbh);
                mma16(o[nt], fah, fbl);
                mma16(o[nt], fal, fbh);
            }
        }
    }

    const float il0 = 1.f / l0, il1 = 1.f / l1;
    const int row0 = b*2048 + qt*64 + qrow + g;
    #pragma unroll
    for (int nt = 0; nt < 8; nt++) {
        const int cp = h*64 + nhalf*32 + nt*4 + t;
        splitpack(o[nt][0]*il0, o[nt][1]*il0, Oh[(size_t)row0*1024 + cp],       Ol[(size_t)row0*1024 + cp]);
        splitpack(o[nt][2]*il1, o[nt][3]*il1, Oh[(size_t)(row0 + 8)*1024 + cp], Ol[(size_t)(row0 + 8)*1024 + cp]);
    }
}

// ================= host orchestration =================
static inline int cdiv(int a, int b) { return (a + b - 1) / b; }

extern "C" void kernel_launch(void* const* d_in, const int* in_sizes, int n_in,
                              void* d_out, int out_size) {
    const float* x        = (const float*)d_in[0];
    const float* wq_down  = (const float*)d_in[1];
    const float* q_norm_w = (const float*)d_in[2];
    const float* wq_up    = (const float*)d_in[3];
    const float* wq_rope  = (const float*)d_in[4];
    const float* wkv_down = (const float*)d_in[5];
    const float* kv_norm_w= (const float*)d_in[6];
    const float* wkv_up   = (const float*)d_in[7];
    const float* wk_rope  = (const float*)d_in[8];
    const float* wo       = (const float*)d_in[9];
    float* out = (float*)d_out;

    uint32_t *xs_h,*xs_l,*wqd_h,*wqd_l,*wkvc_h,*wkvc_l,*wqc_h,*wqc_l,*wkvu_h,*wkvu_l,*wo_h,*wo_l;
    uint32_t *qcs_h,*qcs_l,*kvcs_h,*kvcs_l,*Qh,*Ql,*Kh,*Kl,*Vh,*Vl,*at_h,*at_l;
    float *qc,*kvcat,*qup,*kvup,*ropeC,*ropeS;
    cudaGetSymbolAddress((void**)&xs_h,  g_xs_h);  cudaGetSymbolAddress((void**)&xs_l,  g_xs_l);
    cudaGetSymbolAddress((void**)&wqd_h, g_wqd_h); cudaGetSymbolAddress((void**)&wqd_l, g_wqd_l);
    cudaGetSymbolAddress((void**)&wkvc_h,g_wkvc_h);cudaGetSymbolAddress((void**)&wkvc_l,g_wkvc_l);
    cudaGetSymbolAddress((void**)&wqc_h, g_wqc_h); cudaGetSymbolAddress((void**)&wqc_l, g_wqc_l);
    cudaGetSymbolAddress((void**)&wkvu_h,g_wkvu_h);cudaGetSymbolAddress((void**)&wkvu_l,g_wkvu_l);
    cudaGetSymbolAddress((void**)&wo_h,  g_wo_h);  cudaGetSymbolAddress((void**)&wo_l,  g_wo_l);
    cudaGetSymbolAddress((void**)&qc,    g_qc);    cudaGetSymbolAddress((void**)&kvcat, g_kvcat);
    cudaGetSymbolAddress((void**)&qcs_h, g_qcs_h); cudaGetSymbolAddress((void**)&qcs_l, g_qcs_l);
    cudaGetSymbolAddress((void**)&kvcs_h,g_kvcs_h);cudaGetSymbolAddress((void**)&kvcs_l,g_kvcs_l);
    cudaGetSymbolAddress((void**)&qup,   g_qup);   cudaGetSymbolAddress((void**)&kvup,  g_kvup);
    cudaGetSymbolAddress((void**)&Qh,    g_Qh);    cudaGetSymbolAddress((void**)&Ql,    g_Ql);
    cudaGetSymbolAddress((void**)&Kh,    g_Kh);    cudaGetSymbolAddress((void**)&Kl,    g_Kl);
    cudaGetSymbolAddress((void**)&Vh,    g_Vh);    cudaGetSymbolAddress((void**)&Vl,    g_Vl);
    cudaGetSymbolAddress((void**)&at_h,  g_at_h);  cudaGetSymbolAddress((void**)&at_l,  g_at_l);
    cudaGetSymbolAddress((void**)&ropeC, g_ropeC); cudaGetSymbolAddress((void**)&ropeS, g_ropeS);

    cudaFuncSetAttribute(flash_pk, cudaFuncAttributeMaxDynamicSharedMemorySize, FL_BYTES);

    // ---- split inputs into packed bf16 hi/lo ----
    auto sp = [](const float* s, uint32_t* h, uint32_t* l, int np) {
        split_pairs<<<cdiv(np, 256), 256>>>(s, h, l, np);
    };
    sp(x,        xs_h,   xs_l,   4096*1024);
    sp(wq_down,  wqd_h,  wqd_l,  1536*1024);
    sp(wkv_down, wkvc_h, wkvc_l, 512*1024);
    sp(wk_rope,  wkvc_h + 512*1024, wkvc_l + 512*1024, 64*1024);
    sp(wq_up,    wqc_h,  wqc_l,  2048*768);
    sp(wq_rope,  wqc_h + 2048*768, wqc_l + 2048*768, 1024*768);
    sp(wkv_up,   wkvu_h, wkvu_l, 4096*256);
    sp(wo,       wo_h,   wo_l,   2048*1024);
    rope_table<<<cdiv(2048*32, 256), 256>>>(ropeC, ropeS);

    // ---- down projections ----
    gemm_pk<<<dim3(12, 32), 256>>>(xs_h, xs_l, wqd_h,  wqd_l,  qc,    4096, 1536, 1024);
    gemm_pk<<<dim3(5,  32), 256>>>(xs_h, xs_l, wkvc_h, wkvc_l, kvcat, 4096, 576,  1024);

    rmsnorm_split<<<4096, 256>>>(qc,    1536, q_norm_w,  1536, qcs_h,  qcs_l);
    rmsnorm_split<<<4096, 256>>>(kvcat, 576,  kv_norm_w, 512,  kvcs_h, kvcs_l);

    // ---- up projections ----
    gemm_pk<<<dim3(24, 32), 256>>>(qcs_h,  qcs_l,  wqc_h,  wqc_l,  qup,  4096, 3072, 768);
    gemm_pk<<<dim3(32, 32), 256>>>(kvcs_h, kvcs_l, wkvu_h, wkvu_l, kvup, 4096, 4096, 256);

    // ---- assemble packed Q/K/V ----
    assemble_q_pk<<<cdiv(32*2048*96, 256), 256>>>(qup, ropeC, ropeS, Qh, Ql);
    assemble_k_pk<<<cdiv(32*2048*96, 256), 256>>>(kvup, kvcat, ropeC, ropeS, Kh, Kl);
    split_v<<<dim3(32, 4, 32), dim3(32, 32)>>>(kvup, Vh, Vl);

    // ---- flash attention ----
    flash_pk<<<dim3(32, 32), 256, FL_BYTES>>>(Qh, Ql, Kh, Kl, Vh, Vl, at_h, at_l);

    // ---- output projection ----
    gemm_pk<<<dim3(16, 32), 256>>>(at_h, at_l, wo_h, wo_l, out, 4096, 2048, 1024);
}

// round 7
// speedup vs baseline: 2.2484x; 1.0214x over previous
#include <cuda_runtime.h>
#include <math.h>
#include <stdint.h>

// ================= static scratch (no allocations allowed) =================
__device__ uint32_t g_xs_h [4096u*1024], g_xs_l [4096u*1024];   // x split [4096][1024p]
__device__ uint32_t g_wqd_h[1536u*1024], g_wqd_l[1536u*1024];   // wq_down
__device__ uint32_t g_wkvc_h[576u*1024], g_wkvc_l[576u*1024];   // wkv_down(512) | wk_rope(64)
__device__ uint32_t g_wqc_h[3072u*768],  g_wqc_l[3072u*768];    // wq_up(2048) | wq_rope(1024)
__device__ uint32_t g_wkvu_h[4096u*256], g_wkvu_l[4096u*256];   // wkv_up
__device__ uint32_t g_wo_h [2048u*1024], g_wo_l [2048u*1024];   // wo
__device__ float    g_qc   [4096u*1536];                        // pre-norm q_c
__device__ float    g_kvcat[4096u*576];                         // kv_c(512) | krope(64)
__device__ uint32_t g_qcs_h[4096u*768],  g_qcs_l[4096u*768];    // normed q_c split
__device__ uint32_t g_kvcs_h[4096u*256], g_kvcs_l[4096u*256];   // normed kv_c split
__device__ float    g_qup  [4096ull*3072];                      // qnope(2048) | qpe(1024)
__device__ float    g_kvup [4096ull*4096];                      // per head: k_nope(128)|v(128)
__device__ uint32_t g_Qh[32ull*2048*96], g_Ql[32ull*2048*96];   // Q packed [bh][s][96p]
__device__ uint32_t g_Kh[32ull*2048*96], g_Kl[32ull*2048*96];   // K packed
__device__ uint32_t g_Vh[32ull*128*1024], g_Vl[32ull*128*1024]; // V^T packed [bh][dv][1024 s-pairs]
__device__ uint32_t g_at_h[4096u*1024], g_at_l[4096u*1024];     // attn out packed [4096][1024p]
__device__ float    g_ropeC[2048*32], g_ropeS[2048*32];

// ================= helpers =================
__device__ __forceinline__ void splitpack(float x0, float x1, uint32_t& h, uint32_t& l) {
    uint32_t hb;
    asm("cvt.rn.bf16x2.f32 %0, %1, %2;" : "=r"(hb) : "f"(x1), "f"(x0));
    const float h0 = __uint_as_float(hb << 16);
    const float h1 = __uint_as_float(hb & 0xffff0000u);
    uint32_t lb;
    asm("cvt.rn.bf16x2.f32 %0, %1, %2;" : "=r"(lb) : "f"(x1 - h1), "f"(x0 - h0));
    h = hb; l = lb;
}

__device__ __forceinline__ void mma16(float* d, const uint32_t* a, const uint32_t* b) {
    asm volatile("mma.sync.aligned.m16n8k16.row.col.f32.bf16.bf16.f32 "
        "{%0,%1,%2,%3}, {%4,%5,%6,%7}, {%8,%9}, {%0,%1,%2,%3};"
        : "+f"(d[0]), "+f"(d[1]), "+f"(d[2]), "+f"(d[3])
        : "r"(a[0]), "r"(a[1]), "r"(a[2]), "r"(a[3]), "r"(b[0]), "r"(b[1]));
}

__device__ __forceinline__ uint32_t smem_u32(const void* p) {
    uint32_t a;
    asm("{ .reg .u64 t; cvta.to.shared.u64 t, %1; cvt.u32.u64 %0, t; }" : "=r"(a) : "l"(p));
    return a;
}
__device__ __forceinline__ void ldsm4(uint32_t* r, uint32_t addr) {
    asm volatile("ldmatrix.sync.aligned.m8n8.x4.shared.b16 {%0,%1,%2,%3}, [%4];"
        : "=r"(r[0]), "=r"(r[1]), "=r"(r[2]), "=r"(r[3]) : "r"(addr));
}
__device__ __forceinline__ void ldsm2(uint32_t* r, uint32_t addr) {
    asm volatile("ldmatrix.sync.aligned.m8n8.x2.shared.b16 {%0,%1}, [%2];"
        : "=r"(r[0]), "=r"(r[1]) : "r"(addr));
}
__device__ __forceinline__ void cpa16(uint32_t dst, const void* src) {
    asm volatile("cp.async.cg.shared.global [%0], [%1], 16;" :: "r"(dst), "l"(src));
}
__device__ __forceinline__ void cpa16z(uint32_t dst, const void* src, int ssz) {
    asm volatile("cp.async.cg.shared.global [%0], [%1], 16, %2;" :: "r"(dst), "l"(src), "r"(ssz));
}
__device__ __forceinline__ void cpa_commit() { asm volatile("cp.async.commit_group;" ::: "memory"); }
template<int NN> __device__ __forceinline__ void cpa_wait() {
    asm volatile("cp.async.wait_group %0;" :: "n"(NN) : "memory");
}

// ================= fused split: all fp32 inputs -> packed bf16 hi/lo =================
#define NP_X    4194304
#define NP_WQD  1572864
#define NP_WKVD  524288
#define NP_WKR    65536
#define NP_WQU  1572864
#define NP_WQR   786432
#define NP_WKVU 1048576
#define NP_WO   2097152
#define NP_TOTAL (NP_X+NP_WQD+NP_WKVD+NP_WKR+NP_WQU+NP_WQR+NP_WKVU+NP_WO)

__global__ __launch_bounds__(256) void split_all(
    const float* __restrict__ x,   const float* __restrict__ wqd,
    const float* __restrict__ wkvd,const float* __restrict__ wkr,
    const float* __restrict__ wqu, const float* __restrict__ wqr,
    const float* __restrict__ wkvu,const float* __restrict__ wo) {
    long long i = (long long)blockIdx.x * 256 + threadIdx.x;
    if (i >= NP_TOTAL) return;
    const float2* s; uint32_t *h, *l;
    long long j = i;
    if (j < NP_X)                    { s = (const float2*)x;    h = g_xs_h;             l = g_xs_l; }
    else if ((j -= NP_X)   < NP_WQD) { s = (const float2*)wqd;  h = g_wqd_h;            l = g_wqd_l; }
    else if ((j -= NP_WQD) < NP_WKVD){ s = (const float2*)wkvd; h = g_wkvc_h;           l = g_wkvc_l; }
    else if ((j -= NP_WKVD)< NP_WKR) { s = (const float2*)wkr;  h = g_wkvc_h + NP_WKVD; l = g_wkvc_l + NP_WKVD; }
    else if ((j -= NP_WKR) < NP_WQU) { s = (const float2*)wqu;  h = g_wqc_h;            l = g_wqc_l; }
    else if ((j -= NP_WQU) < NP_WQR) { s = (const float2*)wqr;  h = g_wqc_h + NP_WQU;   l = g_wqc_l + NP_WQU; }
    else if ((j -= NP_WQR) < NP_WKVU){ s = (const float2*)wkvu; h = g_wkvu_h;           l = g_wkvu_l; }
    else    { j -= NP_WKVU;            s = (const float2*)wo;   h = g_wo_h;             l = g_wo_l; }
    const float2 v = s[j];
    splitpack(v.x, v.y, h[j], l[j]);
}

// ================= packed bf16x3 GEMM: C[M,N] = A[M,K] @ B[N,K]^T =================
// BM=BN=128, BK=16 pairs, cp.async double-buffered, 2 CTAs/SM, ldmatrix frags.
#define GP 20                       // smem pair stride
#define GEMM_SMEM (2 * 40960)       // 2 buffers x 4 regions x 128*GP*4 bytes
__global__ __launch_bounds__(256, 2) void gemm_pk(
    const uint32_t* __restrict__ Ahg, const uint32_t* __restrict__ Alg,
    const uint32_t* __restrict__ Bhg, const uint32_t* __restrict__ Blg,
    float* __restrict__ C, int M, int N, int Kp) {
    extern __shared__ uint32_t gsm[];
    const int tid = threadIdx.x, bx = blockIdx.x, by = blockIdx.y;
    const int w = tid >> 5, lane = tid & 31;
    const int wm = (w >> 2) * 64, wn = (w & 3) * 32;
    const int lrow = tid >> 1, lp = (tid & 1) * 8;
    const int rowA = lane & 15, kselA = (lane >> 4) << 2;
    const int rowB = lane & 7,  kselB = ((lane >> 3) & 1) << 2;
    const uint32_t sbase = smem_u32(gsm);

    const uint32_t* Aph = Ahg + (size_t)(by*128 + lrow) * Kp + lp;
    const uint32_t* Apl = Alg + (size_t)(by*128 + lrow) * Kp + lp;
    const int brow = bx*128 + lrow;
    const bool bok = brow < N;
    const int ssz = bok ? 16 : 0;
    const size_t boff = (size_t)(bok ? brow : 0) * Kp + lp;
    const uint32_t* Bph = Bhg + boff;
    const uint32_t* Bpl = Blg + boff;

    float acc[4][4][4];
    #pragma unroll
    for (int mt = 0; mt < 4; mt++)
        #pragma unroll
        for (int nt = 0; nt < 4; nt++)
            #pragma unroll
            for (int i = 0; i < 4; i++) acc[mt][nt][i] = 0.f;

    // byte offsets: regions Ah 0, Al 10240, Bh 20480, Bl 30720; buffer stride 40960
    const uint32_t dfill = (uint32_t)(lrow*GP + lp) * 4u;

    const int NC = Kp >> 4;   // chunks of 16 pairs
    {   // prologue fill chunk 0 -> buffer 0
        const uint32_t base = sbase + dfill;
        cpa16 (base,          Aph);      cpa16 (base + 16,          Aph + 4);
        cpa16 (base + 10240,  Apl);      cpa16 (base + 10240 + 16,  Apl + 4);
        cpa16z(base + 20480,  Bph, ssz); cpa16z(base + 20480 + 16,  Bph + 4, ssz);
        cpa16z(base + 30720,  Bpl, ssz); cpa16z(base + 30720 + 16,  Bpl + 4, ssz);
        cpa_commit();
    }

    for (int kc = 0; kc < NC; kc++) {
        const int cur = kc & 1;
        if (kc + 1 < NC) {
            const uint32_t base = sbase + (cur ^ 1) * 40960 + dfill;
            const int ko = (kc + 1) * 16;
            cpa16 (base,          Aph + ko);      cpa16 (base + 16,          Aph + ko + 4);
            cpa16 (base + 10240,  Apl + ko);      cpa16 (base + 10240 + 16,  Apl + ko + 4);
            cpa16z(base + 20480,  Bph + ko, ssz); cpa16z(base + 20480 + 16,  Bph + ko + 4, ssz);
            cpa16z(base + 30720,  Bpl + ko, ssz); cpa16z(base + 30720 + 16,  Bpl + ko + 4, ssz);
            cpa_commit();
            cpa_wait<1>();
        } else {
            cpa_wait<0>();
        }
        __syncthreads();

        const uint32_t cb = sbase + cur * 40960;
        #pragma unroll
        for (int stp = 0; stp < 2; stp++) {
            const int p0 = stp * 8;
            uint32_t fbh[4][2], fbl[4][2];
            #pragma unroll
            for (int nt = 0; nt < 4; nt++) {
                const uint32_t ob = cb + 20480 + (uint32_t)((wn + nt*8 + rowB)*GP + p0 + kselB) * 4u;
                ldsm2(fbh[nt], ob);
                ldsm2(fbl[nt], ob + 10240);
            }
            #pragma unroll
            for (int mt = 0; mt < 4; mt++) {
                const uint32_t oa = cb + (uint32_t)((wm + mt*16 + rowA)*GP + p0 + kselA) * 4u;
                uint32_t fah[4], fal[4];
                ldsm4(fah, oa);
                ldsm4(fal, oa + 10240);
                #pragma unroll
                for (int nt = 0; nt < 4; nt++) {
                    mma16(acc[mt][nt], fah, fbh[nt]);
                    mma16(acc[mt][nt], fah, fbl[nt]);
                    mma16(acc[mt][nt], fal, fbh[nt]);
                }
            }
        }
        __syncthreads();   // compute done before next iter's fill overwrites this buffer
    }

    const int g = lane >> 2, t = lane & 3;
    #pragma unroll
    for (int mt = 0; mt < 4; mt++) {
        const int row = by*128 + wm + mt*16 + g;
        #pragma unroll
        for (int nt = 0; nt < 4; nt++) {
            const int col = bx*128 + wn + nt*8 + 2*t;
            if (col < N) {
                float* cp = C + (size_t)row * N + col;
                *(float2*)cp                   = make_float2(acc[mt][nt][0], acc[mt][nt][1]);
                *(float2*)(cp + 8 * (size_t)N) = make_float2(acc[mt][nt][2], acc[mt][nt][3]);
            }
        }
    }
}

// ================= RMSNorm + split =================
__global__ __launch_bounds__(256) void rmsnorm_split(const float* __restrict__ x, int stride,
                                                     const float* __restrict__ w, int cols,
                                                     uint32_t* __restrict__ oh,
                                                     uint32_t* __restrict__ ol) {
    const int row = blockIdx.x;
    const float* xr = x + (size_t)row * stride;
    const int tid = threadIdx.x;
    float s = 0.f;
    const float4* x4 = (const float4*)xr;
    for (int c = tid; c < (cols >> 2); c += 256) {
        const float4 v = x4[c];
        s = fmaf(v.x, v.x, s); s = fmaf(v.y, v.y, s);
        s = fmaf(v.z, v.z, s); s = fmaf(v.w, v.w, s);
    }
    __shared__ float red[256];
    red[tid] = s; __syncthreads();
    for (int st = 128; st > 0; st >>= 1) {
        if (tid < st) red[tid] += red[tid + st];
        __syncthreads();
    }
    const float inv = rsqrtf(red[0] / (float)cols + 1e-6f);
    const int pairs = cols >> 1;
    const float2* x2 = (const float2*)xr;
    const float2* w2 = (const float2*)w;
    for (int p = tid; p < pairs; p += 256) {
        const float2 xv = x2[p];
        const float2 wv = w2[p];
        splitpack(xv.x * inv * wv.x, xv.y * inv * wv.y,
                  oh[(size_t)row * pairs + p], ol[(size_t)row * pairs + p]);
    }
}

// ================= RoPE table =================
__global__ void rope_table(float* __restrict__ cosT, float* __restrict__ sinT) {
    const int idx = blockIdx.x * 256 + threadIdx.x;
    if (idx >= 2048 * 32) return;
    const int s = idx >> 5, jp = idx & 31;
    const float inv = powf(10000.0f, -(float)(2*jp) * (1.0f/64.0f));
    float sn, cs; sincosf((float)s * inv, &sn, &cs);
    cosT[idx] = cs; sinT[idx] = sn;
}

// ================= assemble Q packed =================
__global__ __launch_bounds__(256) void assemble_q_pk(const float* __restrict__ qup,
        const float* __restrict__ cosT, const float* __restrict__ sinT,
        uint32_t* __restrict__ Qh, uint32_t* __restrict__ Ql) {
    const int idx = blockIdx.x * 256 + threadIdx.x;
    if (idx >= 32*2048*96) return;
    const int p  = idx % 96;
    const int ts = idx / 96;
    const int s  = ts & 2047;
    const int bh = ts >> 11;
    const int b = bh >> 4, h = bh & 15;
    const int m = b*2048 + s;
    float x0, x1;
    if (p < 64) {
        const float* src = qup + (size_t)m*3072 + h*128 + 2*p;
        x0 = src[0]; x1 = src[1];
    } else {
        const int jp = p - 64;
        const float* src = qup + (size_t)m*3072 + 2048 + h*64 + 2*jp;
        const float c = cosT[s*32 + jp], sn = sinT[s*32 + jp];
        const float a = src[0], bb = src[1];
        x0 = a*c - bb*sn;
        x1 = a*sn + bb*c;
    }
    splitpack(x0, x1, Qh[idx], Ql[idx]);
}

// ================= assemble K packed =================
__global__ __launch_bounds__(256) void assemble_k_pk(const float* __restrict__ kvup,
        const float* __restrict__ kvcat,
        const float* __restrict__ cosT, const float* __restrict__ sinT,
        uint32_t* __restrict__ Kh, uint32_t* __restrict__ Kl) {
    const int idx = blockIdx.x * 256 + threadIdx.x;
    if (idx >= 32*2048*96) return;
    const int p  = idx % 96;
    const int ts = idx / 96;
    const int s  = ts & 2047;
    const int bh = ts >> 11;
    const int b = bh >> 4, h = bh & 15;
    const int m = b*2048 + s;
    float x0, x1;
    if (p < 64) {
        const float* src = kvup + (size_t)m*4096 + h*256 + 2*p;
        x0 = src[0]; x1 = src[1];
    } else {
        const int jp = p - 64;
        const float* src = kvcat + (size_t)m*576 + 512 + 2*jp;
        const float c = cosT[s*32 + jp], sn = sinT[s*32 + jp];
        const float a = src[0], bb = src[1];
        x0 = a*c - bb*sn;
        x1 = a*sn + bb*c;
    }
    splitpack(x0, x1, Kh[idx], Kl[idx]);
}

// ================= V transpose + split =================
__global__ void split_v(const float* __restrict__ kvup,
                        uint32_t* __restrict__ Vh, uint32_t* __restrict__ Vl) {
    __shared__ float tile[64][33];
    const int bh = blockIdx.z, b = bh >> 4, h = bh & 15;
    const int s0 = blockIdx.x * 64, dv0 = blockIdx.y * 32;
    const int tx = threadIdx.x, ty = threadIdx.y;
    #pragma unroll
    for (int half = 0; half < 2; half++) {
        const int s = s0 + half*32 + ty;
        tile[half*32 + ty][tx] =
            kvup[((size_t)(b*2048 + s))*4096 + h*256 + 128 + dv0 + tx];
    }
    __syncthreads();
    const float x0 = tile[2*tx][ty], x1 = tile[2*tx + 1][ty];
    uint32_t hh, ll; splitpack(x0, x1, hh, ll);
    const size_t o = ((size_t)bh*128 + dv0 + ty)*1024 + (s0 >> 1) + tx;
    Vh[o] = hh; Vl[o] = ll;
}

// ================= flash attention (causal, packed bf16x3, ldmatrix frags) =================
#define FQP 100
#define FVP 36
#define FPP 36
#define FL_BYTES ((4*64*FQP + 2*128*FVP + 2*64*FPP + 2*128) * 4)
__global__ __launch_bounds__(256) void flash_pk(
    const uint32_t* __restrict__ Qhg, const uint32_t* __restrict__ Qlg,
    const uint32_t* __restrict__ Khg, const uint32_t* __restrict__ Klg,
    const uint32_t* __restrict__ Vhg, const uint32_t* __restrict__ Vlg,
    uint32_t* __restrict__ Oh, uint32_t* __restrict__ Ol) {
    extern __shared__ uint32_t sw[];
    uint32_t* Qsh = sw;
    uint32_t* Qsl = Qsh + 64*FQP;
    uint32_t* Ksh = Qsl + 64*FQP;
    uint32_t* Ksl = Ksh + 64*FQP;
    uint32_t* Vsh = Ksl + 64*FQP;
    uint32_t* Vsl = Vsh + 128*FVP;
    uint32_t* Psh = Vsl + 128*FVP;
    uint32_t* Psl = Psh + 64*FPP;
    float* sMax = (float*)(Psl + 64*FPP);
    float* sSum = sMax + 128;

    const int qt = 31 - blockIdx.x;
    const int bh = blockIdx.y;
    const int b = bh >> 4, h = bh & 15;
    const int tid = threadIdx.x;
    const int w = tid >> 5, lane = tid & 31;
    const int qg = w & 3, nhalf = w >> 2;
    const int g = lane >> 2, t = lane & 3;
    const int qrow = qg * 16;

    const int rowA = lane & 15, kselA = (lane >> 4) << 2;
    const int rowB = lane & 7,  kselB = ((lane >> 3) & 1) << 2;
    const uint32_t aQh = smem_u32(Qsh), aQl = smem_u32(Qsl);
    const uint32_t aKh = smem_u32(Ksh), aKl = smem_u32(Ksl);
    const uint32_t aVh = smem_u32(Vsh), aVl = smem_u32(Vsl);
    const uint32_t aPh = smem_u32(Psh), aPl = smem_u32(Psl);

    {
        const size_t base = ((size_t)bh*2048 + qt*64) * 96;
        for (int i = tid; i < 64*24; i += 256) {
            const int r = i / 24, c = i % 24;
            *(uint4*)&Qsh[r*FQP + c*4] = *(const uint4*)(Qhg + base + (size_t)r*96 + c*4);
            *(uint4*)&Qsl[r*FQP + c*4] = *(const uint4*)(Qlg + base + (size_t)r*96 + c*4);
        }
    }

    float m0 = -INFINITY, m1 = -INFINITY, l0 = 0.f, l1 = 0.f;
    float o[8][4];
    #pragma unroll
    for (int nt = 0; nt < 8; nt++)
        #pragma unroll
        for (int e = 0; e < 4; e++) o[nt][e] = 0.f;

    const float scale = 0.07216878364870323f;   // 1/sqrt(192)

    for (int kt = 0; kt <= qt; kt++) {
        __syncthreads();
        {
            const size_t base = ((size_t)bh*2048 + kt*64) * 96;
            for (int i = tid; i < 64*24; i += 256) {
                const int r = i / 24, c = i % 24;
                *(uint4*)&Ksh[r*FQP + c*4] = *(const uint4*)(Khg + base + (size_t)r*96 + c*4);
                *(uint4*)&Ksl[r*FQP + c*4] = *(const uint4*)(Klg + base + (size_t)r*96 + c*4);
            }
            const size_t vb = (size_t)bh*128*1024 + kt*32;
            for (int i = tid; i < 128*8; i += 256) {
                const int r = i / 8, c = i % 8;
                *(uint4*)&Vsh[r*FVP + c*4] = *(const uint4*)(Vhg + vb + (size_t)r*1024 + c*4);
                *(uint4*)&Vsl[r*FVP + c*4] = *(const uint4*)(Vlg + vb + (size_t)r*1024 + c*4);
            }
        }
        __syncthreads();

        float sa[4][4];
        #pragma unroll
        for (int nt = 0; nt < 4; nt++)
            #pragma unroll
            for (int e = 0; e < 4; e++) sa[nt][e] = 0.f;

        #pragma unroll 4
        for (int st = 0; st < 12; st++) {
            const int p0 = st * 8;
            const uint32_t oq = (uint32_t)((qrow + rowA)*FQP + p0 + kselA) * 4u;
            uint32_t fah[4], fal[4];
            ldsm4(fah, aQh + oq);
            ldsm4(fal, aQl + oq);
            #pragma unroll
            for (int nt = 0; nt < 4; nt++) {
                const uint32_t ok = (uint32_t)((nhalf*32 + nt*8 + rowB)*FQP + p0 + kselB) * 4u;
                uint32_t fbh[2], fbl[2];
                ldsm2(fbh, aKh + ok);
                ldsm2(fbl, aKl + ok);
                mma16(sa[nt], fah, fbh);
                mma16(sa[nt], fah, fbl);
                mma16(sa[nt], fal, fbh);
            }
        }

        const bool diag = (kt == qt);
        float pm0 = -INFINITY, pm1 = -INFINITY;
        #pragma unroll
        for (int nt = 0; nt < 4; nt++) {
            const int colb = nhalf*32 + nt*8 + 2*t;
            #pragma unroll
            for (int e = 0; e < 4; e++) {
                float v = sa[nt][e] * scale;
                if (diag) {
                    const int col = colb + (e & 1);
                    const int row = qrow + g + ((e >> 1) << 3);
                    if (col > row) v = -INFINITY;
                }
                sa[nt][e] = v;
                if (e < 2) pm0 = fmaxf(pm0, v); else pm1 = fmaxf(pm1, v);
            }
        }
        pm0 = fmaxf(pm0, __shfl_xor_sync(0xffffffffu, pm0, 1));
        pm0 = fmaxf(pm0, __shfl_xor_sync(0xffffffffu, pm0, 2));
        pm1 = fmaxf(pm1, __shfl_xor_sync(0xffffffffu, pm1, 1));
        pm1 = fmaxf(pm1, __shfl_xor_sync(0xffffffffu, pm1, 2));
        if (t == 0) {
            sMax[nhalf*64 + qrow + g]     = pm0;
            sMax[nhalf*64 + qrow + g + 8] = pm1;
        }
        __syncthreads();
        const float mn0 = fmaxf(m0, fmaxf(pm0, sMax[(1 - nhalf)*64 + qrow + g]));
        const float mn1 = fmaxf(m1, fmaxf(pm1, sMax[(1 - nhalf)*64 + qrow + g + 8]));
        const float al0 = __expf(m0 - mn0);
        const float al1 = __expf(m1 - mn1);

        float ps0 = 0.f, ps1 = 0.f;
        #pragma unroll
        for (int nt = 0; nt < 4; nt++) {
            const int pidx = nhalf*16 + nt*4 + t;
            const float p0v = __expf(sa[nt][0] - mn0);
            const float p1v = __expf(sa[nt][1] - mn0);
            const float p2v = __expf(sa[nt][2] - mn1);
            const float p3v = __expf(sa[nt][3] - mn1);
            ps0 += p0v + p1v; ps1 += p2v + p3v;
            splitpack(p0v, p1v, Psh[(qrow + g)*FPP + pidx],     Psl[(qrow + g)*FPP + pidx]);
            splitpack(p2v, p3v, Psh[(qrow + g + 8)*FPP + pidx], Psl[(qrow + g + 8)*FPP + pidx]);
        }
        ps0 += __shfl_xor_sync(0xffffffffu, ps0, 1);
        ps0 += __shfl_xor_sync(0xffffffffu, ps0, 2);
        ps1 += __shfl_xor_sync(0xffffffffu, ps1, 1);
        ps1 += __shfl_xor_sync(0xffffffffu, ps1, 2);
        if (t == 0) {
            sSum[nhalf*64 + qrow + g]     = ps0;
            sSum[nhalf*64 + qrow + g + 8] = ps1;
        }
        __syncthreads();
        l0 = l0 * al0 + ps0 + sSum[(1 - nhalf)*64 + qrow + g];
        l1 = l1 * al1 + ps1 + sSum[(1 - nhalf)*64 + qrow + g + 8];
        m0 = mn0; m1 = mn1;

        #pragma unroll
        for (int nt = 0; nt < 8; nt++) {
            o[nt][0] *= al0; o[nt][1] *= al0;
            o[nt][2] *= al1; o[nt][3] *= al1;
        }

        #pragma unroll
        for (int st = 0; st < 4; st++) {
            const int p0 = st * 8;
            const uint32_t op = (uint32_t)((qrow + rowA)*FPP + p0 + kselA) * 4u;
            uint32_t fah[4], fal[4];
            ldsm4(fah, aPh + op);
            ldsm4(fal, aPl + op);
            #pragma unroll
            for (int nt = 0; nt < 8; nt++) {
                const uint32_t ov = (uint32_t)((nhalf*64 + nt*8 + rowB)*FVP + p0 + kselB) * 4u;
                uint32_t fbh[2], fbl[2];
                ldsm2(fbh, aVh + ov);
                ldsm2(fbl, aVl + ov);
                mma16(o[nt], fah, fbh);
                mma16(o[nt], fah, fbl);
                mma16(o[nt], fal, fbh);
            }
        }
    }

    const float il0 = 1.f / l0, il1 = 1.f / l1;
    const int row0 = b*2048 + qt*64 + qrow + g;
    #pragma unroll
    for (int nt = 0; nt < 8; nt++) {
        const int cp = h*64 + nhalf*32 + nt*4 + t;
        splitpack(o[nt][0]*il0, o[nt][1]*il0, Oh[(size_t)row0*1024 + cp],       Ol[(size_t)row0*1024 + cp]);
        splitpack(o[nt][2]*il1, o[nt][3]*il1, Oh[(size_t)(row0 + 8)*1024 + cp], Ol[(size_t)(row0 + 8)*1024 + cp]);
    }
}

// ================= host orchestration =================
static inline int cdiv(int a, int b) { return (a + b - 1) / b; }

extern "C" void kernel_launch(void* const* d_in, const int* in_sizes, int n_in,
                              void* d_out, int out_size) {
    const float* x        = (const float*)d_in[0];
    const float* wq_down  = (const float*)d_in[1];
    const float* q_norm_w = (const float*)d_in[2];
    const float* wq_up    = (const float*)d_in[3];
    const float* wq_rope  = (const float*)d_in[4];
    const float* wkv_down = (const float*)d_in[5];
    const float* kv_norm_w= (const float*)d_in[6];
    const float* wkv_up   = (const float*)d_in[7];
    const float* wk_rope  = (const float*)d_in[8];
    const float* wo       = (const float*)d_in[9];
    float* out = (float*)d_out;

    uint32_t *xs_h,*xs_l,*wqd_h,*wqd_l,*wkvc_h,*wkvc_l,*wqc_h,*wqc_l,*wkvu_h,*wkvu_l,*wo_h,*wo_l;
    uint32_t *qcs_h,*qcs_l,*kvcs_h,*kvcs_l,*Qh,*Ql,*Kh,*Kl,*Vh,*Vl,*at_h,*at_l;
    float *qc,*kvcat,*qup,*kvup,*ropeC,*ropeS;
    cudaGetSymbolAddress((void**)&xs_h,  g_xs_h);  cudaGetSymbolAddress((void**)&xs_l,  g_xs_l);
    cudaGetSymbolAddress((void**)&wqd_h, g_wqd_h); cudaGetSymbolAddress((void**)&wqd_l, g_wqd_l);
    cudaGetSymbolAddress((void**)&wkvc_h,g_wkvc_h);cudaGetSymbolAddress((void**)&wkvc_l,g_wkvc_l);
    cudaGetSymbolAddress((void**)&wqc_h, g_wqc_h); cudaGetSymbolAddress((void**)&wqc_l, g_wqc_l);
    cudaGetSymbolAddress((void**)&wkvu_h,g_wkvu_h);cudaGetSymbolAddress((void**)&wkvu_l,g_wkvu_l);
    cudaGetSymbolAddress((void**)&wo_h,  g_wo_h);  cudaGetSymbolAddress((void**)&wo_l,  g_wo_l);
    cudaGetSymbolAddress((void**)&qc,    g_qc);    cudaGetSymbolAddress((void**)&kvcat, g_kvcat);
    cudaGetSymbolAddress((void**)&qcs_h, g_qcs_h); cudaGetSymbolAddress((void**)&qcs_l, g_qcs_l);
    cudaGetSymbolAddress((void**)&kvcs_h,g_kvcs_h);cudaGetSymbolAddress((void**)&kvcs_l,g_kvcs_l);
    cudaGetSymbolAddress((void**)&qup,   g_qup);   cudaGetSymbolAddress((void**)&kvup,  g_kvup);
    cudaGetSymbolAddress((void**)&Qh,    g_Qh);    cudaGetSymbolAddress((void**)&Ql,    g_Ql);
    cudaGetSymbolAddress((void**)&Kh,    g_Kh);    cudaGetSymbolAddress((void**)&Kl,    g_Kl);
    cudaGetSymbolAddress((void**)&Vh,    g_Vh);    cudaGetSymbolAddress((void**)&Vl,    g_Vl);
    cudaGetSymbolAddress((void**)&at_h,  g_at_h);  cudaGetSymbolAddress((void**)&at_l,  g_at_l);
    cudaGetSymbolAddress((void**)&ropeC, g_ropeC); cudaGetSymbolAddress((void**)&ropeS, g_ropeS);

    cudaFuncSetAttribute(gemm_pk, cudaFuncAttributeMaxDynamicSharedMemorySize, GEMM_SMEM);
    cudaFuncSetAttribute(flash_pk, cudaFuncAttributeMaxDynamicSharedMemorySize, FL_BYTES);

    // ---- one fused split of all fp32 inputs ----
    split_all<<<cdiv((int)NP_TOTAL, 256), 256>>>(x, wq_down, wkv_down, wk_rope,
                                                 wq_up, wq_rope, wkv_up, wo);
    rope_table<<<cdiv(2048*32, 256), 256>>>(ropeC, ropeS);

    // ---- down projections ----
    gemm_pk<<<dim3(12, 32), 256, GEMM_SMEM>>>(xs_h, xs_l, wqd_h,  wqd_l,  qc,    4096, 1536, 1024);
    gemm_pk<<<dim3(5,  32), 256, GEMM_SMEM>>>(xs_h, xs_l, wkvc_h, wkvc_l, kvcat, 4096, 576,  1024);

    rmsnorm_split<<<4096, 256>>>(qc,    1536, q_norm_w,  1536, qcs_h,  qcs_l);
    rmsnorm_split<<<4096, 256>>>(kvcat, 576,  kv_norm_w, 512,  kvcs_h, kvcs_l);

    // ---- up projections ----
    gemm_pk<<<dim3(24, 32), 256, GEMM_SMEM>>>(qcs_h,  qcs_l,  wqc_h,  wqc_l,  qup,  4096, 3072, 768);
    gemm_pk<<<dim3(32, 32), 256, GEMM_SMEM>>>(kvcs_h, kvcs_l, wkvu_h, wkvu_l, kvup, 4096, 4096, 256);

    // ---- assemble packed Q/K/V ----
    assemble_q_pk<<<cdiv(32*2048*96, 256), 256>>>(qup, ropeC, ropeS, Qh, Ql);
    assemble_k_pk<<<cdiv(32*2048*96, 256), 256>>>(kvup, kvcat, ropeC, ropeS, Kh, Kl);
    split_v<<<dim3(32, 4, 32), dim3(32, 32)>>>(kvup, Vh, Vl);

    // ---- flash attention ----
    flash_pk<<<dim3(32, 32), 256, FL_BYTES>>>(Qh, Ql, Kh, Kl, Vh, Vl, at_h, at_l);

    // ---- output projection ----
    gemm_pk<<<dim3(16, 32), 256, GEMM_SMEM>>>(at_h, at_l, wo_h, wo_l, out, 4096, 2048, 1024);
}

// round 8
// speedup vs baseline: 2.2613x; 1.0057x over previous
#include <cuda_runtime.h>
#include <math.h>
#include <stdint.h>

// ================= static scratch (no allocations allowed) =================
__device__ uint32_t g_xs_h [4096u*1024], g_xs_l [4096u*1024];   // x split [4096][1024p]
__device__ uint32_t g_wqd_h[1536u*1024], g_wqd_l[1536u*1024];   // wq_down
__device__ uint32_t g_wkvc_h[576u*1024], g_wkvc_l[576u*1024];   // wkv_down(512) | wk_rope(64)
__device__ uint32_t g_wqc_h[3072u*768],  g_wqc_l[3072u*768];    // wq_up(2048) | wq_rope(1024)
__device__ uint32_t g_wkvu_h[4096u*256], g_wkvu_l[4096u*256];   // wkv_up
__device__ uint32_t g_wo_h [2048u*1024], g_wo_l [2048u*1024];   // wo
__device__ float    g_qc   [4096u*1536];                        // pre-norm q_c
__device__ float    g_kvcat[4096u*576];                         // kv_c(512) | krope(64)
__device__ uint32_t g_qcs_h[4096u*768],  g_qcs_l[4096u*768];    // normed q_c split
__device__ uint32_t g_kvcs_h[4096u*256], g_kvcs_l[4096u*256];   // normed kv_c split
__device__ float    g_qup  [4096ull*3072];                      // qnope(2048) | qpe(1024)
__device__ float    g_kvup [4096ull*4096];                      // per head: k_nope(128)|v(128)
__device__ uint32_t g_Qh[32ull*2048*96], g_Ql[32ull*2048*96];   // Q packed [bh][s][96p]
__device__ uint32_t g_Kh[32ull*2048*96], g_Kl[32ull*2048*96];   // K packed
__device__ uint32_t g_Vh[32ull*128*1024], g_Vl[32ull*128*1024]; // V^T packed [bh][dv][1024 s-pairs]
__device__ uint32_t g_at_h[4096u*1024], g_at_l[4096u*1024];     // attn out packed [4096][1024p]
__device__ float    g_ropeC[2048*32], g_ropeS[2048*32];

// ================= helpers =================
__device__ __forceinline__ void splitpack(float x0, float x1, uint32_t& h, uint32_t& l) {
    uint32_t hb;
    asm("cvt.rn.bf16x2.f32 %0, %1, %2;" : "=r"(hb) : "f"(x1), "f"(x0));
    const float h0 = __uint_as_float(hb << 16);
    const float h1 = __uint_as_float(hb & 0xffff0000u);
    uint32_t lb;
    asm("cvt.rn.bf16x2.f32 %0, %1, %2;" : "=r"(lb) : "f"(x1 - h1), "f"(x0 - h0));
    h = hb; l = lb;
}

__device__ __forceinline__ void mma16(float* d, const uint32_t* a, const uint32_t* b) {
    asm volatile("mma.sync.aligned.m16n8k16.row.col.f32.bf16.bf16.f32 "
        "{%0,%1,%2,%3}, {%4,%5,%6,%7}, {%8,%9}, {%0,%1,%2,%3};"
        : "+f"(d[0]), "+f"(d[1]), "+f"(d[2]), "+f"(d[3])
        : "r"(a[0]), "r"(a[1]), "r"(a[2]), "r"(a[3]), "r"(b[0]), "r"(b[1]));
}

__device__ __forceinline__ uint32_t smem_u32(const void* p) {
    uint32_t a;
    asm("{ .reg .u64 t; cvta.to.shared.u64 t, %1; cvt.u32.u64 %0, t; }" : "=r"(a) : "l"(p));
    return a;
}
__device__ __forceinline__ void ldsm4(uint32_t* r, uint32_t addr) {
    asm volatile("ldmatrix.sync.aligned.m8n8.x4.shared.b16 {%0,%1,%2,%3}, [%4];"
        : "=r"(r[0]), "=r"(r[1]), "=r"(r[2]), "=r"(r[3]) : "r"(addr));
}
__device__ __forceinline__ void ldsm2(uint32_t* r, uint32_t addr) {
    asm volatile("ldmatrix.sync.aligned.m8n8.x2.shared.b16 {%0,%1}, [%2];"
        : "=r"(r[0]), "=r"(r[1]) : "r"(addr));
}
__device__ __forceinline__ void cpa16(uint32_t dst, const void* src) {
    asm volatile("cp.async.cg.shared.global [%0], [%1], 16;" :: "r"(dst), "l"(src));
}
__device__ __forceinline__ void cpa16z(uint32_t dst, const void* src, int ssz) {
    asm volatile("cp.async.cg.shared.global [%0], [%1], 16, %2;" :: "r"(dst), "l"(src), "r"(ssz));
}
__device__ __forceinline__ void cpa_commit() { asm volatile("cp.async.commit_group;" ::: "memory"); }
template<int NN> __device__ __forceinline__ void cpa_wait() {
    asm volatile("cp.async.wait_group %0;" :: "n"(NN) : "memory");
}

// ================= fused split: all fp32 inputs -> packed bf16 hi/lo =================
#define NP_X    4194304
#define NP_WQD  1572864
#define NP_WKVD  524288
#define NP_WKR    65536
#define NP_WQU  1572864
#define NP_WQR   786432
#define NP_WKVU 1048576
#define NP_WO   2097152
#define NP_TOTAL (NP_X+NP_WQD+NP_WKVD+NP_WKR+NP_WQU+NP_WQR+NP_WKVU+NP_WO)

__global__ __launch_bounds__(256) void split_all(
    const float* __restrict__ x,   const float* __restrict__ wqd,
    const float* __restrict__ wkvd,const float* __restrict__ wkr,
    const float* __restrict__ wqu, const float* __restrict__ wqr,
    const float* __restrict__ wkvu,const float* __restrict__ wo) {
    long long i = (long long)blockIdx.x * 256 + threadIdx.x;
    if (i >= NP_TOTAL) return;
    const float2* s; uint32_t *h, *l;
    long long j = i;
    if (j < NP_X)                    { s = (const float2*)x;    h = g_xs_h;             l = g_xs_l; }
    else if ((j -= NP_X)   < NP_WQD) { s = (const float2*)wqd;  h = g_wqd_h;            l = g_wqd_l; }
    else if ((j -= NP_WQD) < NP_WKVD){ s = (const float2*)wkvd; h = g_wkvc_h;           l = g_wkvc_l; }
    else if ((j -= NP_WKVD)< NP_WKR) { s = (const float2*)wkr;  h = g_wkvc_h + NP_WKVD; l = g_wkvc_l + NP_WKVD; }
    else if ((j -= NP_WKR) < NP_WQU) { s = (const float2*)wqu;  h = g_wqc_h;            l = g_wqc_l; }
    else if ((j -= NP_WQU) < NP_WQR) { s = (const float2*)wqr;  h = g_wqc_h + NP_WQU;   l = g_wqc_l + NP_WQU; }
    else if ((j -= NP_WQR) < NP_WKVU){ s = (const float2*)wkvu; h = g_wkvu_h;           l = g_wkvu_l; }
    else    { j -= NP_WKVU;            s = (const float2*)wo;   h = g_wo_h;             l = g_wo_l; }
    const float2 v = s[j];
    splitpack(v.x, v.y, h[j], l[j]);
}

// ================= packed bf16x3 GEMM: C[M,N] = A[M,K] @ B[N,K]^T =================
// BM=BN=128, BK=16 pairs, cp.async double-buffered, 2 CTAs/SM, ldmatrix frags.
// Inner loops ordered so same-accumulator mmas are 4 apart (no RAW chains).
#define GP 20
#define GEMM_SMEM (2 * 40960)
__global__ __launch_bounds__(256, 2) void gemm_pk(
    const uint32_t* __restrict__ Ahg, const uint32_t* __restrict__ Alg,
    const uint32_t* __restrict__ Bhg, const uint32_t* __restrict__ Blg,
    float* __restrict__ C, int M, int N, int Kp) {
    extern __shared__ uint32_t gsm[];
    const int tid = threadIdx.x, bx = blockIdx.x, by = blockIdx.y;
    const int w = tid >> 5, lane = tid & 31;
    const int wm = (w >> 2) * 64, wn = (w & 3) * 32;
    const int lrow = tid >> 1, lp = (tid & 1) * 8;
    const int rowA = lane & 15, kselA = (lane >> 4) << 2;
    const int rowB = lane & 7,  kselB = ((lane >> 3) & 1) << 2;
    const uint32_t sbase = smem_u32(gsm);

    const uint32_t* Aph = Ahg + (size_t)(by*128 + lrow) * Kp + lp;
    const uint32_t* Apl = Alg + (size_t)(by*128 + lrow) * Kp + lp;
    const int brow = bx*128 + lrow;
    const bool bok = brow < N;
    const int ssz = bok ? 16 : 0;
    const size_t boff = (size_t)(bok ? brow : 0) * Kp + lp;
    const uint32_t* Bph = Bhg + boff;
    const uint32_t* Bpl = Blg + boff;

    float acc[4][4][4];
    #pragma unroll
    for (int mt = 0; mt < 4; mt++)
        #pragma unroll
        for (int nt = 0; nt < 4; nt++)
            #pragma unroll
            for (int i = 0; i < 4; i++) acc[mt][nt][i] = 0.f;

    const uint32_t dfill = (uint32_t)(lrow*GP + lp) * 4u;

    const int NC = Kp >> 4;
    {   // prologue fill chunk 0 -> buffer 0
        const uint32_t base = sbase + dfill;
        cpa16 (base,          Aph);      cpa16 (base + 16,          Aph + 4);
        cpa16 (base + 10240,  Apl);      cpa16 (base + 10240 + 16,  Apl + 4);
        cpa16z(base + 20480,  Bph, ssz); cpa16z(base + 20480 + 16,  Bph + 4, ssz);
        cpa16z(base + 30720,  Bpl, ssz); cpa16z(base + 30720 + 16,  Bpl + 4, ssz);
        cpa_commit();
    }

    for (int kc = 0; kc < NC; kc++) {
        const int cur = kc & 1;
        if (kc + 1 < NC) {
            const uint32_t base = sbase + (cur ^ 1) * 40960 + dfill;
            const int ko = (kc + 1) * 16;
            cpa16 (base,          Aph + ko);      cpa16 (base + 16,          Aph + ko + 4);
            cpa16 (base + 10240,  Apl + ko);      cpa16 (base + 10240 + 16,  Apl + ko + 4);
            cpa16z(base + 20480,  Bph + ko, ssz); cpa16z(base + 20480 + 16,  Bph + ko + 4, ssz);
            cpa16z(base + 30720,  Bpl + ko, ssz); cpa16z(base + 30720 + 16,  Bpl + ko + 4, ssz);
            cpa_commit();
            cpa_wait<1>();
        } else {
            cpa_wait<0>();
        }
        __syncthreads();

        const uint32_t cb = sbase + cur * 40960;
        #pragma unroll
        for (int stp = 0; stp < 2; stp++) {
            const int p0 = stp * 8;
            uint32_t fbh[4][2], fbl[4][2];
            #pragma unroll
            for (int nt = 0; nt < 4; nt++) {
                const uint32_t ob = cb + 20480 + (uint32_t)((wn + nt*8 + rowB)*GP + p0 + kselB) * 4u;
                ldsm2(fbh[nt], ob);
                ldsm2(fbl[nt], ob + 10240);
            }
            #pragma unroll
            for (int mt = 0; mt < 4; mt++) {
                const uint32_t oa = cb + (uint32_t)((wm + mt*16 + rowA)*GP + p0 + kselA) * 4u;
                uint32_t fah[4], fal[4];
                ldsm4(fah, oa);
                ldsm4(fal, oa + 10240);
                // term sweeps: same acc touched every 4 mmas, order per-acc preserved (hh,hl,lh)
                #pragma unroll
                for (int nt = 0; nt < 4; nt++) mma16(acc[mt][nt], fah, fbh[nt]);
                #pragma unroll
                for (int nt = 0; nt < 4; nt++) mma16(acc[mt][nt], fah, fbl[nt]);
                #pragma unroll
                for (int nt = 0; nt < 4; nt++) mma16(acc[mt][nt], fal, fbh[nt]);
            }
        }
        __syncthreads();
    }

    const int g = lane >> 2, t = lane & 3;
    #pragma unroll
    for (int mt = 0; mt < 4; mt++) {
        const int row = by*128 + wm + mt*16 + g;
        #pragma unroll
        for (int nt = 0; nt < 4; nt++) {
            const int col = bx*128 + wn + nt*8 + 2*t;
            if (col < N) {
                float* cp = C + (size_t)row * N + col;
                *(float2*)cp                   = make_float2(acc[mt][nt][0], acc[mt][nt][1]);
                *(float2*)(cp + 8 * (size_t)N) = make_float2(acc[mt][nt][2], acc[mt][nt][3]);
            }
        }
    }
}

// ================= RMSNorm + split =================
__global__ __launch_bounds__(256) void rmsnorm_split(const float* __restrict__ x, int stride,
                                                     const float* __restrict__ w, int cols,
                                                     uint32_t* __restrict__ oh,
                                                     uint32_t* __restrict__ ol) {
    const int row = blockIdx.x;
    const float* xr = x + (size_t)row * stride;
    const int tid = threadIdx.x;
    float s = 0.f;
    const float4* x4 = (const float4*)xr;
    for (int c = tid; c < (cols >> 2); c += 256) {
        const float4 v = x4[c];
        s = fmaf(v.x, v.x, s); s = fmaf(v.y, v.y, s);
        s = fmaf(v.z, v.z, s); s = fmaf(v.w, v.w, s);
    }
    __shared__ float red[256];
    red[tid] = s; __syncthreads();
    for (int st = 128; st > 0; st >>= 1) {
        if (tid < st) red[tid] += red[tid + st];
        __syncthreads();
    }
    const float inv = rsqrtf(red[0] / (float)cols + 1e-6f);
    const int pairs = cols >> 1;
    const float2* x2 = (const float2*)xr;
    const float2* w2 = (const float2*)w;
    for (int p = tid; p < pairs; p += 256) {
        const float2 xv = x2[p];
        const float2 wv = w2[p];
        splitpack(xv.x * inv * wv.x, xv.y * inv * wv.y,
                  oh[(size_t)row * pairs + p], ol[(size_t)row * pairs + p]);
    }
}

// ================= RoPE table =================
__global__ void rope_table(float* __restrict__ cosT, float* __restrict__ sinT) {
    const int idx = blockIdx.x * 256 + threadIdx.x;
    if (idx >= 2048 * 32) return;
    const int s = idx >> 5, jp = idx & 31;
    const float inv = powf(10000.0f, -(float)(2*jp) * (1.0f/64.0f));
    float sn, cs; sincosf((float)s * inv, &sn, &cs);
    cosT[idx] = cs; sinT[idx] = sn;
}

// ================= assemble Q packed =================
__global__ __launch_bounds__(256) void assemble_q_pk(const float* __restrict__ qup,
        const float* __restrict__ cosT, const float* __restrict__ sinT,
        uint32_t* __restrict__ Qh, uint32_t* __restrict__ Ql) {
    const int idx = blockIdx.x * 256 + threadIdx.x;
    if (idx >= 32*2048*96) return;
    const int p  = idx % 96;
    const int ts = idx / 96;
    const int s  = ts & 2047;
    const int bh = ts >> 11;
    const int b = bh >> 4, h = bh & 15;
    const int m = b*2048 + s;
    float x0, x1;
    if (p < 64) {
        const float* src = qup + (size_t)m*3072 + h*128 + 2*p;
        x0 = src[0]; x1 = src[1];
    } else {
        const int jp = p - 64;
        const float* src = qup + (size_t)m*3072 + 2048 + h*64 + 2*jp;
        const float c = cosT[s*32 + jp], sn = sinT[s*32 + jp];
        const float a = src[0], bb = src[1];
        x0 = a*c - bb*sn;
        x1 = a*sn + bb*c;
    }
    splitpack(x0, x1, Qh[idx], Ql[idx]);
}

// ================= assemble K packed =================
__global__ __launch_bounds__(256) void assemble_k_pk(const float* __restrict__ kvup,
        const float* __restrict__ kvcat,
        const float* __restrict__ cosT, const float* __restrict__ sinT,
        uint32_t* __restrict__ Kh, uint32_t* __restrict__ Kl) {
    const int idx = blockIdx.x * 256 + threadIdx.x;
    if (idx >= 32*2048*96) return;
    const int p  = idx % 96;
    const int ts = idx / 96;
    const int s  = ts & 2047;
    const int bh = ts >> 11;
    const int b = bh >> 4, h = bh & 15;
    const int m = b*2048 + s;
    float x0, x1;
    if (p < 64) {
        const float* src = kvup + (size_t)m*4096 + h*256 + 2*p;
        x0 = src[0]; x1 = src[1];
    } else {
        const int jp = p - 64;
        const float* src = kvcat + (size_t)m*576 + 512 + 2*jp;
        const float c = cosT[s*32 + jp], sn = sinT[s*32 + jp];
        const float a = src[0], bb = src[1];
        x0 = a*c - bb*sn;
        x1 = a*sn + bb*c;
    }
    splitpack(x0, x1, Kh[idx], Kl[idx]);
}

// ================= V transpose + split =================
__global__ void split_v(const float* __restrict__ kvup,
                        uint32_t* __restrict__ Vh, uint32_t* __restrict__ Vl) {
    __shared__ float tile[64][33];
    const int bh = blockIdx.z, b = bh >> 4, h = bh & 15;
    const int s0 = blockIdx.x * 64, dv0 = blockIdx.y * 32;
    const int tx = threadIdx.x, ty = threadIdx.y;
    #pragma unroll
    for (int half = 0; half < 2; half++) {
        const int s = s0 + half*32 + ty;
        tile[half*32 + ty][tx] =
            kvup[((size_t)(b*2048 + s))*4096 + h*256 + 128 + dv0 + tx];
    }
    __syncthreads();
    const float x0 = tile[2*tx][ty], x1 = tile[2*tx + 1][ty];
    uint32_t hh, ll; splitpack(x0, x1, hh, ll);
    const size_t o = ((size_t)bh*128 + dv0 + ty)*1024 + (s0 >> 1) + tx;
    Vh[o] = hh; Vl[o] = ll;
}

// ================= flash attention (causal, packed bf16x3, ldmatrix frags) =================
#define FQP 100
#define FVP 36
#define FPP 36
#define FL_BYTES ((4*64*FQP + 2*128*FVP + 2*64*FPP + 2*128) * 4)
__global__ __launch_bounds__(256) void flash_pk(
    const uint32_t* __restrict__ Qhg, const uint32_t* __restrict__ Qlg,
    const uint32_t* __restrict__ Khg, const uint32_t* __restrict__ Klg,
    const uint32_t* __restrict__ Vhg, const uint32_t* __restrict__ Vlg,
    uint32_t* __restrict__ Oh, uint32_t* __restrict__ Ol) {
    extern __shared__ uint32_t sw[];
    uint32_t* Qsh = sw;
    uint32_t* Qsl = Qsh + 64*FQP;
    uint32_t* Ksh = Qsl + 64*FQP;
    uint32_t* Ksl = Ksh + 64*FQP;
    uint32_t* Vsh = Ksl + 64*FQP;
    uint32_t* Vsl = Vsh + 128*FVP;
    uint32_t* Psh = Vsl + 128*FVP;
    uint32_t* Psl = Psh + 64*FPP;
    float* sMax = (float*)(Psl + 64*FPP);
    float* sSum = sMax + 128;

    const int qt = 31 - blockIdx.x;
    const int bh = blockIdx.y;
    const int b = bh >> 4, h = bh & 15;
    const int tid = threadIdx.x;
    const int w = tid >> 5, lane = tid & 31;
    const int qg = w & 3, nhalf = w >> 2;
    const int g = lane >> 2, t = lane & 3;
    const int qrow = qg * 16;

    const int rowA = lane & 15, kselA = (lane >> 4) << 2;
    const int rowB = lane & 7,  kselB = ((lane >> 3) & 1) << 2;
    const uint32_t aQh = smem_u32(Qsh), aQl = smem_u32(Qsl);
    const uint32_t aKh = smem_u32(Ksh), aKl = smem_u32(Ksl);
    const uint32_t aVh = smem_u32(Vsh), aVl = smem_u32(Vsl);
    const uint32_t aPh = smem_u32(Psh), aPl = smem_u32(Psl);

    {
        const size_t base = ((size_t)bh*2048 + qt*64) * 96;
        for (int i = tid; i < 64*24; i += 256) {
            const int r = i / 24, c = i % 24;
            *(uint4*)&Qsh[r*FQP + c*4] = *(const uint4*)(Qhg + base + (size_t)r*96 + c*4);
            *(uint4*)&Qsl[r*FQP + c*4] = *(const uint4*)(Qlg + base + (size_t)r*96 + c*4);
        }
    }

    float m0 = -INFINITY, m1 = -INFINITY, l0 = 0.f, l1 = 0.f;
    float o[8][4];
    #pragma unroll
    for (int nt = 0; nt < 8; nt++)
        #pragma unroll
        for (int e = 0; e < 4; e++) o[nt][e] = 0.f;

    const float scale = 0.07216878364870323f;   // 1/sqrt(192)

    for (int kt = 0; kt <= qt; kt++) {
        __syncthreads();
        {
            const size_t base = ((size_t)bh*2048 + kt*64) * 96;
            for (int i = tid; i < 64*24; i += 256) {
                const int r = i / 24, c = i % 24;
                *(uint4*)&Ksh[r*FQP + c*4] = *(const uint4*)(Khg + base + (size_t)r*96 + c*4);
                *(uint4*)&Ksl[r*FQP + c*4] = *(const uint4*)(Klg + base + (size_t)r*96 + c*4);
            }
            const size_t vb = (size_t)bh*128*1024 + kt*32;
            for (int i = tid; i < 128*8; i += 256) {
                const int r = i / 8, c = i % 8;
                *(uint4*)&Vsh[r*FVP + c*4] = *(const uint4*)(Vhg + vb + (size_t)r*1024 + c*4);
                *(uint4*)&Vsl[r*FVP + c*4] = *(const uint4*)(Vlg + vb + (size_t)r*1024 + c*4);
            }
        }
        __syncthreads();

        float sa[4][4];
        #pragma unroll
        for (int nt = 0; nt < 4; nt++)
            #pragma unroll
            for (int e = 0; e < 4; e++) sa[nt][e] = 0.f;

        #pragma unroll 4
        for (int st = 0; st < 12; st++) {
            const int p0 = st * 8;
            const uint32_t oq = (uint32_t)((qrow + rowA)*FQP + p0 + kselA) * 4u;
            uint32_t fah[4], fal[4];
            ldsm4(fah, aQh + oq);
            ldsm4(fal, aQl + oq);
            uint32_t fbh[4][2], fbl[4][2];
            #pragma unroll
            for (int nt = 0; nt < 4; nt++) {
                const uint32_t ok = (uint32_t)((nhalf*32 + nt*8 + rowB)*FQP + p0 + kselB) * 4u;
                ldsm2(fbh[nt], aKh + ok);
                ldsm2(fbl[nt], aKl + ok);
            }
            #pragma unroll
            for (int nt = 0; nt < 4; nt++) mma16(sa[nt], fah, fbh[nt]);
            #pragma unroll
            for (int nt = 0; nt < 4; nt++) mma16(sa[nt], fah, fbl[nt]);
            #pragma unroll
            for (int nt = 0; nt < 4; nt++) mma16(sa[nt], fal, fbh[nt]);
        }

        const bool diag = (kt == qt);
        float pm0 = -INFINITY, pm1 = -INFINITY;
        #pragma unroll
        for (int nt = 0; nt < 4; nt++) {
            const int colb = nhalf*32 + nt*8 + 2*t;
            #pragma unroll
            for (int e = 0; e < 4; e++) {
                float v = sa[nt][e] * scale;
                if (diag) {
                    const int col = colb + (e & 1);
                    const int row = qrow + g + ((e >> 1) << 3);
                    if (col > row) v = -INFINITY;
                }
                sa[nt][e] = v;
                if (e < 2) pm0 = fmaxf(pm0, v); else pm1 = fmaxf(pm1, v);
            }
        }
        pm0 = fmaxf(pm0, __shfl_xor_sync(0xffffffffu, pm0, 1));
        pm0 = fmaxf(pm0, __shfl_xor_sync(0xffffffffu, pm0, 2));
        pm1 = fmaxf(pm1, __shfl_xor_sync(0xffffffffu, pm1, 1));
        pm1 = fmaxf(pm1, __shfl_xor_sync(0xffffffffu, pm1, 2));
        if (t == 0) {
            sMax[nhalf*64 + qrow + g]     = pm0;
            sMax[nhalf*64 + qrow + g + 8] = pm1;
        }
        __syncthreads();
        const float mn0 = fmaxf(m0, fmaxf(pm0, sMax[(1 - nhalf)*64 + qrow + g]));
        const float mn1 = fmaxf(m1, fmaxf(pm1, sMax[(1 - nhalf)*64 + qrow + g + 8]));
        const float al0 = __expf(m0 - mn0);
        const float al1 = __expf(m1 - mn1);

        float ps0 = 0.f, ps1 = 0.f;
        #pragma unroll
        for (int nt = 0; nt < 4; nt++) {
            const int pidx = nhalf*16 + nt*4 + t;
            const float p0v = __expf(sa[nt][0] - mn0);
            const float p1v = __expf(sa[nt][1] - mn0);
            const float p2v = __expf(sa[nt][2] - mn1);
            const float p3v = __expf(sa[nt][3] - mn1);
            ps0 += p0v + p1v; ps1 += p2v + p3v;
            splitpack(p0v, p1v, Psh[(qrow + g)*FPP + pidx],     Psl[(qrow + g)*FPP + pidx]);
            splitpack(p2v, p3v, Psh[(qrow + g + 8)*FPP + pidx], Psl[(qrow + g + 8)*FPP + pidx]);
        }
        ps0 += __shfl_xor_sync(0xffffffffu, ps0, 1);
        ps0 += __shfl_xor_sync(0xffffffffu, ps0, 2);
        ps1 += __shfl_xor_sync(0xffffffffu, ps1, 1);
        ps1 += __shfl_xor_sync(0xffffffffu, ps1, 2);
        if (t == 0) {
            sSum[nhalf*64 + qrow + g]     = ps0;
            sSum[nhalf*64 + qrow + g + 8] = ps1;
        }
        __syncthreads();
        l0 = l0 * al0 + ps0 + sSum[(1 - nhalf)*64 + qrow + g];
        l1 = l1 * al1 + ps1 + sSum[(1 - nhalf)*64 + qrow + g + 8];
        m0 = mn0; m1 = mn1;

        #pragma unroll
        for (int nt = 0; nt < 8; nt++) {
            o[nt][0] *= al0; o[nt][1] *= al0;
            o[nt][2] *= al1; o[nt][3] *= al1;
        }

        // ---- O += P V : per st, per nt-half of 4: term sweeps ----
        #pragma unroll
        for (int st = 0; st < 4; st++) {
            const int p0 = st * 8;
            const uint32_t op = (uint32_t)((qrow + rowA)*FPP + p0 + kselA) * 4u;
            uint32_t fah[4], fal[4];
            ldsm4(fah, aPh + op);
            ldsm4(fal, aPl + op);
            #pragma unroll
            for (int hv = 0; hv < 2; hv++) {
                uint32_t fbh[4][2], fbl[4][2];
                #pragma unroll
                for (int n4 = 0; n4 < 4; n4++) {
                    const int nt = hv*4 + n4;
                    const uint32_t ov = (uint32_t)((nhalf*64 + nt*8 + rowB)*FVP + p0 + kselB) * 4u;
                    ldsm2(fbh[n4], aVh + ov);
                    ldsm2(fbl[n4], aVl + ov);
                }
                #pragma unroll
                for (int n4 = 0; n4 < 4; n4++) mma16(o[hv*4 + n4], fah, fbh[n4]);
                #pragma unroll
                for (int n4 = 0; n4 < 4; n4++) mma16(o[hv*4 + n4], fah, fbl[n4]);
                #pragma unroll
                for (int n4 = 0; n4 < 4; n4++) mma16(o[hv*4 + n4], fal, fbh[n4]);
            }
        }
    }

    const float il0 = 1.f / l0, il1 = 1.f / l1;
    const int row0 = b*2048 + qt*64 + qrow + g;
    #pragma unroll
    for (int nt = 0; nt < 8; nt++) {
        const int cp = h*64 + nhalf*32 + nt*4 + t;
        splitpack(o[nt][0]*il0, o[nt][1]*il0, Oh[(size_t)row0*1024 + cp],       Ol[(size_t)row0*1024 + cp]);
        splitpack(o[nt][2]*il1, o[nt][3]*il1, Oh[(size_t)(row0 + 8)*1024 + cp], Ol[(size_t)(row0 + 8)*1024 + cp]);
    }
}

// ================= host orchestration =================
static inline int cdiv(int a, int b) { return (a + b - 1) / b; }

extern "C" void kernel_launch(void* const* d_in, const int* in_sizes, int n_in,
                              void* d_out, int out_size) {
    const float* x        = (const float*)d_in[0];
    const float* wq_down  = (const float*)d_in[1];
    const float* q_norm_w = (const float*)d_in[2];
    const float* wq_up    = (const float*)d_in[3];
    const float* wq_rope  = (const float*)d_in[4];
    const float* wkv_down = (const float*)d_in[5];
    const float* kv_norm_w= (const float*)d_in[6];
    const float* wkv_up   = (const float*)d_in[7];
    const float* wk_rope  = (const float*)d_in[8];
    const float* wo       = (const float*)d_in[9];
    float* out = (float*)d_out;

    uint32_t *xs_h,*xs_l,*wqd_h,*wqd_l,*wkvc_h,*wkvc_l,*wqc_h,*wqc_l,*wkvu_h,*wkvu_l,*wo_h,*wo_l;
    uint32_t *qcs_h,*qcs_l,*kvcs_h,*kvcs_l,*Qh,*Ql,*Kh,*Kl,*Vh,*Vl,*at_h,*at_l;
    float *qc,*kvcat,*qup,*kvup,*ropeC,*ropeS;
    cudaGetSymbolAddress((void**)&xs_h,  g_xs_h);  cudaGetSymbolAddress((void**)&xs_l,  g_xs_l);
    cudaGetSymbolAddress((void**)&wqd_h, g_wqd_h); cudaGetSymbolAddress((void**)&wqd_l, g_wqd_l);
    cudaGetSymbolAddress((void**)&wkvc_h,g_wkvc_h);cudaGetSymbolAddress((void**)&wkvc_l,g_wkvc_l);
    cudaGetSymbolAddress((void**)&wqc_h, g_wqc_h); cudaGetSymbolAddress((void**)&wqc_l, g_wqc_l);
    cudaGetSymbolAddress((void**)&wkvu_h,g_wkvu_h);cudaGetSymbolAddress((void**)&wkvu_l,g_wkvu_l);
    cudaGetSymbolAddress((void**)&wo_h,  g_wo_h);  cudaGetSymbolAddress((void**)&wo_l,  g_wo_l);
    cudaGetSymbolAddress((void**)&qc,    g_qc);    cudaGetSymbolAddress((void**)&kvcat, g_kvcat);
    cudaGetSymbolAddress((void**)&qcs_h, g_qcs_h); cudaGetSymbolAddress((void**)&qcs_l, g_qcs_l);
    cudaGetSymbolAddress((void**)&kvcs_h,g_kvcs_h);cudaGetSymbolAddress((void**)&kvcs_l,g_kvcs_l);
    cudaGetSymbolAddress((void**)&qup,   g_qup);   cudaGetSymbolAddress((void**)&kvup,  g_kvup);
    cudaGetSymbolAddress((void**)&Qh,    g_Qh);    cudaGetSymbolAddress((void**)&Ql,    g_Ql);
    cudaGetSymbolAddress((void**)&Kh,    g_Kh);    cudaGetSymbolAddress((void**)&Kl,    g_Kl);
    cudaGetSymbolAddress((void**)&Vh,    g_Vh);    cudaGetSymbolAddress((void**)&Vl,    g_Vl);
    cudaGetSymbolAddress((void**)&at_h,  g_at_h);  cudaGetSymbolAddress((void**)&at_l,  g_at_l);
    cudaGetSymbolAddress((void**)&ropeC, g_ropeC); cudaGetSymbolAddress((void**)&ropeS, g_ropeS);

    cudaFuncSetAttribute(gemm_pk, cudaFuncAttributeMaxDynamicSharedMemorySize, GEMM_SMEM);
    cudaFuncSetAttribute(flash_pk, cudaFuncAttributeMaxDynamicSharedMemorySize, FL_BYTES);

    // ---- one fused split of all fp32 inputs ----
    split_all<<<cdiv((int)NP_TOTAL, 256), 256>>>(x, wq_down, wkv_down, wk_rope,
                                                 wq_up, wq_rope, wkv_up, wo);
    rope_table<<<cdiv(2048*32, 256), 256>>>(ropeC, ropeS);

    // ---- down projections ----
    gemm_pk<<<dim3(12, 32), 256, GEMM_SMEM>>>(xs_h, xs_l, wqd_h,  wqd_l,  qc,    4096, 1536, 1024);
    gemm_pk<<<dim3(5,  32), 256, GEMM_SMEM>>>(xs_h, xs_l, wkvc_h, wkvc_l, kvcat, 4096, 576,  1024);

    rmsnorm_split<<<4096, 256>>>(qc,    1536, q_norm_w,  1536, qcs_h,  qcs_l);
    rmsnorm_split<<<4096, 256>>>(kvcat, 576,  kv_norm_w, 512,  kvcs_h, kvcs_l);

    // ---- up projections ----
    gemm_pk<<<dim3(24, 32), 256, GEMM_SMEM>>>(qcs_h,  qcs_l,  wqc_h,  wqc_l,  qup,  4096, 3072, 768);
    gemm_pk<<<dim3(32, 32), 256, GEMM_SMEM>>>(kvcs_h, kvcs_l, wkvu_h, wkvu_l, kvup, 4096, 4096, 256);

    // ---- assemble packed Q/K/V ----
    assemble_q_pk<<<cdiv(32*2048*96, 256), 256>>>(qup, ropeC, ropeS, Qh, Ql);
    assemble_k_pk<<<cdiv(32*2048*96, 256), 256>>>(kvup, kvcat, ropeC, ropeS, Kh, Kl);
    split_v<<<dim3(32, 4, 32), dim3(32, 32)>>>(kvup, Vh, Vl);

    // ---- flash attention ----
    flash_pk<<<dim3(32, 32), 256, FL_BYTES>>>(Qh, Ql, Kh, Kl, Vh, Vl, at_h, at_l);

    // ---- output projection ----
    gemm_pk<<<dim3(16, 32), 256, GEMM_SMEM>>>(at_h, at_l, wo_h, wo_l, out, 4096, 2048, 1024);
}

// round 9
// speedup vs baseline: 2.3527x; 1.0404x over previous
#include <cuda_runtime.h>
#include <math.h>
#include <stdint.h>

// ================= static scratch (no allocations allowed) =================
__device__ uint32_t g_xs_h [4096u*1024], g_xs_l [4096u*1024];   // x split [4096][1024p]
__device__ uint32_t g_wd_h [2112u*1024], g_wd_l [2112u*1024];   // wq_down(1536)|wkv_down(512)|wk_rope(64)
__device__ uint32_t g_wqc_h[3072u*768],  g_wqc_l[3072u*768];    // wq_up(2048) | wq_rope(1024)
__device__ uint32_t g_wkvu_h[4096u*256], g_wkvu_l[4096u*256];   // wkv_up
__device__ uint32_t g_wo_h [2048u*1024], g_wo_l [2048u*1024];   // wo
__device__ float    g_dcat [4096u*2112];                        // q_c(1536) | kv_c(512) | krope(64)
__device__ uint32_t g_qcs_h[4096u*768],  g_qcs_l[4096u*768];    // normed q_c split
__device__ uint32_t g_kvcs_h[4096u*256], g_kvcs_l[4096u*256];   // normed kv_c split
__device__ float    g_qup  [4096ull*3072];                      // qnope(2048) | qpe(1024)
__device__ float    g_kvup [4096ull*4096];                      // per head: k_nope(128)|v(128)
__device__ uint32_t g_Qh[32ull*2048*96], g_Ql[32ull*2048*96];   // Q packed [bh][s][96p]
__device__ uint32_t g_Kh[32ull*2048*96], g_Kl[32ull*2048*96];   // K packed
__device__ uint32_t g_Vh[32ull*128*1024], g_Vl[32ull*128*1024]; // V^T packed [bh][dv][1024 s-pairs]
__device__ uint32_t g_at_h[4096u*1024], g_at_l[4096u*1024];     // attn out packed [4096][1024p]
__device__ float    g_ropeC[2048*32], g_ropeS[2048*32];

// ================= helpers =================
__device__ __forceinline__ void splitpack(float x0, float x1, uint32_t& h, uint32_t& l) {
    uint32_t hb;
    asm("cvt.rn.bf16x2.f32 %0, %1, %2;" : "=r"(hb) : "f"(x1), "f"(x0));
    const float h0 = __uint_as_float(hb << 16);
    const float h1 = __uint_as_float(hb & 0xffff0000u);
    uint32_t lb;
    asm("cvt.rn.bf16x2.f32 %0, %1, %2;" : "=r"(lb) : "f"(x1 - h1), "f"(x0 - h0));
    h = hb; l = lb;
}

__device__ __forceinline__ void mma16(float* d, const uint32_t* a, const uint32_t* b) {
    asm volatile("mma.sync.aligned.m16n8k16.row.col.f32.bf16.bf16.f32 "
        "{%0,%1,%2,%3}, {%4,%5,%6,%7}, {%8,%9}, {%0,%1,%2,%3};"
        : "+f"(d[0]), "+f"(d[1]), "+f"(d[2]), "+f"(d[3])
        : "r"(a[0]), "r"(a[1]), "r"(a[2]), "r"(a[3]), "r"(b[0]), "r"(b[1]));
}

__device__ __forceinline__ uint32_t smem_u32(const void* p) {
    uint32_t a;
    asm("{ .reg .u64 t; cvta.to.shared.u64 t, %1; cvt.u32.u64 %0, t; }" : "=r"(a) : "l"(p));
    return a;
}
__device__ __forceinline__ void ldsm4(uint32_t* r, uint32_t addr) {
    asm volatile("ldmatrix.sync.aligned.m8n8.x4.shared.b16 {%0,%1,%2,%3}, [%4];"
        : "=r"(r[0]), "=r"(r[1]), "=r"(r[2]), "=r"(r[3]) : "r"(addr));
}
__device__ __forceinline__ void ldsm2(uint32_t* r, uint32_t addr) {
    asm volatile("ldmatrix.sync.aligned.m8n8.x2.shared.b16 {%0,%1}, [%2];"
        : "=r"(r[0]), "=r"(r[1]) : "r"(addr));
}
__device__ __forceinline__ void cpa16(uint32_t dst, const void* src) {
    asm volatile("cp.async.cg.shared.global [%0], [%1], 16;" :: "r"(dst), "l"(src));
}
__device__ __forceinline__ void cpa16z(uint32_t dst, const void* src, int ssz) {
    asm volatile("cp.async.cg.shared.global [%0], [%1], 16, %2;" :: "r"(dst), "l"(src), "r"(ssz));
}
__device__ __forceinline__ void cpa_commit() { asm volatile("cp.async.commit_group;" ::: "memory"); }
template<int NN> __device__ __forceinline__ void cpa_wait() {
    asm volatile("cp.async.wait_group %0;" :: "n"(NN) : "memory");
}

// ================= fused split: all fp32 inputs -> packed bf16 hi/lo =================
#define NP_X    4194304
#define NP_WQD  1572864
#define NP_WKVD  524288
#define NP_WKR    65536
#define NP_WQU  1572864
#define NP_WQR   786432
#define NP_WKVU 1048576
#define NP_WO   2097152
#define NP_TOTAL (NP_X+NP_WQD+NP_WKVD+NP_WKR+NP_WQU+NP_WQR+NP_WKVU+NP_WO)

__global__ __launch_bounds__(256) void split_all(
    const float* __restrict__ x,   const float* __restrict__ wqd,
    const float* __restrict__ wkvd,const float* __restrict__ wkr,
    const float* __restrict__ wqu, const float* __restrict__ wqr,
    const float* __restrict__ wkvu,const float* __restrict__ wo) {
    long long i = (long long)blockIdx.x * 256 + threadIdx.x;
    if (i >= NP_TOTAL) return;
    const float2* s; uint32_t *h, *l;
    long long j = i;
    if (j < NP_X)                    { s = (const float2*)x;    h = g_xs_h;                      l = g_xs_l; }
    else if ((j -= NP_X)   < NP_WQD) { s = (const float2*)wqd;  h = g_wd_h;                      l = g_wd_l; }
    else if ((j -= NP_WQD) < NP_WKVD){ s = (const float2*)wkvd; h = g_wd_h + NP_WQD;             l = g_wd_l + NP_WQD; }
    else if ((j -= NP_WKVD)< NP_WKR) { s = (const float2*)wkr;  h = g_wd_h + NP_WQD + NP_WKVD;   l = g_wd_l + NP_WQD + NP_WKVD; }
    else if ((j -= NP_WKR) < NP_WQU) { s = (const float2*)wqu;  h = g_wqc_h;                     l = g_wqc_l; }
    else if ((j -= NP_WQU) < NP_WQR) { s = (const float2*)wqr;  h = g_wqc_h + NP_WQU;            l = g_wqc_l + NP_WQU; }
    else if ((j -= NP_WQR) < NP_WKVU){ s = (const float2*)wkvu; h = g_wkvu_h;                    l = g_wkvu_l; }
    else    { j -= NP_WKVU;            s = (const float2*)wo;   h = g_wo_h;                      l = g_wo_l; }
    const float2 v = s[j];
    splitpack(v.x, v.y, h[j], l[j]);
}

// ================= packed bf16x3 GEMM: C[M,N] = A[M,K] @ B[N,K]^T =================
#define GP 20
#define GEMM_SMEM (2 * 40960)
__global__ __launch_bounds__(256, 2) void gemm_pk(
    const uint32_t* __restrict__ Ahg, const uint32_t* __restrict__ Alg,
    const uint32_t* __restrict__ Bhg, const uint32_t* __restrict__ Blg,
    float* __restrict__ C, int M, int N, int Kp) {
    extern __shared__ uint32_t gsm[];
    const int tid = threadIdx.x, bx = blockIdx.x, by = blockIdx.y;
    const int w = tid >> 5, lane = tid & 31;
    const int wm = (w >> 2) * 64, wn = (w & 3) * 32;
    const int lrow = tid >> 1, lp = (tid & 1) * 8;
    const int rowA = lane & 15, kselA = (lane >> 4) << 2;
    const int rowB = lane & 7,  kselB = ((lane >> 3) & 1) << 2;
    const uint32_t sbase = smem_u32(gsm);

    const uint32_t* Aph = Ahg + (size_t)(by*128 + lrow) * Kp + lp;
    const uint32_t* Apl = Alg + (size_t)(by*128 + lrow) * Kp + lp;
    const int brow = bx*128 + lrow;
    const bool bok = brow < N;
    const int ssz = bok ? 16 : 0;
    const size_t boff = (size_t)(bok ? brow : 0) * Kp + lp;
    const uint32_t* Bph = Bhg + boff;
    const uint32_t* Bpl = Blg + boff;

    float acc[4][4][4];
    #pragma unroll
    for (int mt = 0; mt < 4; mt++)
        #pragma unroll
        for (int nt = 0; nt < 4; nt++)
            #pragma unroll
            for (int i = 0; i < 4; i++) acc[mt][nt][i] = 0.f;

    const uint32_t dfill = (uint32_t)(lrow*GP + lp) * 4u;

    const int NC = Kp >> 4;
    {
        const uint32_t base = sbase + dfill;
        cpa16 (base,          Aph);      cpa16 (base + 16,          Aph + 4);
        cpa16 (base + 10240,  Apl);      cpa16 (base + 10240 + 16,  Apl + 4);
        cpa16z(base + 20480,  Bph, ssz); cpa16z(base + 20480 + 16,  Bph + 4, ssz);
        cpa16z(base + 30720,  Bpl, ssz); cpa16z(base + 30720 + 16,  Bpl + 4, ssz);
        cpa_commit();
    }

    for (int kc = 0; kc < NC; kc++) {
        const int cur = kc & 1;
        if (kc + 1 < NC) {
            const uint32_t base = sbase + (cur ^ 1) * 40960 + dfill;
            const int ko = (kc + 1) * 16;
            cpa16 (base,          Aph + ko);      cpa16 (base + 16,          Aph + ko + 4);
            cpa16 (base + 10240,  Apl + ko);      cpa16 (base + 10240 + 16,  Apl + ko + 4);
            cpa16z(base + 20480,  Bph + ko, ssz); cpa16z(base + 20480 + 16,  Bph + ko + 4, ssz);
            cpa16z(base + 30720,  Bpl + ko, ssz); cpa16z(base + 30720 + 16,  Bpl + ko + 4, ssz);
            cpa_commit();
            cpa_wait<1>();
        } else {
            cpa_wait<0>();
        }
        __syncthreads();

        const uint32_t cb = sbase + cur * 40960;
        #pragma unroll
        for (int stp = 0; stp < 2; stp++) {
            const int p0 = stp * 8;
            uint32_t fbh[4][2], fbl[4][2];
            #pragma unroll
            for (int nt = 0; nt < 4; nt++) {
                const uint32_t ob = cb + 20480 + (uint32_t)((wn + nt*8 + rowB)*GP + p0 + kselB) * 4u;
                ldsm2(fbh[nt], ob);
                ldsm2(fbl[nt], ob + 10240);
            }
            #pragma unroll
            for (int mt = 0; mt < 4; mt++) {
                const uint32_t oa = cb + (uint32_t)((wm + mt*16 + rowA)*GP + p0 + kselA) * 4u;
                uint32_t fah[4], fal[4];
                ldsm4(fah, oa);
                ldsm4(fal, oa + 10240);
                #pragma unroll
                for (int nt = 0; nt < 4; nt++) mma16(acc[mt][nt], fah, fbh[nt]);
                #pragma unroll
                for (int nt = 0; nt < 4; nt++) mma16(acc[mt][nt], fah, fbl[nt]);
                #pragma unroll
                for (int nt = 0; nt < 4; nt++) mma16(acc[mt][nt], fal, fbh[nt]);
            }
        }
        __syncthreads();
    }

    const int g = lane >> 2, t = lane & 3;
    #pragma unroll
    for (int mt = 0; mt < 4; mt++) {
        const int row = by*128 + wm + mt*16 + g;
        #pragma unroll
        for (int nt = 0; nt < 4; nt++) {
            const int col = bx*128 + wn + nt*8 + 2*t;
            if (col < N) {
                float* cp = C + (size_t)row * N + col;
                *(float2*)cp                   = make_float2(acc[mt][nt][0], acc[mt][nt][1]);
                *(float2*)(cp + 8 * (size_t)N) = make_float2(acc[mt][nt][2], acc[mt][nt][3]);
            }
        }
    }
}

// ================= RMSNorm + split =================
__global__ __launch_bounds__(256) void rmsnorm_split(const float* __restrict__ x, int stride,
                                                     const float* __restrict__ w, int cols,
                                                     uint32_t* __restrict__ oh,
                                                     uint32_t* __restrict__ ol) {
    const int row = blockIdx.x;
    const float* xr = x + (size_t)row * stride;
    const int tid = threadIdx.x;
    float s = 0.f;
    const float4* x4 = (const float4*)xr;
    for (int c = tid; c < (cols >> 2); c += 256) {
        const float4 v = x4[c];
        s = fmaf(v.x, v.x, s); s = fmaf(v.y, v.y, s);
        s = fmaf(v.z, v.z, s); s = fmaf(v.w, v.w, s);
    }
    __shared__ float red[256];
    red[tid] = s; __syncthreads();
    for (int st = 128; st > 0; st >>= 1) {
        if (tid < st) red[tid] += red[tid + st];
        __syncthreads();
    }
    const float inv = rsqrtf(red[0] / (float)cols + 1e-6f);
    const int pairs = cols >> 1;
    const float2* x2 = (const float2*)xr;
    const float2* w2 = (const float2*)w;
    for (int p = tid; p < pairs; p += 256) {
        const float2 xv = x2[p];
        const float2 wv = w2[p];
        splitpack(xv.x * inv * wv.x, xv.y * inv * wv.y,
                  oh[(size_t)row * pairs + p], ol[(size_t)row * pairs + p]);
    }
}

// ================= RoPE table =================
__global__ void rope_table(float* __restrict__ cosT, float* __restrict__ sinT) {
    const int idx = blockIdx.x * 256 + threadIdx.x;
    if (idx >= 2048 * 32) return;
    const int s = idx >> 5, jp = idx & 31;
    const float inv = powf(10000.0f, -(float)(2*jp) * (1.0f/64.0f));
    float sn, cs; sincosf((float)s * inv, &sn, &cs);
    cosT[idx] = cs; sinT[idx] = sn;
}

// ================= assemble Q packed =================
__global__ __launch_bounds__(256) void assemble_q_pk(const float* __restrict__ qup,
        const float* __restrict__ cosT, const float* __restrict__ sinT,
        uint32_t* __restrict__ Qh, uint32_t* __restrict__ Ql) {
    const int idx = blockIdx.x * 256 + threadIdx.x;
    if (idx >= 32*2048*96) return;
    const int p  = idx % 96;
    const int ts = idx / 96;
    const int s  = ts & 2047;
    const int bh = ts >> 11;
    const int b = bh >> 4, h = bh & 15;
    const int m = b*2048 + s;
    float x0, x1;
    if (p < 64) {
        const float* src = qup + (size_t)m*3072 + h*128 + 2*p;
        x0 = src[0]; x1 = src[1];
    } else {
        const int jp = p - 64;
        const float* src = qup + (size_t)m*3072 + 2048 + h*64 + 2*jp;
        const float c = cosT[s*32 + jp], sn = sinT[s*32 + jp];
        const float a = src[0], bb = src[1];
        x0 = a*c - bb*sn;
        x1 = a*sn + bb*c;
    }
    splitpack(x0, x1, Qh[idx], Ql[idx]);
}

// ================= assemble K packed (krope read from dcat at col 2048) =================
__global__ __launch_bounds__(256) void assemble_k_pk(const float* __restrict__ kvup,
        const float* __restrict__ dcat,
        const float* __restrict__ cosT, const float* __restrict__ sinT,
        uint32_t* __restrict__ Kh, uint32_t* __restrict__ Kl) {
    const int idx = blockIdx.x * 256 + threadIdx.x;
    if (idx >= 32*2048*96) return;
    const int p  = idx % 96;
    const int ts = idx / 96;
    const int s  = ts & 2047;
    const int bh = ts >> 11;
    const int b = bh >> 4, h = bh & 15;
    const int m = b*2048 + s;
    float x0, x1;
    if (p < 64) {
        const float* src = kvup + (size_t)m*4096 + h*256 + 2*p;
        x0 = src[0]; x1 = src[1];
    } else {
        const int jp = p - 64;
        const float* src = dcat + (size_t)m*2112 + 2048 + 2*jp;
        const float c = cosT[s*32 + jp], sn = sinT[s*32 + jp];
        const float a = src[0], bb = src[1];
        x0 = a*c - bb*sn;
        x1 = a*sn + bb*c;
    }
    splitpack(x0, x1, Kh[idx], Kl[idx]);
}

// ================= V transpose + split =================
__global__ void split_v(const float* __restrict__ kvup,
                        uint32_t* __restrict__ Vh, uint32_t* __restrict__ Vl) {
    __shared__ float tile[64][33];
    const int bh = blockIdx.z, b = bh >> 4, h = bh & 15;
    const int s0 = blockIdx.x * 64, dv0 = blockIdx.y * 32;
    const int tx = threadIdx.x, ty = threadIdx.y;
    #pragma unroll
    for (int half = 0; half < 2; half++) {
        const int s = s0 + half*32 + ty;
        tile[half*32 + ty][tx] =
            kvup[((size_t)(b*2048 + s))*4096 + h*256 + 128 + dv0 + tx];
    }
    __syncthreads();
    const float x0 = tile[2*tx][ty], x1 = tile[2*tx + 1][ty];
    uint32_t hh, ll; splitpack(x0, x1, hh, ll);
    const size_t o = ((size_t)bh*128 + dv0 + ty)*1024 + (s0 >> 1) + tx;
    Vh[o] = hh; Vl[o] = ll;
}

// ================= flash attention (causal, packed bf16x3, ldmatrix frags) =================
#define FQP 100
#define FVP 36
#define FPP 36
#define FL_BYTES ((4*64*FQP + 2*128*FVP + 2*64*FPP + 2*128) * 4)
__global__ __launch_bounds__(256) void flash_pk(
    const uint32_t* __restrict__ Qhg, const uint32_t* __restrict__ Qlg,
    const uint32_t* __restrict__ Khg, const uint32_t* __restrict__ Klg,
    const uint32_t* __restrict__ Vhg, const uint32_t* __restrict__ Vlg,
    uint32_t* __restrict__ Oh, uint32_t* __restrict__ Ol) {
    extern __shared__ uint32_t sw[];
    uint32_t* Qsh = sw;
    uint32_t* Qsl = Qsh + 64*FQP;
    uint32_t* Ksh = Qsl + 64*FQP;
    uint32_t* Ksl = Ksh + 64*FQP;
    uint32_t* Vsh = Ksl + 64*FQP;
    uint32_t* Vsl = Vsh + 128*FVP;
    uint32_t* Psh = Vsl + 128*FVP;
    uint32_t* Psl = Psh + 64*FPP;
    float* sMax = (float*)(Psl + 64*FPP);
    float* sSum = sMax + 128;

    const int qt = 31 - blockIdx.x;
    const int bh = blockIdx.y;
    const int b = bh >> 4, h = bh & 15;
    const int tid = threadIdx.x;
    const int w = tid >> 5, lane = tid & 31;
    const int qg = w & 3, nhalf = w >> 2;
    const int g = lane >> 2, t = lane & 3;
    const int qrow = qg * 16;

    const int rowA = lane & 15, kselA = (lane >> 4) << 2;
    const int rowB = lane & 7,  kselB = ((lane >> 3) & 1) << 2;
    const uint32_t aQh = smem_u32(Qsh), aQl = smem_u32(Qsl);
    const uint32_t aKh = smem_u32(Ksh), aKl = smem_u32(Ksl);
    const uint32_t aVh = smem_u32(Vsh), aVl = smem_u32(Vsl);
    const uint32_t aPh = smem_u32(Psh), aPl = smem_u32(Psl);

    {
        const size_t base = ((size_t)bh*2048 + qt*64) * 96;
        for (int i = tid; i < 64*24; i += 256) {
            const int r = i / 24, c = i % 24;
            *(uint4*)&Qsh[r*FQP + c*4] = *(const uint4*)(Qhg + base + (size_t)r*96 + c*4);
            *(uint4*)&Qsl[r*FQP + c*4] = *(const uint4*)(Qlg + base + (size_t)r*96 + c*4);
        }
    }

    float m0 = -INFINITY, m1 = -INFINITY, l0 = 0.f, l1 = 0.f;
    float o[8][4];
    #pragma unroll
    for (int nt = 0; nt < 8; nt++)
        #pragma unroll
        for (int e = 0; e < 4; e++) o[nt][e] = 0.f;

    const float scale = 0.07216878364870323f;   // 1/sqrt(192)

    for (int kt = 0; kt <= qt; kt++) {
        __syncthreads();
        {
            const size_t base = ((size_t)bh*2048 + kt*64) * 96;
            for (int i = tid; i < 64*24; i += 256) {
                const int r = i / 24, c = i % 24;
                *(uint4*)&Ksh[r*FQP + c*4] = *(const uint4*)(Khg + base + (size_t)r*96 + c*4);
                *(uint4*)&Ksl[r*FQP + c*4] = *(const uint4*)(Klg + base + (size_t)r*96 + c*4);
            }
            const size_t vb = (size_t)bh*128*1024 + kt*32;
            for (int i = tid; i < 128*8; i += 256) {
                const int r = i / 8, c = i % 8;
                *(uint4*)&Vsh[r*FVP + c*4] = *(const uint4*)(Vhg + vb + (size_t)r*1024 + c*4);
                *(uint4*)&Vsl[r*FVP + c*4] = *(const uint4*)(Vlg + vb + (size_t)r*1024 + c*4);
            }
        }
        __syncthreads();

        float sa[4][4];
        #pragma unroll
        for (int nt = 0; nt < 4; nt++)
            #pragma unroll
            for (int e = 0; e < 4; e++) sa[nt][e] = 0.f;

        #pragma unroll 4
        for (int st = 0; st < 12; st++) {
            const int p0 = st * 8;
            const uint32_t oq = (uint32_t)((qrow + rowA)*FQP + p0 + kselA) * 4u;
            uint32_t fah[4], fal[4];
            ldsm4(fah, aQh + oq);
            ldsm4(fal, aQl + oq);
            uint32_t fbh[4][2], fbl[4][2];
            #pragma unroll
            for (int nt = 0; nt < 4; nt++) {
                const uint32_t ok = (uint32_t)((nhalf*32 + nt*8 + rowB)*FQP + p0 + kselB) * 4u;
                ldsm2(fbh[nt], aKh + ok);
                ldsm2(fbl[nt], aKl + ok);
            }
            #pragma unroll
            for (int nt = 0; nt < 4; nt++) mma16(sa[nt], fah, fbh[nt]);
            #pragma unroll
            for (int nt = 0; nt < 4; nt++) mma16(sa[nt], fah, fbl[nt]);
            #pragma unroll
            for (int nt = 0; nt < 4; nt++) mma16(sa[nt], fal, fbh[nt]);
        }

        const bool diag = (kt == qt);
        float pm0 = -INFINITY, pm1 = -INFINITY;
        #pragma unroll
        for (int nt = 0; nt < 4; nt++) {
            const int colb = nhalf*32 + nt*8 + 2*t;
            #pragma unroll
            for (int e = 0; e < 4; e++) {
                float v = sa[nt][e] * scale;
                if (diag) {
                    const int col = colb + (e & 1);
                    const int row = qrow + g + ((e >> 1) << 3);
                    if (col > row) v = -INFINITY;
                }
                sa[nt][e] = v;
                if (e < 2) pm0 = fmaxf(pm0, v); else pm1 = fmaxf(pm1, v);
            }
        }
        pm0 = fmaxf(pm0, __shfl_xor_sync(0xffffffffu, pm0, 1));
        pm0 = fmaxf(pm0, __shfl_xor_sync(0xffffffffu, pm0, 2));
        pm1 = fmaxf(pm1, __shfl_xor_sync(0xffffffffu, pm1, 1));
        pm1 = fmaxf(pm1, __shfl_xor_sync(0xffffffffu, pm1, 2));
        if (t == 0) {
            sMax[nhalf*64 + qrow + g]     = pm0;
            sMax[nhalf*64 + qrow + g + 8] = pm1;
        }
        __syncthreads();
        const float mn0 = fmaxf(m0, fmaxf(pm0, sMax[(1 - nhalf)*64 + qrow + g]));
        const float mn1 = fmaxf(m1, fmaxf(pm1, sMax[(1 - nhalf)*64 + qrow + g + 8]));
        const float al0 = __expf(m0 - mn0);
        const float al1 = __expf(m1 - mn1);

        float ps0 = 0.f, ps1 = 0.f;
        #pragma unroll
        for (int nt = 0; nt < 4; nt++) {
            const int pidx = nhalf*16 + nt*4 + t;
            const float p0v = __expf(sa[nt][0] - mn0);
            const float p1v = __expf(sa[nt][1] - mn0);
            const float p2v = __expf(sa[nt][2] - mn1);
            const float p3v = __expf(sa[nt][3] - mn1);
            ps0 += p0v + p1v; ps1 += p2v + p3v;
            splitpack(p0v, p1v, Psh[(qrow + g)*FPP + pidx],     Psl[(qrow + g)*FPP + pidx]);
            splitpack(p2v, p3v, Psh[(qrow + g + 8)*FPP + pidx], Psl[(qrow + g + 8)*FPP + pidx]);
        }
        ps0 += __shfl_xor_sync(0xffffffffu, ps0, 1);
        ps0 += __shfl_xor_sync(0xffffffffu, ps0, 2);
        ps1 += __shfl_xor_sync(0xffffffffu, ps1, 1);
        ps1 += __shfl_xor_sync(0xffffffffu, ps1, 2);
        if (t == 0) {
            sSum[nhalf*64 + qrow + g]     = ps0;
            sSum[nhalf*64 + qrow + g + 8] = ps1;
        }
        __syncthreads();
        l0 = l0 * al0 + ps0 + sSum[(1 - nhalf)*64 + qrow + g];
        l1 = l1 * al1 + ps1 + sSum[(1 - nhalf)*64 + qrow + g + 8];
        m0 = mn0; m1 = mn1;

        #pragma unroll
        for (int nt = 0; nt < 8; nt++) {
            o[nt][0] *= al0; o[nt][1] *= al0;
            o[nt][2] *= al1; o[nt][3] *= al1;
        }

        #pragma unroll
        for (int st = 0; st < 4; st++) {
            const int p0 = st * 8;
            const uint32_t op = (uint32_t)((qrow + rowA)*FPP + p0 + kselA) * 4u;
            uint32_t fah[4], fal[4];
            ldsm4(fah, aPh + op);
            ldsm4(fal, aPl + op);
            #pragma unroll
            for (int hv = 0; hv < 2; hv++) {
                uint32_t fbh[4][2], fbl[4][2];
                #pragma unroll
                for (int n4 = 0; n4 < 4; n4++) {
                    const int nt = hv*4 + n4;
                    const uint32_t ov = (uint32_t)((nhalf*64 + nt*8 + rowB)*FVP + p0 + kselB) * 4u;
                    ldsm2(fbh[n4], aVh + ov);
                    ldsm2(fbl[n4], aVl + ov);
                }
                #pragma unroll
                for (int n4 = 0; n4 < 4; n4++) mma16(o[hv*4 + n4], fah, fbh[n4]);
                #pragma unroll
                for (int n4 = 0; n4 < 4; n4++) mma16(o[hv*4 + n4], fah, fbl[n4]);
                #pragma unroll
                for (int n4 = 0; n4 < 4; n4++) mma16(o[hv*4 + n4], fal, fbh[n4]);
            }
        }
    }

    const float il0 = 1.f / l0, il1 = 1.f / l1;
    const int row0 = b*2048 + qt*64 + qrow + g;
    #pragma unroll
    for (int nt = 0; nt < 8; nt++) {
        const int cp = h*64 + nhalf*32 + nt*4 + t;
        splitpack(o[nt][0]*il0, o[nt][1]*il0, Oh[(size_t)row0*1024 + cp],       Ol[(size_t)row0*1024 + cp]);
        splitpack(o[nt][2]*il1, o[nt][3]*il1, Oh[(size_t)(row0 + 8)*1024 + cp], Ol[(size_t)(row0 + 8)*1024 + cp]);
    }
}

// ================= host orchestration =================
static inline int cdiv(int a, int b) { return (a + b - 1) / b; }

extern "C" void kernel_launch(void* const* d_in, const int* in_sizes, int n_in,
                              void* d_out, int out_size) {
    const float* x        = (const float*)d_in[0];
    const float* wq_down  = (const float*)d_in[1];
    const float* q_norm_w = (const float*)d_in[2];
    const float* wq_up    = (const float*)d_in[3];
    const float* wq_rope  = (const float*)d_in[4];
    const float* wkv_down = (const float*)d_in[5];
    const float* kv_norm_w= (const float*)d_in[6];
    const float* wkv_up   = (const float*)d_in[7];
    const float* wk_rope  = (const float*)d_in[8];
    const float* wo       = (const float*)d_in[9];
    float* out = (float*)d_out;

    uint32_t *xs_h,*xs_l,*wd_h,*wd_l,*wqc_h,*wqc_l,*wkvu_h,*wkvu_l,*wo_h,*wo_l;
    uint32_t *qcs_h,*qcs_l,*kvcs_h,*kvcs_l,*Qh,*Ql,*Kh,*Kl,*Vh,*Vl,*at_h,*at_l;
    float *dcat,*qup,*kvup,*ropeC,*ropeS;
    cudaGetSymbolAddress((void**)&xs_h,  g_xs_h);  cudaGetSymbolAddress((void**)&xs_l,  g_xs_l);
    cudaGetSymbolAddress((void**)&wd_h,  g_wd_h);  cudaGetSymbolAddress((void**)&wd_l,  g_wd_l);
    cudaGetSymbolAddress((void**)&wqc_h, g_wqc_h); cudaGetSymbolAddress((void**)&wqc_l, g_wqc_l);
    cudaGetSymbolAddress((void**)&wkvu_h,g_wkvu_h);cudaGetSymbolAddress((void**)&wkvu_l,g_wkvu_l);
    cudaGetSymbolAddress((void**)&wo_h,  g_wo_h);  cudaGetSymbolAddress((void**)&wo_l,  g_wo_l);
    cudaGetSymbolAddress((void**)&dcat,  g_dcat);
    cudaGetSymbolAddress((void**)&qcs_h, g_qcs_h); cudaGetSymbolAddress((void**)&qcs_l, g_qcs_l);
    cudaGetSymbolAddress((void**)&kvcs_h,g_kvcs_h);cudaGetSymbolAddress((void**)&kvcs_l,g_kvcs_l);
    cudaGetSymbolAddress((void**)&qup,   g_qup);   cudaGetSymbolAddress((void**)&kvup,  g_kvup);
    cudaGetSymbolAddress((void**)&Qh,    g_Qh);    cudaGetSymbolAddress((void**)&Ql,    g_Ql);
    cudaGetSymbolAddress((void**)&Kh,    g_Kh);    cudaGetSymbolAddress((void**)&Kl,    g_Kl);
    cudaGetSymbolAddress((void**)&Vh,    g_Vh);    cudaGetSymbolAddress((void**)&Vl,    g_Vl);
    cudaGetSymbolAddress((void**)&at_h,  g_at_h);  cudaGetSymbolAddress((void**)&at_l,  g_at_l);
    cudaGetSymbolAddress((void**)&ropeC, g_ropeC); cudaGetSymbolAddress((void**)&ropeS, g_ropeS);

    cudaFuncSetAttribute(gemm_pk, cudaFuncAttributeMaxDynamicSharedMemorySize, GEMM_SMEM);
    cudaFuncSetAttribute(flash_pk, cudaFuncAttributeMaxDynamicSharedMemorySize, FL_BYTES);

    // ---- one fused split of all fp32 inputs ----
    split_all<<<cdiv((int)NP_TOTAL, 256), 256>>>(x, wq_down, wkv_down, wk_rope,
                                                 wq_up, wq_rope, wkv_up, wo);
    rope_table<<<cdiv(2048*32, 256), 256>>>(ropeC, ropeS);

    // ---- merged down projection: C[4096][2112] = x @ [wq_down|wkv_down|wk_rope]^T ----
    gemm_pk<<<dim3(17, 32), 256, GEMM_SMEM>>>(xs_h, xs_l, wd_h, wd_l, dcat, 4096, 2112, 1024);

    rmsnorm_split<<<4096, 256>>>(dcat,        2112, q_norm_w,  1536, qcs_h,  qcs_l);
    rmsnorm_split<<<4096, 256>>>(dcat + 1536, 2112, kv_norm_w, 512,  kvcs_h, kvcs_l);

    // ---- up projections ----
    gemm_pk<<<dim3(24, 32), 256, GEMM_SMEM>>>(qcs_h,  qcs_l,  wqc_h,  wqc_l,  qup,  4096, 3072, 768);
    gemm_pk<<<dim3(32, 32), 256, GEMM_SMEM>>>(kvcs_h, kvcs_l, wkvu_h, wkvu_l, kvup, 4096, 4096, 256);

    // ---- assemble packed Q/K/V ----
    assemble_q_pk<<<cdiv(32*2048*96, 256), 256>>>(qup, ropeC, ropeS, Qh, Ql);
    assemble_k_pk<<<cdiv(32*2048*96, 256), 256>>>(kvup, dcat, ropeC, ropeS, Kh, Kl);
    split_v<<<dim3(32, 4, 32), dim3(32, 32)>>>(kvup, Vh, Vl);

    // ---- flash attention ----
    flash_pk<<<dim3(32, 32), 256, FL_BYTES>>>(Qh, Ql, Kh, Kl, Vh, Vl, at_h, at_l);

    // ---- output projection ----
    gemm_pk<<<dim3(16, 32), 256, GEMM_SMEM>>>(at_h, at_l, wo_h, wo_l, out, 4096, 2048, 1024);
}

// round 10
// speedup vs baseline: 2.3581x; 1.0023x over previous
#include <cuda_runtime.h>
#include <math.h>
#include <stdint.h>

// ================= static scratch (no allocations allowed) =================
__device__ uint32_t g_xs_h [4096u*1024], g_xs_l [4096u*1024];   // x split [4096][1024p]
__device__ uint32_t g_wd_h [2112u*1024], g_wd_l [2112u*1024];   // wq_down(1536)|wkv_down(512)|wk_rope(64)
__device__ uint32_t g_wqc_h[3072u*768],  g_wqc_l[3072u*768];    // wq_up(2048) | wq_rope(1024)
__device__ uint32_t g_wkvu_h[4096u*256], g_wkvu_l[4096u*256];   // wkv_up
__device__ uint32_t g_wo_h [2048u*1024], g_wo_l [2048u*1024];   // wo
__device__ float    g_dcat [4096u*2112];                        // q_c(1536) | kv_c(512) | krope(64)
__device__ uint32_t g_qcs_h[4096u*768],  g_qcs_l[4096u*768];    // normed q_c split
__device__ uint32_t g_kvcs_h[4096u*256], g_kvcs_l[4096u*256];   // normed kv_c split
__device__ float    g_qup  [4096ull*3072];                      // qnope(2048) | qpe(1024)
__device__ float    g_kvup [4096ull*4096];                      // per head: k_nope(128)|v(128)
__device__ uint32_t g_Qh[32ull*2048*96], g_Ql[32ull*2048*96];   // Q packed [bh][s][96p]
__device__ uint32_t g_Kh[32ull*2048*96], g_Kl[32ull*2048*96];   // K packed
__device__ uint32_t g_Vh[32ull*128*1024], g_Vl[32ull*128*1024]; // V^T packed [bh][dv][1024 s-pairs]
__device__ uint32_t g_at_h[4096u*1024], g_at_l[4096u*1024];     // attn out packed [4096][1024p]
__device__ float    g_ropeC[2048*32], g_ropeS[2048*32];

// ================= helpers =================
__device__ __forceinline__ void splitpack(float x0, float x1, uint32_t& h, uint32_t& l) {
    uint32_t hb;
    asm("cvt.rn.bf16x2.f32 %0, %1, %2;" : "=r"(hb) : "f"(x1), "f"(x0));
    const float h0 = __uint_as_float(hb << 16);
    const float h1 = __uint_as_float(hb & 0xffff0000u);
    uint32_t lb;
    asm("cvt.rn.bf16x2.f32 %0, %1, %2;" : "=r"(lb) : "f"(x1 - h1), "f"(x0 - h0));
    h = hb; l = lb;
}

__device__ __forceinline__ void mma16(float* d, const uint32_t* a, const uint32_t* b) {
    asm volatile("mma.sync.aligned.m16n8k16.row.col.f32.bf16.bf16.f32 "
        "{%0,%1,%2,%3}, {%4,%5,%6,%7}, {%8,%9}, {%0,%1,%2,%3};"
        : "+f"(d[0]), "+f"(d[1]), "+f"(d[2]), "+f"(d[3])
        : "r"(a[0]), "r"(a[1]), "r"(a[2]), "r"(a[3]), "r"(b[0]), "r"(b[1]));
}

__device__ __forceinline__ uint32_t smem_u32(const void* p) {
    uint32_t a;
    asm("{ .reg .u64 t; cvta.to.shared.u64 t, %1; cvt.u32.u64 %0, t; }" : "=r"(a) : "l"(p));
    return a;
}
__device__ __forceinline__ void ldsm4(uint32_t* r, uint32_t addr) {
    asm volatile("ldmatrix.sync.aligned.m8n8.x4.shared.b16 {%0,%1,%2,%3}, [%4];"
        : "=r"(r[0]), "=r"(r[1]), "=r"(r[2]), "=r"(r[3]) : "r"(addr));
}
__device__ __forceinline__ void ldsm2(uint32_t* r, uint32_t addr) {
    asm volatile("ldmatrix.sync.aligned.m8n8.x2.shared.b16 {%0,%1}, [%2];"
        : "=r"(r[0]), "=r"(r[1]) : "r"(addr));
}
__device__ __forceinline__ void cpa16(uint32_t dst, const void* src) {
    asm volatile("cp.async.cg.shared.global [%0], [%1], 16;" :: "r"(dst), "l"(src));
}
__device__ __forceinline__ void cpa16z(uint32_t dst, const void* src, int ssz) {
    asm volatile("cp.async.cg.shared.global [%0], [%1], 16, %2;" :: "r"(dst), "l"(src), "r"(ssz));
}
__device__ __forceinline__ void cpa_commit() { asm volatile("cp.async.commit_group;" ::: "memory"); }
template<int NN> __device__ __forceinline__ void cpa_wait() {
    asm volatile("cp.async.wait_group %0;" :: "n"(NN) : "memory");
}

// ================= fused split: all fp32 inputs -> packed bf16 hi/lo =================
#define NP_X    4194304
#define NP_WQD  1572864
#define NP_WKVD  524288
#define NP_WKR    65536
#define NP_WQU  1572864
#define NP_WQR   786432
#define NP_WKVU 1048576
#define NP_WO   2097152
#define NP_TOTAL (NP_X+NP_WQD+NP_WKVD+NP_WKR+NP_WQU+NP_WQR+NP_WKVU+NP_WO)

__global__ __launch_bounds__(256) void split_all(
    const float* __restrict__ x,   const float* __restrict__ wqd,
    const float* __restrict__ wkvd,const float* __restrict__ wkr,
    const float* __restrict__ wqu, const float* __restrict__ wqr,
    const float* __restrict__ wkvu,const float* __restrict__ wo) {
    long long i = (long long)blockIdx.x * 256 + threadIdx.x;
    if (i >= NP_TOTAL) return;
    const float2* s; uint32_t *h, *l;
    long long j = i;
    if (j < NP_X)                    { s = (const float2*)x;    h = g_xs_h;                      l = g_xs_l; }
    else if ((j -= NP_X)   < NP_WQD) { s = (const float2*)wqd;  h = g_wd_h;                      l = g_wd_l; }
    else if ((j -= NP_WQD) < NP_WKVD){ s = (const float2*)wkvd; h = g_wd_h + NP_WQD;             l = g_wd_l + NP_WQD; }
    else if ((j -= NP_WKVD)< NP_WKR) { s = (const float2*)wkr;  h = g_wd_h + NP_WQD + NP_WKVD;   l = g_wd_l + NP_WQD + NP_WKVD; }
    else if ((j -= NP_WKR) < NP_WQU) { s = (const float2*)wqu;  h = g_wqc_h;                     l = g_wqc_l; }
    else if ((j -= NP_WQU) < NP_WQR) { s = (const float2*)wqr;  h = g_wqc_h + NP_WQU;            l = g_wqc_l + NP_WQU; }
    else if ((j -= NP_WQR) < NP_WKVU){ s = (const float2*)wkvu; h = g_wkvu_h;                    l = g_wkvu_l; }
    else    { j -= NP_WKVU;            s = (const float2*)wo;   h = g_wo_h;                      l = g_wo_l; }
    const float2 v = s[j];
    splitpack(v.x, v.y, h[j], l[j]);
}

// ================= packed bf16x3 GEMM: C[M,N] = A[M,K] @ B[N,K]^T =================
#define GP 20
#define GEMM_SMEM (2 * 40960)
__global__ __launch_bounds__(256, 2) void gemm_pk(
    const uint32_t* __restrict__ Ahg, const uint32_t* __restrict__ Alg,
    const uint32_t* __restrict__ Bhg, const uint32_t* __restrict__ Blg,
    float* __restrict__ C, int M, int N, int Kp) {
    extern __shared__ uint32_t gsm[];
    const int tid = threadIdx.x, bx = blockIdx.x, by = blockIdx.y;
    const int w = tid >> 5, lane = tid & 31;
    const int wm = (w >> 2) * 64, wn = (w & 3) * 32;
    const int lrow = tid >> 1, lp = (tid & 1) * 8;
    const int rowA = lane & 15, kselA = (lane >> 4) << 2;
    const int rowB = lane & 7,  kselB = ((lane >> 3) & 1) << 2;
    const uint32_t sbase = smem_u32(gsm);

    const uint32_t* Aph = Ahg + (size_t)(by*128 + lrow) * Kp + lp;
    const uint32_t* Apl = Alg + (size_t)(by*128 + lrow) * Kp + lp;
    const int brow = bx*128 + lrow;
    const bool bok = brow < N;
    const int ssz = bok ? 16 : 0;
    const size_t boff = (size_t)(bok ? brow : 0) * Kp + lp;
    const uint32_t* Bph = Bhg + boff;
    const uint32_t* Bpl = Blg + boff;

    float acc[4][4][4];
    #pragma unroll
    for (int mt = 0; mt < 4; mt++)
        #pragma unroll
        for (int nt = 0; nt < 4; nt++)
            #pragma unroll
            for (int i = 0; i < 4; i++) acc[mt][nt][i] = 0.f;

    const uint32_t dfill = (uint32_t)(lrow*GP + lp) * 4u;

    const int NC = Kp >> 4;
    {
        const uint32_t base = sbase + dfill;
        cpa16 (base,          Aph);      cpa16 (base + 16,          Aph + 4);
        cpa16 (base + 10240,  Apl);      cpa16 (base + 10240 + 16,  Apl + 4);
        cpa16z(base + 20480,  Bph, ssz); cpa16z(base + 20480 + 16,  Bph + 4, ssz);
        cpa16z(base + 30720,  Bpl, ssz); cpa16z(base + 30720 + 16,  Bpl + 4, ssz);
        cpa_commit();
    }

    for (int kc = 0; kc < NC; kc++) {
        const int cur = kc & 1;
        if (kc + 1 < NC) {
            const uint32_t base = sbase + (cur ^ 1) * 40960 + dfill;
            const int ko = (kc + 1) * 16;
            cpa16 (base,          Aph + ko);      cpa16 (base + 16,          Aph + ko + 4);
            cpa16 (base + 10240,  Apl + ko);      cpa16 (base + 10240 + 16,  Apl + ko + 4);
            cpa16z(base + 20480,  Bph + ko, ssz); cpa16z(base + 20480 + 16,  Bph + ko + 4, ssz);
            cpa16z(base + 30720,  Bpl + ko, ssz); cpa16z(base + 30720 + 16,  Bpl + ko + 4, ssz);
            cpa_commit();
            cpa_wait<1>();
        } else {
            cpa_wait<0>();
        }
        __syncthreads();

        const uint32_t cb = sbase + cur * 40960;
        #pragma unroll
        for (int stp = 0; stp < 2; stp++) {
            const int p0 = stp * 8;
            uint32_t fbh[4][2], fbl[4][2];
            #pragma unroll
            for (int nt = 0; nt < 4; nt++) {
                const uint32_t ob = cb + 20480 + (uint32_t)((wn + nt*8 + rowB)*GP + p0 + kselB) * 4u;
                ldsm2(fbh[nt], ob);
                ldsm2(fbl[nt], ob + 10240);
            }
            #pragma unroll
            for (int mt = 0; mt < 4; mt++) {
                const uint32_t oa = cb + (uint32_t)((wm + mt*16 + rowA)*GP + p0 + kselA) * 4u;
                uint32_t fah[4], fal[4];
                ldsm4(fah, oa);
                ldsm4(fal, oa + 10240);
                #pragma unroll
                for (int nt = 0; nt < 4; nt++) mma16(acc[mt][nt], fah, fbh[nt]);
                #pragma unroll
                for (int nt = 0; nt < 4; nt++) mma16(acc[mt][nt], fah, fbl[nt]);
                #pragma unroll
                for (int nt = 0; nt < 4; nt++) mma16(acc[mt][nt], fal, fbh[nt]);
            }
        }
        __syncthreads();
    }

    const int g = lane >> 2, t = lane & 3;
    #pragma unroll
    for (int mt = 0; mt < 4; mt++) {
        const int row = by*128 + wm + mt*16 + g;
        #pragma unroll
        for (int nt = 0; nt < 4; nt++) {
            const int col = bx*128 + wn + nt*8 + 2*t;
            if (col < N) {
                float* cp = C + (size_t)row * N + col;
                *(float2*)cp                   = make_float2(acc[mt][nt][0], acc[mt][nt][1]);
                *(float2*)(cp + 8 * (size_t)N) = make_float2(acc[mt][nt][2], acc[mt][nt][3]);
            }
        }
    }
}

// ================= RMSNorm + split =================
__global__ __launch_bounds__(256) void rmsnorm_split(const float* __restrict__ x, int stride,
                                                     const float* __restrict__ w, int cols,
                                                     uint32_t* __restrict__ oh,
                                                     uint32_t* __restrict__ ol) {
    const int row = blockIdx.x;
    const float* xr = x + (size_t)row * stride;
    const int tid = threadIdx.x;
    float s = 0.f;
    const float4* x4 = (const float4*)xr;
    for (int c = tid; c < (cols >> 2); c += 256) {
        const float4 v = x4[c];
        s = fmaf(v.x, v.x, s); s = fmaf(v.y, v.y, s);
        s = fmaf(v.z, v.z, s); s = fmaf(v.w, v.w, s);
    }
    __shared__ float red[256];
    red[tid] = s; __syncthreads();
    for (int st = 128; st > 0; st >>= 1) {
        if (tid < st) red[tid] += red[tid + st];
        __syncthreads();
    }
    const float inv = rsqrtf(red[0] / (float)cols + 1e-6f);
    const int pairs = cols >> 1;
    const float2* x2 = (const float2*)xr;
    const float2* w2 = (const float2*)w;
    for (int p = tid; p < pairs; p += 256) {
        const float2 xv = x2[p];
        const float2 wv = w2[p];
        splitpack(xv.x * inv * wv.x, xv.y * inv * wv.y,
                  oh[(size_t)row * pairs + p], ol[(size_t)row * pairs + p]);
    }
}

// ================= RoPE table =================
__global__ void rope_table(float* __restrict__ cosT, float* __restrict__ sinT) {
    const int idx = blockIdx.x * 256 + threadIdx.x;
    if (idx >= 2048 * 32) return;
    const int s = idx >> 5, jp = idx & 31;
    const float inv = powf(10000.0f, -(float)(2*jp) * (1.0f/64.0f));
    float sn, cs; sincosf((float)s * inv, &sn, &cs);
    cosT[idx] = cs; sinT[idx] = sn;
}

// ================= assemble Q packed =================
__global__ __launch_bounds__(256) void assemble_q_pk(const float* __restrict__ qup,
        const float* __restrict__ cosT, const float* __restrict__ sinT,
        uint32_t* __restrict__ Qh, uint32_t* __restrict__ Ql) {
    const int idx = blockIdx.x * 256 + threadIdx.x;
    if (idx >= 32*2048*96) return;
    const int p  = idx % 96;
    const int ts = idx / 96;
    const int s  = ts & 2047;
    const int bh = ts >> 11;
    const int b = bh >> 4, h = bh & 15;
    const int m = b*2048 + s;
    float x0, x1;
    if (p < 64) {
        const float* src = qup + (size_t)m*3072 + h*128 + 2*p;
        x0 = src[0]; x1 = src[1];
    } else {
        const int jp = p - 64;
        const float* src = qup + (size_t)m*3072 + 2048 + h*64 + 2*jp;
        const float c = cosT[s*32 + jp], sn = sinT[s*32 + jp];
        const float a = src[0], bb = src[1];
        x0 = a*c - bb*sn;
        x1 = a*sn + bb*c;
    }
    splitpack(x0, x1, Qh[idx], Ql[idx]);
}

// ================= assemble K packed (krope read from dcat at col 2048) =================
__global__ __launch_bounds__(256) void assemble_k_pk(const float* __restrict__ kvup,
        const float* __restrict__ dcat,
        const float* __restrict__ cosT, const float* __restrict__ sinT,
        uint32_t* __restrict__ Kh, uint32_t* __restrict__ Kl) {
    const int idx = blockIdx.x * 256 + threadIdx.x;
    if (idx >= 32*2048*96) return;
    const int p  = idx % 96;
    const int ts = idx / 96;
    const int s  = ts & 2047;
    const int bh = ts >> 11;
    const int b = bh >> 4, h = bh & 15;
    const int m = b*2048 + s;
    float x0, x1;
    if (p < 64) {
        const float* src = kvup + (size_t)m*4096 + h*256 + 2*p;
        x0 = src[0]; x1 = src[1];
    } else {
        const int jp = p - 64;
        const float* src = dcat + (size_t)m*2112 + 2048 + 2*jp;
        const float c = cosT[s*32 + jp], sn = sinT[s*32 + jp];
        const float a = src[0], bb = src[1];
        x0 = a*c - bb*sn;
        x1 = a*sn + bb*c;
    }
    splitpack(x0, x1, Kh[idx], Kl[idx]);
}

// ================= V transpose + split =================
__global__ void split_v(const float* __restrict__ kvup,
                        uint32_t* __restrict__ Vh, uint32_t* __restrict__ Vl) {
    __shared__ float tile[64][33];
    const int bh = blockIdx.z, b = bh >> 4, h = bh & 15;
    const int s0 = blockIdx.x * 64, dv0 = blockIdx.y * 32;
    const int tx = threadIdx.x, ty = threadIdx.y;
    #pragma unroll
    for (int half = 0; half < 2; half++) {
        const int s = s0 + half*32 + ty;
        tile[half*32 + ty][tx] =
            kvup[((size_t)(b*2048 + s))*4096 + h*256 + 128 + dv0 + tx];
    }
    __syncthreads();
    const float x0 = tile[2*tx][ty], x1 = tile[2*tx + 1][ty];
    uint32_t hh, ll; splitpack(x0, x1, hh, ll);
    const size_t o = ((size_t)bh*128 + dv0 + ty)*1024 + (s0 >> 1) + tx;
    Vh[o] = hh; Vl[o] = ll;
}

// ================= flash attention (causal, packed bf16x3, ldmatrix frags) =================
#define FQP 100
#define FVP 36
#define FPP 36
#define FL_BYTES ((4*64*FQP + 2*128*FVP + 2*64*FPP + 2*128) * 4)
__global__ __launch_bounds__(256) void flash_pk(
    const uint32_t* __restrict__ Qhg, const uint32_t* __restrict__ Qlg,
    const uint32_t* __restrict__ Khg, const uint32_t* __restrict__ Klg,
    const uint32_t* __restrict__ Vhg, const uint32_t* __restrict__ Vlg,
    uint32_t* __restrict__ Oh, uint32_t* __restrict__ Ol) {
    extern __shared__ uint32_t sw[];
    uint32_t* Qsh = sw;
    uint32_t* Qsl = Qsh + 64*FQP;
    uint32_t* Ksh = Qsl + 64*FQP;
    uint32_t* Ksl = Ksh + 64*FQP;
    uint32_t* Vsh = Ksl + 64*FQP;
    uint32_t* Vsl = Vsh + 128*FVP;
    uint32_t* Psh = Vsl + 128*FVP;
    uint32_t* Psl = Psh + 64*FPP;
    float* sMax = (float*)(Psl + 64*FPP);
    float* sSum = sMax + 128;

    const int qt = 31 - blockIdx.x;
    const int bh = blockIdx.y;
    const int b = bh >> 4, h = bh & 15;
    const int tid = threadIdx.x;
    const int w = tid >> 5, lane = tid & 31;
    const int qg = w & 3, nhalf = w >> 2;
    const int g = lane >> 2, t = lane & 3;
    const int qrow = qg * 16;

    const int rowA = lane & 15, kselA = (lane >> 4) << 2;
    const int rowB = lane & 7,  kselB = ((lane >> 3) & 1) << 2;
    const uint32_t aQh = smem_u32(Qsh), aQl = smem_u32(Qsl);
    const uint32_t aKh = smem_u32(Ksh), aKl = smem_u32(Ksl);
    const uint32_t aVh = smem_u32(Vsh), aVl = smem_u32(Vsl);
    const uint32_t aPh = smem_u32(Psh), aPl = smem_u32(Psl);

    {
        const size_t base = ((size_t)bh*2048 + qt*64) * 96;
        for (int i = tid; i < 64*24; i += 256) {
            const int r = i / 24, c = i % 24;
            *(uint4*)&Qsh[r*FQP + c*4] = *(const uint4*)(Qhg + base + (size_t)r*96 + c*4);
            *(uint4*)&Qsl[r*FQP + c*4] = *(const uint4*)(Qlg + base + (size_t)r*96 + c*4);
        }
    }

    float m0 = -INFINITY, m1 = -INFINITY, l0 = 0.f, l1 = 0.f;
    float o[8][4];
    #pragma unroll
    for (int nt = 0; nt < 8; nt++)
        #pragma unroll
        for (int e = 0; e < 4; e++) o[nt][e] = 0.f;

    const float scale = 0.07216878364870323f;   // 1/sqrt(192)

    for (int kt = 0; kt <= qt; kt++) {
        __syncthreads();
        {
            const size_t base = ((size_t)bh*2048 + kt*64) * 96;
            for (int i = tid; i < 64*24; i += 256) {
                const int r = i / 24, c = i % 24;
                *(uint4*)&Ksh[r*FQP + c*4] = *(const uint4*)(Khg + base + (size_t)r*96 + c*4);
                *(uint4*)&Ksl[r*FQP + c*4] = *(const uint4*)(Klg + base + (size_t)r*96 + c*4);
            }
            const size_t vb = (size_t)bh*128*1024 + kt*32;
            for (int i = tid; i < 128*8; i += 256) {
                const int r = i / 8, c = i % 8;
                *(uint4*)&Vsh[r*FVP + c*4] = *(const uint4*)(Vhg + vb + (size_t)r*1024 + c*4);
                *(uint4*)&Vsl[r*FVP + c*4] = *(const uint4*)(Vlg + vb + (size_t)r*1024 + c*4);
            }
        }
        __syncthreads();

        float sa[4][4];
        #pragma unroll
        for (int nt = 0; nt < 4; nt++)
            #pragma unroll
            for (int e = 0; e < 4; e++) sa[nt][e] = 0.f;

        #pragma unroll 4
        for (int st = 0; st < 12; st++) {
            const int p0 = st * 8;
            const uint32_t oq = (uint32_t)((qrow + rowA)*FQP + p0 + kselA) * 4u;
            uint32_t fah[4], fal[4];
            ldsm4(fah, aQh + oq);
            ldsm4(fal, aQl + oq);
            uint32_t fbh[4][2], fbl[4][2];
            #pragma unroll
            for (int nt = 0; nt < 4; nt++) {
                const uint32_t ok = (uint32_t)((nhalf*32 + nt*8 + rowB)*FQP + p0 + kselB) * 4u;
                ldsm2(fbh[nt], aKh + ok);
                ldsm2(fbl[nt], aKl + ok);
            }
            #pragma unroll
            for (int nt = 0; nt < 4; nt++) mma16(sa[nt], fah, fbh[nt]);
            #pragma unroll
            for (int nt = 0; nt < 4; nt++) mma16(sa[nt], fah, fbl[nt]);
            #pragma unroll
            for (int nt = 0; nt < 4; nt++) mma16(sa[nt], fal, fbh[nt]);
        }

        const bool diag = (kt == qt);
        float pm0 = -INFINITY, pm1 = -INFINITY;
        #pragma unroll
        for (int nt = 0; nt < 4; nt++) {
            const int colb = nhalf*32 + nt*8 + 2*t;
            #pragma unroll
            for (int e = 0; e < 4; e++) {
                float v = sa[nt][e] * scale;
                if (diag) {
                    const int col = colb + (e & 1);
                    const int row = qrow + g + ((e >> 1) << 3);
                    if (col > row) v = -INFINITY;
                }
                sa[nt][e] = v;
                if (e < 2) pm0 = fmaxf(pm0, v); else pm1 = fmaxf(pm1, v);
            }
        }
        pm0 = fmaxf(pm0, __shfl_xor_sync(0xffffffffu, pm0, 1));
        pm0 = fmaxf(pm0, __shfl_xor_sync(0xffffffffu, pm0, 2));
        pm1 = fmaxf(pm1, __shfl_xor_sync(0xffffffffu, pm1, 1));
        pm1 = fmaxf(pm1, __shfl_xor_sync(0xffffffffu, pm1, 2));
        if (t == 0) {
            sMax[nhalf*64 + qrow + g]     = pm0;
            sMax[nhalf*64 + qrow + g + 8] = pm1;
        }
        __syncthreads();
        const float mn0 = fmaxf(m0, fmaxf(pm0, sMax[(1 - nhalf)*64 + qrow + g]));
        const float mn1 = fmaxf(m1, fmaxf(pm1, sMax[(1 - nhalf)*64 + qrow + g + 8]));
        const float al0 = __expf(m0 - mn0);
        const float al1 = __expf(m1 - mn1);

        float ps0 = 0.f, ps1 = 0.f;
        #pragma unroll
        for (int nt = 0; nt < 4; nt++) {
            const int pidx = nhalf*16 + nt*4 + t;
            const float p0v = __expf(sa[nt][0] - mn0);
            const float p1v = __expf(sa[nt][1] - mn0);
            const float p2v = __expf(sa[nt][2] - mn1);
            const float p3v = __expf(sa[nt][3] - mn1);
            ps0 += p0v + p1v; ps1 += p2v + p3v;
            splitpack(p0v, p1v, Psh[(qrow + g)*FPP + pidx],     Psl[(qrow + g)*FPP + pidx]);
            splitpack(p2v, p3v, Psh[(qrow + g + 8)*FPP + pidx], Psl[(qrow + g + 8)*FPP + pidx]);
        }
        ps0 += __shfl_xor_sync(0xffffffffu, ps0, 1);
        ps0 += __shfl_xor_sync(0xffffffffu, ps0, 2);
        ps1 += __shfl_xor_sync(0xffffffffu, ps1, 1);
        ps1 += __shfl_xor_sync(0xffffffffu, ps1, 2);
        if (t == 0) {
            sSum[nhalf*64 + qrow + g]     = ps0;
            sSum[nhalf*64 + qrow + g + 8] = ps1;
        }
        __syncthreads();
        l0 = l0 * al0 + ps0 + sSum[(1 - nhalf)*64 + qrow + g];
        l1 = l1 * al1 + ps1 + sSum[(1 - nhalf)*64 + qrow + g + 8];
        m0 = mn0; m1 = mn1;

        #pragma unroll
        for (int nt = 0; nt < 8; nt++) {
            o[nt][0] *= al0; o[nt][1] *= al0;
            o[nt][2] *= al1; o[nt][3] *= al1;
        }

        #pragma unroll
        for (int st = 0; st < 4; st++) {
            const int p0 = st * 8;
            const uint32_t op = (uint32_t)((qrow + rowA)*FPP + p0 + kselA) * 4u;
            uint32_t fah[4], fal[4];
            ldsm4(fah, aPh + op);
            ldsm4(fal, aPl + op);
            #pragma unroll
            for (int hv = 0; hv < 2; hv++) {
                uint32_t fbh[4][2], fbl[4][2];
                #pragma unroll
                for (int n4 = 0; n4 < 4; n4++) {
                    const int nt = hv*4 + n4;
                    const uint32_t ov = (uint32_t)((nhalf*64 + nt*8 + rowB)*FVP + p0 + kselB) * 4u;
                    ldsm2(fbh[n4], aVh + ov);
                    ldsm2(fbl[n4], aVl + ov);
                }
                #pragma unroll
                for (int n4 = 0; n4 < 4; n4++) mma16(o[hv*4 + n4], fah, fbh[n4]);
                #pragma unroll
                for (int n4 = 0; n4 < 4; n4++) mma16(o[hv*4 + n4], fah, fbl[n4]);
                #pragma unroll
                for (int n4 = 0; n4 < 4; n4++) mma16(o[hv*4 + n4], fal, fbh[n4]);
            }
        }
    }

    const float il0 = 1.f / l0, il1 = 1.f / l1;
    const int row0 = b*2048 + qt*64 + qrow + g;
    #pragma unroll
    for (int nt = 0; nt < 8; nt++) {
        const int cp = h*64 + nhalf*32 + nt*4 + t;
        splitpack(o[nt][0]*il0, o[nt][1]*il0, Oh[(size_t)row0*1024 + cp],       Ol[(size_t)row0*1024 + cp]);
        splitpack(o[nt][2]*il1, o[nt][3]*il1, Oh[(size_t)(row0 + 8)*1024 + cp], Ol[(size_t)(row0 + 8)*1024 + cp]);
    }
}

// ================= host orchestration =================
static inline int cdiv(int a, int b) { return (a + b - 1) / b; }

extern "C" void kernel_launch(void* const* d_in, const int* in_sizes, int n_in,
                              void* d_out, int out_size) {
    const float* x        = (const float*)d_in[0];
    const float* wq_down  = (const float*)d_in[1];
    const float* q_norm_w = (const float*)d_in[2];
    const float* wq_up    = (const float*)d_in[3];
    const float* wq_rope  = (const float*)d_in[4];
    const float* wkv_down = (const float*)d_in[5];
    const float* kv_norm_w= (const float*)d_in[6];
    const float* wkv_up   = (const float*)d_in[7];
    const float* wk_rope  = (const float*)d_in[8];
    const float* wo       = (const float*)d_in[9];
    float* out = (float*)d_out;

    uint32_t *xs_h,*xs_l,*wd_h,*wd_l,*wqc_h,*wqc_l,*wkvu_h,*wkvu_l,*wo_h,*wo_l;
    uint32_t *qcs_h,*qcs_l,*kvcs_h,*kvcs_l,*Qh,*Ql,*Kh,*Kl,*Vh,*Vl,*at_h,*at_l;
    float *dcat,*qup,*kvup,*ropeC,*ropeS;
    cudaGetSymbolAddress((void**)&xs_h,  g_xs_h);  cudaGetSymbolAddress((void**)&xs_l,  g_xs_l);
    cudaGetSymbolAddress((void**)&wd_h,  g_wd_h);  cudaGetSymbolAddress((void**)&wd_l,  g_wd_l);
    cudaGetSymbolAddress((void**)&wqc_h, g_wqc_h); cudaGetSymbolAddress((void**)&wqc_l, g_wqc_l);
    cudaGetSymbolAddress((void**)&wkvu_h,g_wkvu_h);cudaGetSymbolAddress((void**)&wkvu_l,g_wkvu_l);
    cudaGetSymbolAddress((void**)&wo_h,  g_wo_h);  cudaGetSymbolAddress((void**)&wo_l,  g_wo_l);
    cudaGetSymbolAddress((void**)&dcat,  g_dcat);
    cudaGetSymbolAddress((void**)&qcs_h, g_qcs_h); cudaGetSymbolAddress((void**)&qcs_l, g_qcs_l);
    cudaGetSymbolAddress((void**)&kvcs_h,g_kvcs_h);cudaGetSymbolAddress((void**)&kvcs_l,g_kvcs_l);
    cudaGetSymbolAddress((void**)&qup,   g_qup);   cudaGetSymbolAddress((void**)&kvup,  g_kvup);
    cudaGetSymbolAddress((void**)&Qh,    g_Qh);    cudaGetSymbolAddress((void**)&Ql,    g_Ql);
    cudaGetSymbolAddress((void**)&Kh,    g_Kh);    cudaGetSymbolAddress((void**)&Kl,    g_Kl);
    cudaGetSymbolAddress((void**)&Vh,    g_Vh);    cudaGetSymbolAddress((void**)&Vl,    g_Vl);
    cudaGetSymbolAddress((void**)&at_h,  g_at_h);  cudaGetSymbolAddress((void**)&at_l,  g_at_l);
    cudaGetSymbolAddress((void**)&ropeC, g_ropeC); cudaGetSymbolAddress((void**)&ropeS, g_ropeS);

    cudaFuncSetAttribute(gemm_pk, cudaFuncAttributeMaxDynamicSharedMemorySize, GEMM_SMEM);
    cudaFuncSetAttribute(flash_pk, cudaFuncAttributeMaxDynamicSharedMemorySize, FL_BYTES);

    // ---- one fused split of all fp32 inputs ----
    split_all<<<cdiv((int)NP_TOTAL, 256), 256>>>(x, wq_down, wkv_down, wk_rope,
                                                 wq_up, wq_rope, wkv_up, wo);
    rope_table<<<cdiv(2048*32, 256), 256>>>(ropeC, ropeS);

    // ---- merged down projection: C[4096][2112] = x @ [wq_down|wkv_down|wk_rope]^T ----
    gemm_pk<<<dim3(17, 32), 256, GEMM_SMEM>>>(xs_h, xs_l, wd_h, wd_l, dcat, 4096, 2112, 1024);

    rmsnorm_split<<<4096, 256>>>(dcat,        2112, q_norm_w,  1536, qcs_h,  qcs_l);
    rmsnorm_split<<<4096, 256>>>(dcat + 1536, 2112, kv_norm_w, 512,  kvcs_h, kvcs_l);

    // ---- up projections ----
    gemm_pk<<<dim3(24, 32), 256, GEMM_SMEM>>>(qcs_h,  qcs_l,  wqc_h,  wqc_l,  qup,  4096, 3072, 768);
    gemm_pk<<<dim3(32, 32), 256, GEMM_SMEM>>>(kvcs_h, kvcs_l, wkvu_h, wkvu_l, kvup, 4096, 4096, 256);

    // ---- assemble packed Q/K/V ----
    assemble_q_pk<<<cdiv(32*2048*96, 256), 256>>>(qup, ropeC, ropeS, Qh, Ql);
    assemble_k_pk<<<cdiv(32*2048*96, 256), 256>>>(kvup, dcat, ropeC, ropeS, Kh, Kl);
    split_v<<<dim3(32, 4, 32), dim3(32, 32)>>>(kvup, Vh, Vl);

    // ---- flash attention ----
    flash_pk<<<dim3(32, 32), 256, FL_BYTES>>>(Qh, Ql, Kh, Kl, Vh, Vl, at_h, at_l);

    // ---- output projection ----
    gemm_pk<<<dim3(16, 32), 256, GEMM_SMEM>>>(at_h, at_l, wo_h, wo_l, out, 4096, 2048, 1024);
}